// round 1
// baseline (speedup 1.0000x reference)
#include <cuda_runtime.h>
#include <cuda_bf16.h>
#include <math.h>

#define TT 2048
#define DD 1024
#define HH 16
#define HS 64
#define FF 4096

// ---------------- scratch (device globals, no allocation) ----------------
__device__ float g_xn[TT * DD];        // rmsnorm(x, g1)
__device__ float g_q[HH * TT * HS];    // [H][T][HS]
__device__ float g_k[HH * TT * HS];
__device__ float g_v[HH * TT * HS];
__device__ float g_attn[HH * TT * HS]; // attention output, head-major
__device__ float g_x1[TT * DD];        // x + attn proj
__device__ float g_xn2[TT * DD];       // rmsnorm(x1, g2)
__device__ float g_hbuf[TT * FF];      // silu(xn2 @ W1)

// ---------------- rmsnorm ----------------
__global__ __launch_bounds__(256) void rmsnorm_kernel(const float* __restrict__ x,
                                                      const float* __restrict__ g,
                                                      float* __restrict__ out) {
    int row = blockIdx.x;
    const float* xr = x + (size_t)row * DD;
    float ss = 0.f;
    for (int i = threadIdx.x; i < DD; i += 256) { float v = xr[i]; ss += v * v; }
    __shared__ float red[8];
    #pragma unroll
    for (int o = 16; o; o >>= 1) ss += __shfl_xor_sync(0xffffffffu, ss, o);
    if ((threadIdx.x & 31) == 0) red[threadIdx.x >> 5] = ss;
    __syncthreads();
    if (threadIdx.x < 32) {
        float v = (threadIdx.x < 8) ? red[threadIdx.x] : 0.f;
        #pragma unroll
        for (int o = 4; o; o >>= 1) v += __shfl_xor_sync(0xffffffffu, v, o);
        if (threadIdx.x == 0) red[0] = v;
    }
    __syncthreads();
    float scale = rsqrtf(red[0] * (1.0f / DD) + 1e-6f);
    for (int i = threadIdx.x; i < DD; i += 256)
        out[(size_t)row * DD + i] = xr[i] * scale * g[i];
}

// ---------------- generic 64x64 tile GEMM core (256 threads, 4x4/thread) ----------------
template <class ALoad, class BLoad>
__device__ __forceinline__ void gemm64x64(int K, ALoad aload, BLoad bload, float (&acc)[4][4]) {
    __shared__ float As[16][68];   // As[k][m]
    __shared__ float Bs[16][68];   // Bs[k][n]
    const int tid = threadIdx.x;
    const int tx = tid & 15, ty = tid >> 4;
    const int arow = tid >> 2, acol = (tid & 3) * 4;
    const int brow = tid >> 4, bcol = (tid & 15) * 4;
    for (int k0 = 0; k0 < K; k0 += 16) {
        float4 a = aload(arow, k0 + acol);
        As[acol + 0][arow] = a.x; As[acol + 1][arow] = a.y;
        As[acol + 2][arow] = a.z; As[acol + 3][arow] = a.w;
        float4 b = bload(k0 + brow, bcol);
        *(float4*)&Bs[brow][bcol] = b;
        __syncthreads();
        #pragma unroll
        for (int k = 0; k < 16; k++) {
            float4 av = *(const float4*)&As[k][ty * 4];
            float4 bv = *(const float4*)&Bs[k][tx * 4];
            float ar[4] = {av.x, av.y, av.z, av.w};
            float br[4] = {bv.x, bv.y, bv.z, bv.w};
            #pragma unroll
            for (int i = 0; i < 4; i++)
                #pragma unroll
                for (int j = 0; j < 4; j++)
                    acc[i][j] = fmaf(ar[i], br[j], acc[i][j]);
        }
        __syncthreads();
    }
}

// ---------------- QKV: per head, C[T,64] = xn @ W_h ----------------
__global__ __launch_bounds__(256) void qkv_kernel(const float* __restrict__ Wq,
                                                  const float* __restrict__ Wk,
                                                  const float* __restrict__ Wv) {
    const int r0 = blockIdx.x * 64;
    const int h  = blockIdx.y;
    const int which = blockIdx.z;
    const float* W = (which == 0 ? Wq : which == 1 ? Wk : Wv) + (size_t)h * DD * HS;
    float* out = (which == 0 ? g_q : which == 1 ? g_k : g_v) + (size_t)h * TT * HS;
    float acc[4][4] = {};
    gemm64x64(DD,
        [&](int r, int c) { return *(const float4*)&g_xn[(size_t)(r0 + r) * DD + c]; },
        [&](int r, int c) { return *(const float4*)&W[(size_t)r * HS + c]; },
        acc);
    const int tx = threadIdx.x & 15, ty = threadIdx.x >> 4;
    #pragma unroll
    for (int i = 0; i < 4; i++) {
        float4 v = make_float4(acc[i][0], acc[i][1], acc[i][2], acc[i][3]);
        *(float4*)&out[(size_t)(r0 + ty * 4 + i) * HS + tx * 4] = v;
    }
}

// ---------------- causal flash attention, 64x64 tiles ----------------
__global__ __launch_bounds__(256) void attn_kernel() {
    __shared__ float Qts[64 * 64];   // Qts[s*64 + r] = Q[r][s]
    __shared__ float KPs[64 * 64];   // first K^T (KPs[s*64+c]=K[c][s]), then P row-major
    __shared__ float Vs[64 * 64];    // Vs[j*64 + c] = V[j][c]
    const int h = blockIdx.y, qb = blockIdx.x;
    const float* Qh = g_q + (size_t)h * TT * HS;
    const float* Kh = g_k + (size_t)h * TT * HS;
    const float* Vh = g_v + (size_t)h * TT * HS;
    float* Oh = g_attn + (size_t)h * TT * HS;
    const int tid = threadIdx.x;
    const int tx = tid & 15, ty = tid >> 4;
    const int lrow = tid >> 2, lcol = (tid & 3) * 16;
    const int q0 = qb * 64;

    #pragma unroll
    for (int c = 0; c < 16; c += 4) {
        float4 v = *(const float4*)&Qh[(size_t)(q0 + lrow) * HS + lcol + c];
        Qts[(lcol + c + 0) * 64 + lrow] = v.x;
        Qts[(lcol + c + 1) * 64 + lrow] = v.y;
        Qts[(lcol + c + 2) * 64 + lrow] = v.z;
        Qts[(lcol + c + 3) * 64 + lrow] = v.w;
    }

    float acc[4][4] = {};
    float m_i[4], l_i[4];
    #pragma unroll
    for (int i = 0; i < 4; i++) { m_i[i] = -1e30f; l_i[i] = 0.f; }
    const float scale = 0.125f;  // 1/sqrt(64)

    for (int kb = 0; kb <= qb; kb++) {
        __syncthreads();
        const int k0t = kb * 64;
        #pragma unroll
        for (int c = 0; c < 16; c += 4) {
            float4 v = *(const float4*)&Kh[(size_t)(k0t + lrow) * HS + lcol + c];
            KPs[(lcol + c + 0) * 64 + lrow] = v.x;
            KPs[(lcol + c + 1) * 64 + lrow] = v.y;
            KPs[(lcol + c + 2) * 64 + lrow] = v.z;
            KPs[(lcol + c + 3) * 64 + lrow] = v.w;
            float4 w = *(const float4*)&Vh[(size_t)(k0t + lrow) * HS + lcol + c];
            *(float4*)&Vs[lrow * 64 + lcol + c] = w;
        }
        __syncthreads();

        // S = (Q K^T) * scale, with causal mask on diagonal tile
        float s[4][4] = {};
        #pragma unroll
        for (int k = 0; k < 64; k++) {
            float4 av = *(const float4*)&Qts[k * 64 + ty * 4];
            float4 bv = *(const float4*)&KPs[k * 64 + tx * 4];
            float ar[4] = {av.x, av.y, av.z, av.w};
            float br[4] = {bv.x, bv.y, bv.z, bv.w};
            #pragma unroll
            for (int i = 0; i < 4; i++)
                #pragma unroll
                for (int j = 0; j < 4; j++)
                    s[i][j] = fmaf(ar[i], br[j], s[i][j]);
        }
        const bool diag = (kb == qb);
        #pragma unroll
        for (int i = 0; i < 4; i++)
            #pragma unroll
            for (int j = 0; j < 4; j++) {
                s[i][j] *= scale;
                if (diag && (k0t + tx * 4 + j > q0 + ty * 4 + i)) s[i][j] = -1e30f;
            }

        // online softmax (row group = 16 lanes sharing ty)
        float p[4][4], f[4];
        #pragma unroll
        for (int i = 0; i < 4; i++) {
            float rm = fmaxf(fmaxf(s[i][0], s[i][1]), fmaxf(s[i][2], s[i][3]));
            #pragma unroll
            for (int o = 8; o; o >>= 1) rm = fmaxf(rm, __shfl_xor_sync(0xffffffffu, rm, o));
            float mn = fmaxf(m_i[i], rm);
            f[i] = __expf(m_i[i] - mn);
            m_i[i] = mn;
            float rs = 0.f;
            #pragma unroll
            for (int j = 0; j < 4; j++) { p[i][j] = __expf(s[i][j] - mn); rs += p[i][j]; }
            #pragma unroll
            for (int o = 8; o; o >>= 1) rs += __shfl_xor_sync(0xffffffffu, rs, o);
            l_i[i] = l_i[i] * f[i] + rs;
            #pragma unroll
            for (int j = 0; j < 4; j++) acc[i][j] *= f[i];
        }
        __syncthreads();  // everyone done reading KPs (K^T)
        #pragma unroll
        for (int i = 0; i < 4; i++)
            *(float4*)&KPs[(ty * 4 + i) * 64 + tx * 4] =
                make_float4(p[i][0], p[i][1], p[i][2], p[i][3]);
        __syncthreads();

        // O += P @ V
        #pragma unroll 16
        for (int j = 0; j < 64; j++) {
            float4 bv = *(const float4*)&Vs[j * 64 + tx * 4];
            float br[4] = {bv.x, bv.y, bv.z, bv.w};
            #pragma unroll
            for (int i = 0; i < 4; i++) {
                float pr = KPs[(ty * 4 + i) * 64 + j];
                #pragma unroll
                for (int jj = 0; jj < 4; jj++)
                    acc[i][jj] = fmaf(pr, br[jj], acc[i][jj]);
            }
        }
    }
    #pragma unroll
    for (int i = 0; i < 4; i++) {
        float inv = 1.0f / l_i[i];
        float4 v = make_float4(acc[i][0] * inv, acc[i][1] * inv, acc[i][2] * inv, acc[i][3] * inv);
        *(float4*)&Oh[(size_t)(q0 + ty * 4 + i) * HS + tx * 4] = v;
    }
}

// ---------------- proj + residual: x1 = x + attn_flat @ Wproj + b ----------------
__global__ __launch_bounds__(256) void proj_kernel(const float* __restrict__ x,
                                                   const float* __restrict__ Wp,
                                                   const float* __restrict__ bp) {
    const int r0 = blockIdx.x * 64, c0 = blockIdx.y * 64;
    float acc[4][4] = {};
    gemm64x64(DD,
        [&](int r, int k) {
            int hh = k >> 6, s = k & 63;  // 16-wide chunks never cross a head boundary
            return *(const float4*)&g_attn[((size_t)hh * TT + r0 + r) * HS + s];
        },
        [&](int r, int c) { return *(const float4*)&Wp[(size_t)r * DD + c0 + c]; },
        acc);
    const int tx = threadIdx.x & 15, ty = threadIdx.x >> 4;
    #pragma unroll
    for (int i = 0; i < 4; i++) {
        int r = r0 + ty * 4 + i;
        #pragma unroll
        for (int j = 0; j < 4; j++) {
            int c = c0 + tx * 4 + j;
            g_x1[(size_t)r * DD + c] = x[(size_t)r * DD + c] + bp[c] + acc[i][j];
        }
    }
}

// ---------------- FFN1: h = silu(xn2 @ W1) ----------------
__global__ __launch_bounds__(256) void ffn1_kernel(const float* __restrict__ W1) {
    const int r0 = blockIdx.x * 64, c0 = blockIdx.y * 64;
    float acc[4][4] = {};
    gemm64x64(DD,
        [&](int r, int k) { return *(const float4*)&g_xn2[(size_t)(r0 + r) * DD + k]; },
        [&](int r, int c) { return *(const float4*)&W1[(size_t)r * FF + c0 + c]; },
        acc);
    const int tx = threadIdx.x & 15, ty = threadIdx.x >> 4;
    #pragma unroll
    for (int i = 0; i < 4; i++) {
        int r = r0 + ty * 4 + i;
        #pragma unroll
        for (int j = 0; j < 4; j++) {
            int c = c0 + tx * 4 + j;
            float v = acc[i][j];
            g_hbuf[(size_t)r * FF + c] = v / (1.0f + __expf(-v));
        }
    }
}

// ---------------- FFN2 + residual: out = x1 + h @ W2 ----------------
__global__ __launch_bounds__(256) void ffn2_kernel(const float* __restrict__ W2,
                                                   float* __restrict__ out) {
    const int r0 = blockIdx.x * 64, c0 = blockIdx.y * 64;
    float acc[4][4] = {};
    gemm64x64(FF,
        [&](int r, int k) { return *(const float4*)&g_hbuf[(size_t)(r0 + r) * FF + k]; },
        [&](int r, int c) { return *(const float4*)&W2[(size_t)r * DD + c0 + c]; },
        acc);
    const int tx = threadIdx.x & 15, ty = threadIdx.x >> 4;
    #pragma unroll
    for (int i = 0; i < 4; i++) {
        int r = r0 + ty * 4 + i;
        #pragma unroll
        for (int j = 0; j < 4; j++) {
            int c = c0 + tx * 4 + j;
            out[(size_t)r * DD + c] = g_x1[(size_t)r * DD + c] + acc[i][j];
        }
    }
}

// ---------------- launch ----------------
extern "C" void kernel_launch(void* const* d_in, const int* in_sizes, int n_in,
                              void* d_out, int out_size) {
    const float* x     = (const float*)d_in[0];
    const float* Wq    = (const float*)d_in[1];
    const float* Wk    = (const float*)d_in[2];
    const float* Wv    = (const float*)d_in[3];
    const float* Wproj = (const float*)d_in[4];
    const float* bproj = (const float*)d_in[5];
    const float* W1    = (const float*)d_in[6];
    const float* W2    = (const float*)d_in[7];
    const float* g1    = (const float*)d_in[8];
    const float* g2    = (const float*)d_in[9];
    float* out = (float*)d_out;

    float* p_xn;  cudaGetSymbolAddress((void**)&p_xn,  g_xn);
    float* p_x1;  cudaGetSymbolAddress((void**)&p_x1,  g_x1);
    float* p_xn2; cudaGetSymbolAddress((void**)&p_xn2, g_xn2);

    rmsnorm_kernel<<<TT, 256>>>(x, g1, p_xn);
    qkv_kernel<<<dim3(TT / 64, HH, 3), 256>>>(Wq, Wk, Wv);
    attn_kernel<<<dim3(TT / 64, HH), 256>>>();
    proj_kernel<<<dim3(TT / 64, DD / 64), 256>>>(x, Wproj, bproj);
    rmsnorm_kernel<<<TT, 256>>>(p_x1, g2, p_xn2);
    ffn1_kernel<<<dim3(TT / 64, FF / 64), 256>>>(W1);
    ffn2_kernel<<<dim3(TT / 64, DD / 64), 256>>>(W2, out);
}

// round 2
// speedup vs baseline: 2.1865x; 2.1865x over previous
#include <cuda_runtime.h>
#include <cuda_bf16.h>
#include <math.h>

#define TT 2048
#define DD 1024
#define HH 16
#define HS 64
#define FF 4096
#define NQKV 3072

// ---------------- scratch (device globals, no allocation) ----------------
__device__ float g_xn[TT * DD];          // rmsnorm(x, g1), tf32-rounded
__device__ float g_qkv[TT * NQKV];       // [T][3072]: q | k | v, each h-major*64
__device__ float g_attn[TT * DD];        // attention out, [T][H*64], tf32-rounded
__device__ float g_x1[TT * DD];          // x + attn proj
__device__ float g_xn2[TT * DD];         // rmsnorm(x1, g2), tf32-rounded
__device__ float g_hbuf[TT * FF];        // silu(xn2 @ W1), tf32-rounded
__device__ float g_Bqkv[DD * NQKV];      // packed+rounded QKV weights [D][3072]
__device__ float g_Wpr[DD * DD];         // rounded Wproj
__device__ float g_W1r[DD * FF];         // rounded W1
__device__ float g_W2r[FF * DD];         // rounded W2

// ---------------- helpers ----------------
__device__ __forceinline__ float f2tf(float f) {
    unsigned u;
    asm("cvt.rna.tf32.f32 %0, %1;" : "=r"(u) : "f"(f));
    return __uint_as_float(u);
}

__device__ __forceinline__ void cp16(void* s, const void* g) {
    unsigned saddr = (unsigned)__cvta_generic_to_shared(s);
    asm volatile("cp.async.cg.shared.global [%0], [%1], 16;\n" :: "r"(saddr), "l"(g));
}
__device__ __forceinline__ void cp_commit() { asm volatile("cp.async.commit_group;\n"); }
template <int N> __device__ __forceinline__ void cp_wait() {
    asm volatile("cp.async.wait_group %0;\n" :: "n"(N));
}

__device__ __forceinline__ void mma_tf32(float* c, const unsigned* a, const unsigned* b) {
    asm volatile(
        "mma.sync.aligned.m16n8k8.row.col.f32.tf32.tf32.f32 "
        "{%0,%1,%2,%3}, {%4,%5,%6,%7}, {%8,%9}, {%0,%1,%2,%3};"
        : "+f"(c[0]), "+f"(c[1]), "+f"(c[2]), "+f"(c[3])
        : "r"(a[0]), "r"(a[1]), "r"(a[2]), "r"(a[3]), "r"(b[0]), "r"(b[1]));
}

// ---------------- prep: round weights to tf32 ----------------
__global__ __launch_bounds__(256) void round_kernel(const float* __restrict__ in,
                                                    float* __restrict__ out, int n4) {
    int i = blockIdx.x * 256 + threadIdx.x;
    if (i >= n4) return;
    float4 v = ((const float4*)in)[i];
    v.x = f2tf(v.x); v.y = f2tf(v.y); v.z = f2tf(v.z); v.w = f2tf(v.w);
    ((float4*)out)[i] = v;
}

// pack Wq/Wk/Wv [H,D,HS] -> g_Bqkv[D][3072], n = which*1024 + h*64 + s
__global__ __launch_bounds__(256) void pack_qkv_kernel(const float* __restrict__ Wq,
                                                       const float* __restrict__ Wk,
                                                       const float* __restrict__ Wv) {
    int n = blockIdx.x * 256 + threadIdx.x;  // 0..3071
    int d = blockIdx.y;
    int which = n >> 10;
    int h = (n >> 6) & 15;
    int s = n & 63;
    const float* W = which == 0 ? Wq : which == 1 ? Wk : Wv;
    g_Bqkv[(size_t)d * NQKV + n] = f2tf(W[h * (DD * HS) + d * HS + s]);
}

// ---------------- rmsnorm (output tf32-rounded) ----------------
__global__ __launch_bounds__(256) void rmsnorm_kernel(const float* __restrict__ x,
                                                      const float* __restrict__ g,
                                                      float* __restrict__ out) {
    int row = blockIdx.x;
    const float* xr = x + (size_t)row * DD;
    float ss = 0.f;
    for (int i = threadIdx.x; i < DD; i += 256) { float v = xr[i]; ss += v * v; }
    __shared__ float red[8];
    #pragma unroll
    for (int o = 16; o; o >>= 1) ss += __shfl_xor_sync(0xffffffffu, ss, o);
    if ((threadIdx.x & 31) == 0) red[threadIdx.x >> 5] = ss;
    __syncthreads();
    if (threadIdx.x < 32) {
        float v = (threadIdx.x < 8) ? red[threadIdx.x] : 0.f;
        #pragma unroll
        for (int o = 4; o; o >>= 1) v += __shfl_xor_sync(0xffffffffu, v, o);
        if (threadIdx.x == 0) red[0] = v;
    }
    __syncthreads();
    float scale = rsqrtf(red[0] * (1.0f / DD) + 1e-6f);
    for (int i = threadIdx.x; i < DD; i += 256)
        out[(size_t)row * DD + i] = f2tf(xr[i] * scale * g[i]);
}

// ---------------- tf32 tensor-core GEMM: C[M,N] = A[M,K] @ B[K,N] ----------------
// BM=128 BN=128 BK=32, 256 threads, double-buffered cp.async
#define BM 128
#define BN 128
#define BK 32
#define APAD 36
#define BPAD 136
#define GEMM_SMEM ((2 * BM * APAD + 2 * BK * BPAD) * 4)

// MODE 0: C = acc                         (qkv)
// MODE 1: C = acc + aux1[row,col] + aux2[col]   (proj + residual + bias)
// MODE 2: C = tf32(silu(acc))             (ffn1)
// MODE 3: C = acc + aux1[row,col]         (ffn2 + residual)
template <int MODE>
__global__ __launch_bounds__(256, 1) void gemm_kernel(
    const float* __restrict__ A, const float* __restrict__ B, float* __restrict__ C,
    const float* __restrict__ aux1, const float* __restrict__ aux2,
    int M, int N, int K) {
    extern __shared__ float smem[];
    float* As = smem;                   // [2][BM][APAD]
    float* Bs = smem + 2 * BM * APAD;   // [2][BK][BPAD]

    const int tid = threadIdx.x;
    const int bx = blockIdx.x, by = blockIdx.y;
    const int warp = tid >> 5, lane = tid & 31;
    const int wm = warp & 3, wn = warp >> 2;   // warps 4(m) x 2(n)
    const int g = lane >> 2, t4 = lane & 3;

    const float* Ab = A + (size_t)by * BM * K;
    const float* Bb = B + (size_t)bx * BN;

    // load-index precompute: A: idx -> (m, c): m=idx>>3, c=idx&7 ; B: k=idx>>5, c=idx&31
    float acc[2][8][4];
    #pragma unroll
    for (int i = 0; i < 2; i++)
        #pragma unroll
        for (int j = 0; j < 8; j++)
            #pragma unroll
            for (int c = 0; c < 4; c++) acc[i][j][c] = 0.f;

    const int KT = K / BK;

    auto load_stage = [&](int kt, int buf) {
        float* Asb = As + buf * BM * APAD;
        float* Bsb = Bs + buf * BK * BPAD;
        #pragma unroll
        for (int i = 0; i < 4; i++) {
            int idx = tid + i * 256;
            int m = idx >> 3, c = idx & 7;
            cp16(Asb + m * APAD + c * 4, Ab + (size_t)m * K + kt * BK + c * 4);
        }
        #pragma unroll
        for (int i = 0; i < 4; i++) {
            int idx = tid + i * 256;
            int k = idx >> 5, c = idx & 31;
            cp16(Bsb + k * BPAD + c * 4, Bb + (size_t)(kt * BK + k) * N + c * 4);
        }
        cp_commit();
    };

    load_stage(0, 0);

    for (int kt = 0; kt < KT; kt++) {
        if (kt + 1 < KT) {
            load_stage(kt + 1, (kt + 1) & 1);
            cp_wait<1>();
        } else {
            cp_wait<0>();
        }
        __syncthreads();

        const float* As_ = As + (kt & 1) * BM * APAD;
        const float* Bs_ = Bs + (kt & 1) * BK * BPAD;
        #pragma unroll
        for (int ks = 0; ks < 4; ks++) {
            const int k = ks * 8;
            unsigned a[2][4], b[8][2];
            #pragma unroll
            for (int mi = 0; mi < 2; mi++) {
                int rb = wm * 32 + mi * 16;
                a[mi][0] = __float_as_uint(As_[(rb + g) * APAD + k + t4]);
                a[mi][1] = __float_as_uint(As_[(rb + g + 8) * APAD + k + t4]);
                a[mi][2] = __float_as_uint(As_[(rb + g) * APAD + k + t4 + 4]);
                a[mi][3] = __float_as_uint(As_[(rb + g + 8) * APAD + k + t4 + 4]);
            }
            #pragma unroll
            for (int ni = 0; ni < 8; ni++) {
                int col = wn * 64 + ni * 8 + g;
                b[ni][0] = __float_as_uint(Bs_[(k + t4) * BPAD + col]);
                b[ni][1] = __float_as_uint(Bs_[(k + t4 + 4) * BPAD + col]);
            }
            #pragma unroll
            for (int mi = 0; mi < 2; mi++)
                #pragma unroll
                for (int ni = 0; ni < 8; ni++)
                    mma_tf32(acc[mi][ni], a[mi], b[ni]);
        }
        __syncthreads();
    }

    // epilogue
    #pragma unroll
    for (int mi = 0; mi < 2; mi++)
        #pragma unroll
        for (int r2 = 0; r2 < 2; r2++) {
            int row = by * BM + wm * 32 + mi * 16 + g + r2 * 8;
            #pragma unroll
            for (int ni = 0; ni < 8; ni++) {
                int col = bx * BN + wn * 64 + ni * 8 + t4 * 2;
                float v0 = acc[mi][ni][r2 * 2 + 0];
                float v1 = acc[mi][ni][r2 * 2 + 1];
                size_t oidx = (size_t)row * N + col;
                if (MODE == 0) {
                    C[oidx] = v0; C[oidx + 1] = v1;
                } else if (MODE == 1) {
                    C[oidx] = v0 + aux1[oidx] + aux2[col];
                    C[oidx + 1] = v1 + aux1[oidx + 1] + aux2[col + 1];
                } else if (MODE == 2) {
                    C[oidx] = f2tf(v0 / (1.0f + __expf(-v0)));
                    C[oidx + 1] = f2tf(v1 / (1.0f + __expf(-v1)));
                } else {
                    size_t ridx = (size_t)row * DD + col;
                    C[oidx] = v0 + aux1[ridx];
                    C[oidx + 1] = v1 + aux1[ridx + 1];
                }
            }
        }
}

// ---------------- causal flash attention, 64x64 tiles (fp32 SIMT) ----------------
#define QS NQKV  // row stride of q/k/v inside g_qkv
__global__ __launch_bounds__(256) void attn_kernel() {
    __shared__ float Qts[64 * 64];   // Qts[s*64 + r] = Q[r][s]
    __shared__ float KPs[64 * 64];   // first K^T, then P row-major
    __shared__ float Vs[64 * 64];    // Vs[j*64 + c] = V[j][c]
    const int h = blockIdx.y, qb = blockIdx.x;
    const float* Qh = g_qkv + h * HS;
    const float* Kh = g_qkv + DD + h * HS;
    const float* Vh = g_qkv + 2 * DD + h * HS;
    const int tid = threadIdx.x;
    const int tx = tid & 15, ty = tid >> 4;
    const int lrow = tid >> 2, lcol = (tid & 3) * 16;
    const int q0 = qb * 64;

    #pragma unroll
    for (int c = 0; c < 16; c += 4) {
        float4 v = *(const float4*)&Qh[(size_t)(q0 + lrow) * QS + lcol + c];
        Qts[(lcol + c + 0) * 64 + lrow] = v.x;
        Qts[(lcol + c + 1) * 64 + lrow] = v.y;
        Qts[(lcol + c + 2) * 64 + lrow] = v.z;
        Qts[(lcol + c + 3) * 64 + lrow] = v.w;
    }

    float acc[4][4] = {};
    float m_i[4], l_i[4];
    #pragma unroll
    for (int i = 0; i < 4; i++) { m_i[i] = -1e30f; l_i[i] = 0.f; }
    const float scale = 0.125f;

    for (int kb = 0; kb <= qb; kb++) {
        __syncthreads();
        const int k0t = kb * 64;
        #pragma unroll
        for (int c = 0; c < 16; c += 4) {
            float4 v = *(const float4*)&Kh[(size_t)(k0t + lrow) * QS + lcol + c];
            KPs[(lcol + c + 0) * 64 + lrow] = v.x;
            KPs[(lcol + c + 1) * 64 + lrow] = v.y;
            KPs[(lcol + c + 2) * 64 + lrow] = v.z;
            KPs[(lcol + c + 3) * 64 + lrow] = v.w;
            float4 w = *(const float4*)&Vh[(size_t)(k0t + lrow) * QS + lcol + c];
            *(float4*)&Vs[lrow * 64 + lcol + c] = w;
        }
        __syncthreads();

        float s[4][4] = {};
        #pragma unroll
        for (int k = 0; k < 64; k++) {
            float4 av = *(const float4*)&Qts[k * 64 + ty * 4];
            float4 bv = *(const float4*)&KPs[k * 64 + tx * 4];
            float ar[4] = {av.x, av.y, av.z, av.w};
            float br[4] = {bv.x, bv.y, bv.z, bv.w};
            #pragma unroll
            for (int i = 0; i < 4; i++)
                #pragma unroll
                for (int j = 0; j < 4; j++)
                    s[i][j] = fmaf(ar[i], br[j], s[i][j]);
        }
        const bool diag = (kb == qb);
        #pragma unroll
        for (int i = 0; i < 4; i++)
            #pragma unroll
            for (int j = 0; j < 4; j++) {
                s[i][j] *= scale;
                if (diag && (k0t + tx * 4 + j > q0 + ty * 4 + i)) s[i][j] = -1e30f;
            }

        float p[4][4], f[4];
        #pragma unroll
        for (int i = 0; i < 4; i++) {
            float rm = fmaxf(fmaxf(s[i][0], s[i][1]), fmaxf(s[i][2], s[i][3]));
            #pragma unroll
            for (int o = 8; o; o >>= 1) rm = fmaxf(rm, __shfl_xor_sync(0xffffffffu, rm, o));
            float mn = fmaxf(m_i[i], rm);
            f[i] = __expf(m_i[i] - mn);
            m_i[i] = mn;
            float rs = 0.f;
            #pragma unroll
            for (int j = 0; j < 4; j++) { p[i][j] = __expf(s[i][j] - mn); rs += p[i][j]; }
            #pragma unroll
            for (int o = 8; o; o >>= 1) rs += __shfl_xor_sync(0xffffffffu, rs, o);
            l_i[i] = l_i[i] * f[i] + rs;
            #pragma unroll
            for (int j = 0; j < 4; j++) acc[i][j] *= f[i];
        }
        __syncthreads();
        #pragma unroll
        for (int i = 0; i < 4; i++)
            *(float4*)&KPs[(ty * 4 + i) * 64 + tx * 4] =
                make_float4(p[i][0], p[i][1], p[i][2], p[i][3]);
        __syncthreads();

        #pragma unroll 16
        for (int j = 0; j < 64; j++) {
            float4 bv = *(const float4*)&Vs[j * 64 + tx * 4];
            float br[4] = {bv.x, bv.y, bv.z, bv.w};
            #pragma unroll
            for (int i = 0; i < 4; i++) {
                float pr = KPs[(ty * 4 + i) * 64 + j];
                #pragma unroll
                for (int jj = 0; jj < 4; jj++)
                    acc[i][jj] = fmaf(pr, br[jj], acc[i][jj]);
            }
        }
    }
    // write attention out [T][H*64], tf32-rounded (it feeds proj GEMM A)
    #pragma unroll
    for (int i = 0; i < 4; i++) {
        float inv = 1.0f / l_i[i];
        float4 v = make_float4(f2tf(acc[i][0] * inv), f2tf(acc[i][1] * inv),
                               f2tf(acc[i][2] * inv), f2tf(acc[i][3] * inv));
        *(float4*)&g_attn[(size_t)(q0 + ty * 4 + i) * DD + h * HS + tx * 4] = v;
    }
}

// ---------------- launch ----------------
extern "C" void kernel_launch(void* const* d_in, const int* in_sizes, int n_in,
                              void* d_out, int out_size) {
    const float* x     = (const float*)d_in[0];
    const float* Wq    = (const float*)d_in[1];
    const float* Wk    = (const float*)d_in[2];
    const float* Wv    = (const float*)d_in[3];
    const float* Wproj = (const float*)d_in[4];
    const float* bproj = (const float*)d_in[5];
    const float* W1    = (const float*)d_in[6];
    const float* W2    = (const float*)d_in[7];
    const float* g1    = (const float*)d_in[8];
    const float* g2    = (const float*)d_in[9];
    float* out = (float*)d_out;

    float *p_xn, *p_qkv, *p_attn, *p_x1, *p_xn2, *p_hbuf, *p_Bqkv, *p_Wpr, *p_W1r, *p_W2r;
    cudaGetSymbolAddress((void**)&p_xn,   g_xn);
    cudaGetSymbolAddress((void**)&p_qkv,  g_qkv);
    cudaGetSymbolAddress((void**)&p_attn, g_attn);
    cudaGetSymbolAddress((void**)&p_x1,   g_x1);
    cudaGetSymbolAddress((void**)&p_xn2,  g_xn2);
    cudaGetSymbolAddress((void**)&p_hbuf, g_hbuf);
    cudaGetSymbolAddress((void**)&p_Bqkv, g_Bqkv);
    cudaGetSymbolAddress((void**)&p_Wpr,  g_Wpr);
    cudaGetSymbolAddress((void**)&p_W1r,  g_W1r);
    cudaGetSymbolAddress((void**)&p_W2r,  g_W2r);

    cudaFuncSetAttribute(gemm_kernel<0>, cudaFuncAttributeMaxDynamicSharedMemorySize, GEMM_SMEM);
    cudaFuncSetAttribute(gemm_kernel<1>, cudaFuncAttributeMaxDynamicSharedMemorySize, GEMM_SMEM);
    cudaFuncSetAttribute(gemm_kernel<2>, cudaFuncAttributeMaxDynamicSharedMemorySize, GEMM_SMEM);
    cudaFuncSetAttribute(gemm_kernel<3>, cudaFuncAttributeMaxDynamicSharedMemorySize, GEMM_SMEM);

    // prep: round / pack weights
    round_kernel<<<(DD * DD / 4 + 255) / 256, 256>>>(Wproj, p_Wpr, DD * DD / 4);
    round_kernel<<<(DD * FF / 4 + 255) / 256, 256>>>(W1, p_W1r, DD * FF / 4);
    round_kernel<<<(FF * DD / 4 + 255) / 256, 256>>>(W2, p_W2r, FF * DD / 4);
    pack_qkv_kernel<<<dim3(NQKV / 256, DD), 256>>>(Wq, Wk, Wv);

    rmsnorm_kernel<<<TT, 256>>>(x, g1, p_xn);
    gemm_kernel<0><<<dim3(NQKV / BN, TT / BM), 256, GEMM_SMEM>>>(
        p_xn, p_Bqkv, p_qkv, nullptr, nullptr, TT, NQKV, DD);
    attn_kernel<<<dim3(TT / 64, HH), 256>>>();
    gemm_kernel<1><<<dim3(DD / BN, TT / BM), 256, GEMM_SMEM>>>(
        p_attn, p_Wpr, p_x1, x, bproj, TT, DD, DD);
    rmsnorm_kernel<<<TT, 256>>>(p_x1, g2, p_xn2);
    gemm_kernel<2><<<dim3(FF / BN, TT / BM), 256, GEMM_SMEM>>>(
        p_xn2, p_W1r, p_hbuf, nullptr, nullptr, TT, FF, DD);
    gemm_kernel<3><<<dim3(DD / BN, TT / BM), 256, GEMM_SMEM>>>(
        p_hbuf, p_W2r, out, p_x1, nullptr, TT, DD, FF);
}

// round 3
// speedup vs baseline: 3.0889x; 1.4127x over previous
#include <cuda_runtime.h>
#include <cuda_bf16.h>
#include <math.h>

#define TT 2048
#define DD 1024
#define HH 16
#define HS 64
#define FF 4096
#define NQKV 3072

// ---------------- scratch (device globals, no allocation) ----------------
__device__ float g_xn[TT * DD];          // rmsnorm(x, g1), tf32-rounded
__device__ float g_qkv[TT * NQKV];       // [T][3072]: q | k | v, tf32-rounded
__device__ float g_attn[TT * DD];        // attention out, [T][H*64], tf32-rounded
__device__ float g_x1[TT * DD];          // x + attn proj
__device__ float g_xn2[TT * DD];         // rmsnorm(x1, g2), tf32-rounded
__device__ float g_hbuf[TT * FF];        // silu(xn2 @ W1), tf32-rounded
__device__ float g_Bqkv[DD * NQKV];      // packed+rounded QKV weights [D][3072]
__device__ float g_Wpr[DD * DD];         // rounded Wproj
__device__ float g_W1r[DD * FF];         // rounded W1
__device__ float g_W2r[FF * DD];         // rounded W2

// ---------------- helpers ----------------
__device__ __forceinline__ float f2tf(float f) {
    unsigned u;
    asm("cvt.rna.tf32.f32 %0, %1;" : "=r"(u) : "f"(f));
    return __uint_as_float(u);
}

__device__ __forceinline__ void cp16(void* s, const void* g) {
    unsigned saddr = (unsigned)__cvta_generic_to_shared(s);
    asm volatile("cp.async.cg.shared.global [%0], [%1], 16;\n" :: "r"(saddr), "l"(g));
}
__device__ __forceinline__ void cp_commit() { asm volatile("cp.async.commit_group;\n"); }
template <int N> __device__ __forceinline__ void cp_wait() {
    asm volatile("cp.async.wait_group %0;\n" :: "n"(N));
}

__device__ __forceinline__ void mma_tf32(float* c, const unsigned* a, const unsigned* b) {
    asm volatile(
        "mma.sync.aligned.m16n8k8.row.col.f32.tf32.tf32.f32 "
        "{%0,%1,%2,%3}, {%4,%5,%6,%7}, {%8,%9}, {%0,%1,%2,%3};"
        : "+f"(c[0]), "+f"(c[1]), "+f"(c[2]), "+f"(c[3])
        : "r"(a[0]), "r"(a[1]), "r"(a[2]), "r"(a[3]), "r"(b[0]), "r"(b[1]));
}

// ---------------- prep: round weights to tf32 ----------------
__global__ __launch_bounds__(256) void round_kernel(const float* __restrict__ in,
                                                    float* __restrict__ out, int n4) {
    int i = blockIdx.x * 256 + threadIdx.x;
    if (i >= n4) return;
    float4 v = ((const float4*)in)[i];
    v.x = f2tf(v.x); v.y = f2tf(v.y); v.z = f2tf(v.z); v.w = f2tf(v.w);
    ((float4*)out)[i] = v;
}

// pack Wq/Wk/Wv [H,D,HS] -> g_Bqkv[D][3072], n = which*1024 + h*64 + s
__global__ __launch_bounds__(256) void pack_qkv_kernel(const float* __restrict__ Wq,
                                                       const float* __restrict__ Wk,
                                                       const float* __restrict__ Wv) {
    int n = blockIdx.x * 256 + threadIdx.x;  // 0..3071
    int d = blockIdx.y;
    int which = n >> 10;
    int h = (n >> 6) & 15;
    int s = n & 63;
    const float* W = which == 0 ? Wq : which == 1 ? Wk : Wv;
    g_Bqkv[(size_t)d * NQKV + n] = f2tf(W[h * (DD * HS) + d * HS + s]);
}

// ---------------- rmsnorm (output tf32-rounded) ----------------
__global__ __launch_bounds__(256) void rmsnorm_kernel(const float* __restrict__ x,
                                                      const float* __restrict__ g,
                                                      float* __restrict__ out) {
    int row = blockIdx.x;
    const float* xr = x + (size_t)row * DD;
    float ss = 0.f;
    for (int i = threadIdx.x; i < DD; i += 256) { float v = xr[i]; ss += v * v; }
    __shared__ float red[8];
    #pragma unroll
    for (int o = 16; o; o >>= 1) ss += __shfl_xor_sync(0xffffffffu, ss, o);
    if ((threadIdx.x & 31) == 0) red[threadIdx.x >> 5] = ss;
    __syncthreads();
    if (threadIdx.x < 32) {
        float v = (threadIdx.x < 8) ? red[threadIdx.x] : 0.f;
        #pragma unroll
        for (int o = 4; o; o >>= 1) v += __shfl_xor_sync(0xffffffffu, v, o);
        if (threadIdx.x == 0) red[0] = v;
    }
    __syncthreads();
    float scale = rsqrtf(red[0] * (1.0f / DD) + 1e-6f);
    for (int i = threadIdx.x; i < DD; i += 256)
        out[(size_t)row * DD + i] = f2tf(xr[i] * scale * g[i]);
}

// ---------------- tf32 tensor-core GEMM: C[M,N] = A[M,K] @ B[K,N] ----------------
#define BM 128
#define BN 128
#define BK 32
#define APAD 36
#define BPAD 136
#define GEMM_SMEM ((2 * BM * APAD + 2 * BK * BPAD) * 4)

// MODE 0: C = tf32(acc)                        (qkv)
// MODE 1: C = acc + aux1[row,col] + aux2[col]  (proj + residual + bias)
// MODE 2: C = tf32(silu(acc))                  (ffn1)
// MODE 3: C = acc + aux1[row,col]              (ffn2 + residual)
template <int MODE>
__global__ __launch_bounds__(256, 1) void gemm_kernel(
    const float* __restrict__ A, const float* __restrict__ B, float* __restrict__ C,
    const float* __restrict__ aux1, const float* __restrict__ aux2,
    int M, int N, int K) {
    extern __shared__ float smem[];
    float* As = smem;                   // [2][BM][APAD]
    float* Bs = smem + 2 * BM * APAD;   // [2][BK][BPAD]

    const int tid = threadIdx.x;
    const int bx = blockIdx.x, by = blockIdx.y;
    const int warp = tid >> 5, lane = tid & 31;
    const int wm = warp & 3, wn = warp >> 2;   // warps 4(m) x 2(n)
    const int g = lane >> 2, t4 = lane & 3;

    const float* Ab = A + (size_t)by * BM * K;
    const float* Bb = B + (size_t)bx * BN;

    float acc[2][8][4];
    #pragma unroll
    for (int i = 0; i < 2; i++)
        #pragma unroll
        for (int j = 0; j < 8; j++)
            #pragma unroll
            for (int c = 0; c < 4; c++) acc[i][j][c] = 0.f;

    const int KT = K / BK;

    auto load_stage = [&](int kt, int buf) {
        float* Asb = As + buf * BM * APAD;
        float* Bsb = Bs + buf * BK * BPAD;
        #pragma unroll
        for (int i = 0; i < 4; i++) {
            int idx = tid + i * 256;
            int m = idx >> 3, c = idx & 7;
            cp16(Asb + m * APAD + c * 4, Ab + (size_t)m * K + kt * BK + c * 4);
        }
        #pragma unroll
        for (int i = 0; i < 4; i++) {
            int idx = tid + i * 256;
            int k = idx >> 5, c = idx & 31;
            cp16(Bsb + k * BPAD + c * 4, Bb + (size_t)(kt * BK + k) * N + c * 4);
        }
        cp_commit();
    };

    load_stage(0, 0);

    for (int kt = 0; kt < KT; kt++) {
        if (kt + 1 < KT) {
            load_stage(kt + 1, (kt + 1) & 1);
            cp_wait<1>();
        } else {
            cp_wait<0>();
        }
        __syncthreads();

        const float* As_ = As + (kt & 1) * BM * APAD;
        const float* Bs_ = Bs + (kt & 1) * BK * BPAD;
        #pragma unroll
        for (int ks = 0; ks < 4; ks++) {
            const int k = ks * 8;
            unsigned a[2][4], b[8][2];
            #pragma unroll
            for (int mi = 0; mi < 2; mi++) {
                int rb = wm * 32 + mi * 16;
                a[mi][0] = __float_as_uint(As_[(rb + g) * APAD + k + t4]);
                a[mi][1] = __float_as_uint(As_[(rb + g + 8) * APAD + k + t4]);
                a[mi][2] = __float_as_uint(As_[(rb + g) * APAD + k + t4 + 4]);
                a[mi][3] = __float_as_uint(As_[(rb + g + 8) * APAD + k + t4 + 4]);
            }
            #pragma unroll
            for (int ni = 0; ni < 8; ni++) {
                int col = wn * 64 + ni * 8 + g;
                b[ni][0] = __float_as_uint(Bs_[(k + t4) * BPAD + col]);
                b[ni][1] = __float_as_uint(Bs_[(k + t4 + 4) * BPAD + col]);
            }
            #pragma unroll
            for (int mi = 0; mi < 2; mi++)
                #pragma unroll
                for (int ni = 0; ni < 8; ni++)
                    mma_tf32(acc[mi][ni], a[mi], b[ni]);
        }
        __syncthreads();
    }

    #pragma unroll
    for (int mi = 0; mi < 2; mi++)
        #pragma unroll
        for (int r2 = 0; r2 < 2; r2++) {
            int row = by * BM + wm * 32 + mi * 16 + g + r2 * 8;
            #pragma unroll
            for (int ni = 0; ni < 8; ni++) {
                int col = bx * BN + wn * 64 + ni * 8 + t4 * 2;
                float v0 = acc[mi][ni][r2 * 2 + 0];
                float v1 = acc[mi][ni][r2 * 2 + 1];
                size_t oidx = (size_t)row * N + col;
                if (MODE == 0) {
                    C[oidx] = f2tf(v0); C[oidx + 1] = f2tf(v1);
                } else if (MODE == 1) {
                    C[oidx] = v0 + aux1[oidx] + aux2[col];
                    C[oidx + 1] = v1 + aux1[oidx + 1] + aux2[col + 1];
                } else if (MODE == 2) {
                    C[oidx] = f2tf(v0 / (1.0f + __expf(-v0)));
                    C[oidx + 1] = f2tf(v1 / (1.0f + __expf(-v1)));
                } else {
                    size_t ridx = (size_t)row * DD + col;
                    C[oidx] = v0 + aux1[ridx];
                    C[oidx + 1] = v1 + aux1[ridx + 1];
                }
            }
        }
}

// ---------------- tensor-core causal flash attention ----------------
// BQ=128 rows/CTA, 8 warps (16 rows each), KV tiles 64 wide.
// smem: QPs[128][68] (Q then P, per-warp private rows), Ks[64][68], Vs[64][72]
#define AQP 68
#define AKP 68
#define AVP 72
#define ATTN_SMEM ((128 * AQP + 64 * AKP + 64 * AVP) * 4)

__global__ __launch_bounds__(256, 2) void attn_kernel() {
    extern __shared__ float as_[];
    float* QPs = as_;                    // [128][AQP]
    float* Ks  = as_ + 128 * AQP;        // [64][AKP]
    float* Vs  = Ks + 64 * AKP;          // [64][AVP]

    const int h = blockIdx.y;
    const int qb = gridDim.x - 1 - blockIdx.x;
    const int q0 = qb * 128;
    const float* Qh = g_qkv + h * HS;
    const float* Kh = g_qkv + DD + h * HS;
    const float* Vh = g_qkv + 2 * DD + h * HS;

    const int tid = threadIdx.x;
    const int warp = tid >> 5, lane = tid & 31;
    const int g = lane >> 2, t4 = lane & 3;
    const int r0 = warp * 16;

    // stage Q tile (128 x 64)
    #pragma unroll
    for (int i = 0; i < 8; i++) {
        int idx = tid + i * 256;
        int r = idx >> 4, c = (idx & 15) * 4;
        cp16(QPs + r * AQP + c, Qh + (size_t)(q0 + r) * NQKV + c);
    }
    cp_commit(); cp_wait<0>();
    __syncthreads();

    // Q fragments (scale 1/8 folded in: exact, stays tf32)
    unsigned qa[8][4];
    #pragma unroll
    for (int kf = 0; kf < 8; kf++) {
        qa[kf][0] = __float_as_uint(QPs[(r0 + g) * AQP + kf * 8 + t4] * 0.125f);
        qa[kf][1] = __float_as_uint(QPs[(r0 + g + 8) * AQP + kf * 8 + t4] * 0.125f);
        qa[kf][2] = __float_as_uint(QPs[(r0 + g) * AQP + kf * 8 + t4 + 4] * 0.125f);
        qa[kf][3] = __float_as_uint(QPs[(r0 + g + 8) * AQP + kf * 8 + t4 + 4] * 0.125f);
    }

    float acc[8][4];
    #pragma unroll
    for (int ni = 0; ni < 8; ni++)
        #pragma unroll
        for (int c = 0; c < 4; c++) acc[ni][c] = 0.f;
    float m0 = -1e30f, m1 = -1e30f, l0 = 0.f, l1 = 0.f;
    const int row0 = q0 + r0 + g, row1 = row0 + 8;

    const int nkb = 2 * qb + 2;
    for (int kb = 0; kb < nkb; kb++) {
        const int k0t = kb * 64;
        __syncthreads();  // prev iter done reading Ks/Vs
        #pragma unroll
        for (int i = 0; i < 4; i++) {
            int idx = tid + i * 256;
            int j = idx >> 4, c = (idx & 15) * 4;
            cp16(Ks + j * AKP + c, Kh + (size_t)(k0t + j) * NQKV + c);
            cp16(Vs + j * AVP + c, Vh + (size_t)(k0t + j) * NQKV + c);
        }
        cp_commit(); cp_wait<0>();
        __syncthreads();

        // S = (Q/8) K^T
        float s[8][4];
        #pragma unroll
        for (int ni = 0; ni < 8; ni++)
            #pragma unroll
            for (int c = 0; c < 4; c++) s[ni][c] = 0.f;
        #pragma unroll
        for (int kf = 0; kf < 8; kf++) {
            unsigned b[8][2];
            #pragma unroll
            for (int ni = 0; ni < 8; ni++) {
                b[ni][0] = __float_as_uint(Ks[(ni * 8 + g) * AKP + kf * 8 + t4]);
                b[ni][1] = __float_as_uint(Ks[(ni * 8 + g) * AKP + kf * 8 + t4 + 4]);
            }
            #pragma unroll
            for (int ni = 0; ni < 8; ni++)
                mma_tf32(s[ni], qa[kf], b[ni]);
        }

        // causal mask
        if (k0t + 63 > row0) {
            #pragma unroll
            for (int ni = 0; ni < 8; ni++) {
                int col = k0t + ni * 8 + t4 * 2;
                if (col > row0) s[ni][0] = -1e30f;
                if (col + 1 > row0) s[ni][1] = -1e30f;
                if (col > row1) s[ni][2] = -1e30f;
                if (col + 1 > row1) s[ni][3] = -1e30f;
            }
        }

        // online softmax
        float tm0 = -1e30f, tm1 = -1e30f;
        #pragma unroll
        for (int ni = 0; ni < 8; ni++) {
            tm0 = fmaxf(tm0, fmaxf(s[ni][0], s[ni][1]));
            tm1 = fmaxf(tm1, fmaxf(s[ni][2], s[ni][3]));
        }
        tm0 = fmaxf(tm0, __shfl_xor_sync(0xffffffffu, tm0, 1));
        tm0 = fmaxf(tm0, __shfl_xor_sync(0xffffffffu, tm0, 2));
        tm1 = fmaxf(tm1, __shfl_xor_sync(0xffffffffu, tm1, 1));
        tm1 = fmaxf(tm1, __shfl_xor_sync(0xffffffffu, tm1, 2));
        float mn0 = fmaxf(m0, tm0), mn1 = fmaxf(m1, tm1);
        float f0 = __expf(m0 - mn0), f1 = __expf(m1 - mn1);
        m0 = mn0; m1 = mn1;
        float sum0 = 0.f, sum1 = 0.f;
        #pragma unroll
        for (int ni = 0; ni < 8; ni++) {
            s[ni][0] = __expf(s[ni][0] - mn0);
            s[ni][1] = __expf(s[ni][1] - mn0);
            s[ni][2] = __expf(s[ni][2] - mn1);
            s[ni][3] = __expf(s[ni][3] - mn1);
            sum0 += s[ni][0] + s[ni][1];
            sum1 += s[ni][2] + s[ni][3];
        }
        sum0 += __shfl_xor_sync(0xffffffffu, sum0, 1);
        sum0 += __shfl_xor_sync(0xffffffffu, sum0, 2);
        sum1 += __shfl_xor_sync(0xffffffffu, sum1, 1);
        sum1 += __shfl_xor_sync(0xffffffffu, sum1, 2);
        l0 = l0 * f0 + sum0;
        l1 = l1 * f1 + sum1;
        #pragma unroll
        for (int ni = 0; ni < 8; ni++) {
            acc[ni][0] *= f0; acc[ni][1] *= f0;
            acc[ni][2] *= f1; acc[ni][3] *= f1;
        }

        // P -> smem (own warp rows only; no block sync needed)
        #pragma unroll
        for (int ni = 0; ni < 8; ni++) {
            *(float2*)&QPs[(r0 + g) * AQP + ni * 8 + t4 * 2] =
                make_float2(f2tf(s[ni][0]), f2tf(s[ni][1]));
            *(float2*)&QPs[(r0 + g + 8) * AQP + ni * 8 + t4 * 2] =
                make_float2(f2tf(s[ni][2]), f2tf(s[ni][3]));
        }
        __syncwarp();

        // O += P V
        #pragma unroll
        for (int kf = 0; kf < 8; kf++) {
            unsigned pa[4];
            pa[0] = __float_as_uint(QPs[(r0 + g) * AQP + kf * 8 + t4]);
            pa[1] = __float_as_uint(QPs[(r0 + g + 8) * AQP + kf * 8 + t4]);
            pa[2] = __float_as_uint(QPs[(r0 + g) * AQP + kf * 8 + t4 + 4]);
            pa[3] = __float_as_uint(QPs[(r0 + g + 8) * AQP + kf * 8 + t4 + 4]);
            unsigned vb[8][2];
            #pragma unroll
            for (int ni = 0; ni < 8; ni++) {
                vb[ni][0] = __float_as_uint(Vs[(kf * 8 + t4) * AVP + ni * 8 + g]);
                vb[ni][1] = __float_as_uint(Vs[(kf * 8 + t4 + 4) * AVP + ni * 8 + g]);
            }
            #pragma unroll
            for (int ni = 0; ni < 8; ni++)
                mma_tf32(acc[ni], pa, vb[ni]);
        }
    }

    float inv0 = 1.0f / l0, inv1 = 1.0f / l1;
    #pragma unroll
    for (int ni = 0; ni < 8; ni++) {
        int col = h * HS + ni * 8 + t4 * 2;
        float* o0 = &g_attn[(size_t)row0 * DD + col];
        o0[0] = f2tf(acc[ni][0] * inv0);
        o0[1] = f2tf(acc[ni][1] * inv0);
        float* o1 = &g_attn[(size_t)row1 * DD + col];
        o1[0] = f2tf(acc[ni][2] * inv1);
        o1[1] = f2tf(acc[ni][3] * inv1);
    }
}

// ---------------- launch ----------------
extern "C" void kernel_launch(void* const* d_in, const int* in_sizes, int n_in,
                              void* d_out, int out_size) {
    const float* x     = (const float*)d_in[0];
    const float* Wq    = (const float*)d_in[1];
    const float* Wk    = (const float*)d_in[2];
    const float* Wv    = (const float*)d_in[3];
    const float* Wproj = (const float*)d_in[4];
    const float* bproj = (const float*)d_in[5];
    const float* W1    = (const float*)d_in[6];
    const float* W2    = (const float*)d_in[7];
    const float* g1    = (const float*)d_in[8];
    const float* g2    = (const float*)d_in[9];
    float* out = (float*)d_out;

    float *p_xn, *p_qkv, *p_attn, *p_x1, *p_xn2, *p_hbuf, *p_Bqkv, *p_Wpr, *p_W1r, *p_W2r;
    cudaGetSymbolAddress((void**)&p_xn,   g_xn);
    cudaGetSymbolAddress((void**)&p_qkv,  g_qkv);
    cudaGetSymbolAddress((void**)&p_attn, g_attn);
    cudaGetSymbolAddress((void**)&p_x1,   g_x1);
    cudaGetSymbolAddress((void**)&p_xn2,  g_xn2);
    cudaGetSymbolAddress((void**)&p_hbuf, g_hbuf);
    cudaGetSymbolAddress((void**)&p_Bqkv, g_Bqkv);
    cudaGetSymbolAddress((void**)&p_Wpr,  g_Wpr);
    cudaGetSymbolAddress((void**)&p_W1r,  g_W1r);
    cudaGetSymbolAddress((void**)&p_W2r,  g_W2r);

    cudaFuncSetAttribute(gemm_kernel<0>, cudaFuncAttributeMaxDynamicSharedMemorySize, GEMM_SMEM);
    cudaFuncSetAttribute(gemm_kernel<1>, cudaFuncAttributeMaxDynamicSharedMemorySize, GEMM_SMEM);
    cudaFuncSetAttribute(gemm_kernel<2>, cudaFuncAttributeMaxDynamicSharedMemorySize, GEMM_SMEM);
    cudaFuncSetAttribute(gemm_kernel<3>, cudaFuncAttributeMaxDynamicSharedMemorySize, GEMM_SMEM);
    cudaFuncSetAttribute(attn_kernel, cudaFuncAttributeMaxDynamicSharedMemorySize, ATTN_SMEM);

    // prep: round / pack weights
    round_kernel<<<(DD * DD / 4 + 255) / 256, 256>>>(Wproj, p_Wpr, DD * DD / 4);
    round_kernel<<<(DD * FF / 4 + 255) / 256, 256>>>(W1, p_W1r, DD * FF / 4);
    round_kernel<<<(FF * DD / 4 + 255) / 256, 256>>>(W2, p_W2r, FF * DD / 4);
    pack_qkv_kernel<<<dim3(NQKV / 256, DD), 256>>>(Wq, Wk, Wv);

    rmsnorm_kernel<<<TT, 256>>>(x, g1, p_xn);
    gemm_kernel<0><<<dim3(NQKV / BN, TT / BM), 256, GEMM_SMEM>>>(
        p_xn, p_Bqkv, p_qkv, nullptr, nullptr, TT, NQKV, DD);
    attn_kernel<<<dim3(TT / 128, HH), 256, ATTN_SMEM>>>();
    gemm_kernel<1><<<dim3(DD / BN, TT / BM), 256, GEMM_SMEM>>>(
        p_attn, p_Wpr, p_x1, x, bproj, TT, DD, DD);
    rmsnorm_kernel<<<TT, 256>>>(p_x1, g2, p_xn2);
    gemm_kernel<2><<<dim3(FF / BN, TT / BM), 256, GEMM_SMEM>>>(
        p_xn2, p_W1r, p_hbuf, nullptr, nullptr, TT, FF, DD);
    gemm_kernel<3><<<dim3(DD / BN, TT / BM), 256, GEMM_SMEM>>>(
        p_hbuf, p_W2r, out, p_x1, nullptr, TT, DD, FF);
}

// round 5
// speedup vs baseline: 3.1068x; 1.0058x over previous
#include <cuda_runtime.h>
#include <cuda_bf16.h>
#include <math.h>

#define TT 2048
#define DD 1024
#define HH 16
#define HS 64
#define FF 4096
#define NQKV 3072

// ---------------- scratch (device globals, no allocation) ----------------
__device__ float g_xn[TT * DD];          // rmsnorm(x, g1), tf32-rounded
__device__ float g_qkv[TT * NQKV];       // [T][3072]: q | k | v, tf32-rounded
__device__ float g_attn[TT * DD];        // attention out, [T][H*64], tf32-rounded
__device__ float g_x1[TT * DD];          // x + attn proj
__device__ float g_xn2[TT * DD];         // rmsnorm(x1, g2), tf32-rounded
__device__ float g_hbuf[TT * FF];        // silu(xn2 @ W1), tf32-rounded
__device__ float g_Bqkv[DD * NQKV];      // packed+rounded QKV weights [D][3072]
__device__ float g_Wpr[DD * DD];         // rounded Wproj
__device__ float g_W1r[DD * FF];         // rounded W1
__device__ float g_W2r[FF * DD];         // rounded W2

// ---------------- helpers ----------------
__device__ __forceinline__ float f2tf(float f) {
    unsigned u;
    asm("cvt.rna.tf32.f32 %0, %1;" : "=r"(u) : "f"(f));
    return __uint_as_float(u);
}

__device__ __forceinline__ void cp16(void* s, const void* g) {
    unsigned saddr = (unsigned)__cvta_generic_to_shared(s);
    asm volatile("cp.async.cg.shared.global [%0], [%1], 16;\n" :: "r"(saddr), "l"(g));
}
__device__ __forceinline__ void cp_commit() { asm volatile("cp.async.commit_group;\n"); }
template <int N> __device__ __forceinline__ void cp_wait() {
    asm volatile("cp.async.wait_group %0;\n" :: "n"(N));
}

__device__ __forceinline__ void mma_tf32(float* c, const unsigned* a, const unsigned* b) {
    asm volatile(
        "mma.sync.aligned.m16n8k8.row.col.f32.tf32.tf32.f32 "
        "{%0,%1,%2,%3}, {%4,%5,%6,%7}, {%8,%9}, {%0,%1,%2,%3};"
        : "+f"(c[0]), "+f"(c[1]), "+f"(c[2]), "+f"(c[3])
        : "r"(a[0]), "r"(a[1]), "r"(a[2]), "r"(a[3]), "r"(b[0]), "r"(b[1]));
}

// ---------------- prep: round weights to tf32 ----------------
__global__ __launch_bounds__(256) void round_kernel(const float* __restrict__ in,
                                                    float* __restrict__ out, int n4) {
    int i = blockIdx.x * 256 + threadIdx.x;
    if (i >= n4) return;
    float4 v = ((const float4*)in)[i];
    v.x = f2tf(v.x); v.y = f2tf(v.y); v.z = f2tf(v.z); v.w = f2tf(v.w);
    ((float4*)out)[i] = v;
}

// pack Wq/Wk/Wv [H,D,HS] -> g_Bqkv[D][3072], n = which*1024 + h*64 + s
__global__ __launch_bounds__(256) void pack_qkv_kernel(const float* __restrict__ Wq,
                                                       const float* __restrict__ Wk,
                                                       const float* __restrict__ Wv) {
    int n = blockIdx.x * 256 + threadIdx.x;  // 0..3071
    int d = blockIdx.y;
    int which = n >> 10;
    int h = (n >> 6) & 15;
    int s = n & 63;
    const float* W = which == 0 ? Wq : which == 1 ? Wk : Wv;
    g_Bqkv[(size_t)d * NQKV + n] = f2tf(W[h * (DD * HS) + d * HS + s]);
}

// ---------------- rmsnorm (output tf32-rounded) ----------------
__global__ __launch_bounds__(256) void rmsnorm_kernel(const float* __restrict__ x,
                                                      const float* __restrict__ g,
                                                      float* __restrict__ out) {
    int row = blockIdx.x;
    const float* xr = x + (size_t)row * DD;
    float ss = 0.f;
    for (int i = threadIdx.x; i < DD; i += 256) { float v = xr[i]; ss += v * v; }
    __shared__ float red[8];
    #pragma unroll
    for (int o = 16; o; o >>= 1) ss += __shfl_xor_sync(0xffffffffu, ss, o);
    if ((threadIdx.x & 31) == 0) red[threadIdx.x >> 5] = ss;
    __syncthreads();
    if (threadIdx.x < 32) {
        float v = (threadIdx.x < 8) ? red[threadIdx.x] : 0.f;
        #pragma unroll
        for (int o = 4; o; o >>= 1) v += __shfl_xor_sync(0xffffffffu, v, o);
        if (threadIdx.x == 0) red[0] = v;
    }
    __syncthreads();
    float scale = rsqrtf(red[0] * (1.0f / DD) + 1e-6f);
    for (int i = threadIdx.x; i < DD; i += 256)
        out[(size_t)row * DD + i] = f2tf(xr[i] * scale * g[i]);
}

// ---------------- tf32 tensor-core GEMM, 3-stage pipeline ----------------
// BM=128 BN=128 BK=32, 128 threads (4 warps), warp tile 64x64
#define BM 128
#define BN 128
#define BK 32
#define APITCH 36
#define BPITCH 132
#define STG_A (BM * APITCH)
#define STG_B (BK * BPITCH)
#define STG_F (STG_A + STG_B)
#define GEMM_SMEM (3 * STG_F * 4)

// MODE 0: C = tf32(acc)                        (qkv)
// MODE 1: C = acc + aux1[row,col] + aux2[col]  (proj + residual + bias)
// MODE 2: C = tf32(silu(acc))                  (ffn1)
// MODE 3: C = acc + aux1[row,col]              (ffn2 + residual)
template <int MODE>
__global__ __launch_bounds__(128) void gemm_kernel(
    const float* __restrict__ A, const float* __restrict__ B, float* __restrict__ C,
    const float* __restrict__ aux1, const float* __restrict__ aux2,
    int M, int N, int K) {
    extern __shared__ float smem[];

    const int tid = threadIdx.x;
    const int bx = blockIdx.x, by = blockIdx.y;
    const int warp = tid >> 5, lane = tid & 31;
    const int wm = warp & 1, wn = warp >> 1;   // warps 2(m) x 2(n)
    const int g = lane >> 2, t4 = lane & 3;

    const float* Ab = A + (size_t)by * BM * K;
    const float* Bb = B + (size_t)bx * BN;

    float acc[4][8][4];
    #pragma unroll
    for (int i = 0; i < 4; i++)
        #pragma unroll
        for (int j = 0; j < 8; j++)
            #pragma unroll
            for (int c = 0; c < 4; c++) acc[i][j][c] = 0.f;

    const int KT = K / BK;

    auto load_stage = [&](int kt, int buf) {
        float* Asb = smem + buf * STG_F;
        float* Bsb = Asb + STG_A;
        #pragma unroll
        for (int i = 0; i < 8; i++) {
            int idx = tid + i * 128;
            int m = idx >> 3, c = idx & 7;
            cp16(Asb + m * APITCH + c * 4, Ab + (size_t)m * K + kt * BK + c * 4);
        }
        #pragma unroll
        for (int i = 0; i < 8; i++) {
            int idx = tid + i * 128;
            int k = idx >> 5, c = idx & 31;
            cp16(Bsb + k * BPITCH + c * 4, Bb + (size_t)(kt * BK + k) * N + c * 4);
        }
        cp_commit();
    };

    load_stage(0, 0);
    load_stage(1, 1);

    int buf = 0;
    for (int kt = 0; kt < KT; kt++) {
        if (kt + 1 < KT) cp_wait<1>(); else cp_wait<0>();
        __syncthreads();
        if (kt + 2 < KT) {
            int nb = buf + 2; if (nb >= 3) nb -= 3;
            load_stage(kt + 2, nb);
        }

        const float* As_ = smem + buf * STG_F;
        const float* Bs_ = As_ + STG_A;
        #pragma unroll
        for (int ks = 0; ks < 4; ks++) {
            const int k = ks * 8;
            unsigned a[4][4], b[8][2];
            #pragma unroll
            for (int mi = 0; mi < 4; mi++) {
                int rb = wm * 64 + mi * 16;
                a[mi][0] = __float_as_uint(As_[(rb + g) * APITCH + k + t4]);
                a[mi][1] = __float_as_uint(As_[(rb + g + 8) * APITCH + k + t4]);
                a[mi][2] = __float_as_uint(As_[(rb + g) * APITCH + k + t4 + 4]);
                a[mi][3] = __float_as_uint(As_[(rb + g + 8) * APITCH + k + t4 + 4]);
            }
            #pragma unroll
            for (int ni = 0; ni < 8; ni++) {
                int col = wn * 64 + ni * 8 + g;
                b[ni][0] = __float_as_uint(Bs_[(k + t4) * BPITCH + col]);
                b[ni][1] = __float_as_uint(Bs_[(k + t4 + 4) * BPITCH + col]);
            }
            #pragma unroll
            for (int mi = 0; mi < 4; mi++)
                #pragma unroll
                for (int ni = 0; ni < 8; ni++)
                    mma_tf32(acc[mi][ni], a[mi], b[ni]);
        }
        buf++; if (buf >= 3) buf -= 3;
    }

    // epilogue
    #pragma unroll
    for (int mi = 0; mi < 4; mi++)
        #pragma unroll
        for (int r2 = 0; r2 < 2; r2++) {
            int row = by * BM + wm * 64 + mi * 16 + g + r2 * 8;
            #pragma unroll
            for (int ni = 0; ni < 8; ni++) {
                int col = bx * BN + wn * 64 + ni * 8 + t4 * 2;
                float v0 = acc[mi][ni][r2 * 2 + 0];
                float v1 = acc[mi][ni][r2 * 2 + 1];
                size_t oidx = (size_t)row * N + col;
                if (MODE == 0) {
                    C[oidx] = f2tf(v0); C[oidx + 1] = f2tf(v1);
                } else if (MODE == 1) {
                    C[oidx] = v0 + aux1[oidx] + aux2[col];
                    C[oidx + 1] = v1 + aux1[oidx + 1] + aux2[col + 1];
                } else if (MODE == 2) {
                    C[oidx] = f2tf(v0 / (1.0f + __expf(-v0)));
                    C[oidx + 1] = f2tf(v1 / (1.0f + __expf(-v1)));
                } else {
                    size_t ridx = (size_t)row * DD + col;
                    C[oidx] = v0 + aux1[ridx];
                    C[oidx + 1] = v1 + aux1[ridx + 1];
                }
            }
        }
}

// ---------------- tensor-core causal flash attention ----------------
#define AQP 68
#define AKP 68
#define AVP 72
#define ATTN_SMEM ((128 * AQP + 64 * AKP + 64 * AVP) * 4)

__global__ __launch_bounds__(256, 2) void attn_kernel() {
    extern __shared__ float as_[];
    float* QPs = as_;                    // [128][AQP]
    float* Ks  = as_ + 128 * AQP;        // [64][AKP]
    float* Vs  = Ks + 64 * AKP;          // [64][AVP]

    const int h = blockIdx.y;
    const int qb = gridDim.x - 1 - blockIdx.x;
    const int q0 = qb * 128;
    const float* Qh = g_qkv + h * HS;
    const float* Kh = g_qkv + DD + h * HS;
    const float* Vh = g_qkv + 2 * DD + h * HS;

    const int tid = threadIdx.x;
    const int warp = tid >> 5, lane = tid & 31;
    const int g = lane >> 2, t4 = lane & 3;
    const int r0 = warp * 16;

    #pragma unroll
    for (int i = 0; i < 8; i++) {
        int idx = tid + i * 256;
        int r = idx >> 4, c = (idx & 15) * 4;
        cp16(QPs + r * AQP + c, Qh + (size_t)(q0 + r) * NQKV + c);
    }
    cp_commit(); cp_wait<0>();
    __syncthreads();

    unsigned qa[8][4];
    #pragma unroll
    for (int kf = 0; kf < 8; kf++) {
        qa[kf][0] = __float_as_uint(QPs[(r0 + g) * AQP + kf * 8 + t4] * 0.125f);
        qa[kf][1] = __float_as_uint(QPs[(r0 + g + 8) * AQP + kf * 8 + t4] * 0.125f);
        qa[kf][2] = __float_as_uint(QPs[(r0 + g) * AQP + kf * 8 + t4 + 4] * 0.125f);
        qa[kf][3] = __float_as_uint(QPs[(r0 + g + 8) * AQP + kf * 8 + t4 + 4] * 0.125f);
    }

    float acc[8][4];
    #pragma unroll
    for (int ni = 0; ni < 8; ni++)
        #pragma unroll
        for (int c = 0; c < 4; c++) acc[ni][c] = 0.f;
    float m0 = -1e30f, m1 = -1e30f, l0 = 0.f, l1 = 0.f;
    const int row0 = q0 + r0 + g, row1 = row0 + 8;

    const int nkb = 2 * qb + 2;
    for (int kb = 0; kb < nkb; kb++) {
        const int k0t = kb * 64;
        __syncthreads();
        #pragma unroll
        for (int i = 0; i < 4; i++) {
            int idx = tid + i * 256;
            int j = idx >> 4, c = (idx & 15) * 4;
            cp16(Ks + j * AKP + c, Kh + (size_t)(k0t + j) * NQKV + c);
            cp16(Vs + j * AVP + c, Vh + (size_t)(k0t + j) * NQKV + c);
        }
        cp_commit(); cp_wait<0>();
        __syncthreads();

        float s[8][4];
        #pragma unroll
        for (int ni = 0; ni < 8; ni++)
            #pragma unroll
            for (int c = 0; c < 4; c++) s[ni][c] = 0.f;
        #pragma unroll
        for (int kf = 0; kf < 8; kf++) {
            unsigned b[8][2];
            #pragma unroll
            for (int ni = 0; ni < 8; ni++) {
                b[ni][0] = __float_as_uint(Ks[(ni * 8 + g) * AKP + kf * 8 + t4]);
                b[ni][1] = __float_as_uint(Ks[(ni * 8 + g) * AKP + kf * 8 + t4 + 4]);
            }
            #pragma unroll
            for (int ni = 0; ni < 8; ni++)
                mma_tf32(s[ni], qa[kf], b[ni]);
        }

        if (k0t + 63 > row0) {
            #pragma unroll
            for (int ni = 0; ni < 8; ni++) {
                int col = k0t + ni * 8 + t4 * 2;
                if (col > row0) s[ni][0] = -1e30f;
                if (col + 1 > row0) s[ni][1] = -1e30f;
                if (col > row1) s[ni][2] = -1e30f;
                if (col + 1 > row1) s[ni][3] = -1e30f;
            }
        }

        float tm0 = -1e30f, tm1 = -1e30f;
        #pragma unroll
        for (int ni = 0; ni < 8; ni++) {
            tm0 = fmaxf(tm0, fmaxf(s[ni][0], s[ni][1]));
            tm1 = fmaxf(tm1, fmaxf(s[ni][2], s[ni][3]));
        }
        tm0 = fmaxf(tm0, __shfl_xor_sync(0xffffffffu, tm0, 1));
        tm0 = fmaxf(tm0, __shfl_xor_sync(0xffffffffu, tm0, 2));
        tm1 = fmaxf(tm1, __shfl_xor_sync(0xffffffffu, tm1, 1));
        tm1 = fmaxf(tm1, __shfl_xor_sync(0xffffffffu, tm1, 2));
        float mn0 = fmaxf(m0, tm0), mn1 = fmaxf(m1, tm1);
        float f0 = __expf(m0 - mn0), f1 = __expf(m1 - mn1);
        m0 = mn0; m1 = mn1;
        float sum0 = 0.f, sum1 = 0.f;
        #pragma unroll
        for (int ni = 0; ni < 8; ni++) {
            s[ni][0] = __expf(s[ni][0] - mn0);
            s[ni][1] = __expf(s[ni][1] - mn0);
            s[ni][2] = __expf(s[ni][2] - mn1);
            s[ni][3] = __expf(s[ni][3] - mn1);
            sum0 += s[ni][0] + s[ni][1];
            sum1 += s[ni][2] + s[ni][3];
        }
        sum0 += __shfl_xor_sync(0xffffffffu, sum0, 1);
        sum0 += __shfl_xor_sync(0xffffffffu, sum0, 2);
        sum1 += __shfl_xor_sync(0xffffffffu, sum1, 1);
        sum1 += __shfl_xor_sync(0xffffffffu, sum1, 2);
        l0 = l0 * f0 + sum0;
        l1 = l1 * f1 + sum1;
        #pragma unroll
        for (int ni = 0; ni < 8; ni++) {
            acc[ni][0] *= f0; acc[ni][1] *= f0;
            acc[ni][2] *= f1; acc[ni][3] *= f1;
        }

        #pragma unroll
        for (int ni = 0; ni < 8; ni++) {
            *(float2*)&QPs[(r0 + g) * AQP + ni * 8 + t4 * 2] =
                make_float2(f2tf(s[ni][0]), f2tf(s[ni][1]));
            *(float2*)&QPs[(r0 + g + 8) * AQP + ni * 8 + t4 * 2] =
                make_float2(f2tf(s[ni][2]), f2tf(s[ni][3]));
        }
        __syncwarp();

        #pragma unroll
        for (int kf = 0; kf < 8; kf++) {
            unsigned pa[4];
            pa[0] = __float_as_uint(QPs[(r0 + g) * AQP + kf * 8 + t4]);
            pa[1] = __float_as_uint(QPs[(r0 + g + 8) * AQP + kf * 8 + t4]);
            pa[2] = __float_as_uint(QPs[(r0 + g) * AQP + kf * 8 + t4 + 4]);
            pa[3] = __float_as_uint(QPs[(r0 + g + 8) * AQP + kf * 8 + t4 + 4]);
            unsigned vb[8][2];
            #pragma unroll
            for (int ni = 0; ni < 8; ni++) {
                vb[ni][0] = __float_as_uint(Vs[(kf * 8 + t4) * AVP + ni * 8 + g]);
                vb[ni][1] = __float_as_uint(Vs[(kf * 8 + t4 + 4) * AVP + ni * 8 + g]);
            }
            #pragma unroll
            for (int ni = 0; ni < 8; ni++)
                mma_tf32(acc[ni], pa, vb[ni]);
        }
    }

    float inv0 = 1.0f / l0, inv1 = 1.0f / l1;
    #pragma unroll
    for (int ni = 0; ni < 8; ni++) {
        int col = h * HS + ni * 8 + t4 * 2;
        float* o0 = &g_attn[(size_t)row0 * DD + col];
        o0[0] = f2tf(acc[ni][0] * inv0);
        o0[1] = f2tf(acc[ni][1] * inv0);
        float* o1 = &g_attn[(size_t)row1 * DD + col];
        o1[0] = f2tf(acc[ni][2] * inv1);
        o1[1] = f2tf(acc[ni][3] * inv1);
    }
}

// ---------------- launch ----------------
extern "C" void kernel_launch(void* const* d_in, const int* in_sizes, int n_in,
                              void* d_out, int out_size) {
    const float* x     = (const float*)d_in[0];
    const float* Wq    = (const float*)d_in[1];
    const float* Wk    = (const float*)d_in[2];
    const float* Wv    = (const float*)d_in[3];
    const float* Wproj = (const float*)d_in[4];
    const float* bproj = (const float*)d_in[5];
    const float* W1    = (const float*)d_in[6];
    const float* W2    = (const float*)d_in[7];
    const float* g1    = (const float*)d_in[8];
    const float* g2    = (const float*)d_in[9];
    float* out = (float*)d_out;

    float *p_xn, *p_qkv, *p_attn, *p_x1, *p_xn2, *p_hbuf, *p_Bqkv, *p_Wpr, *p_W1r, *p_W2r;
    cudaGetSymbolAddress((void**)&p_xn,   g_xn);
    cudaGetSymbolAddress((void**)&p_qkv,  g_qkv);
    cudaGetSymbolAddress((void**)&p_attn, g_attn);
    cudaGetSymbolAddress((void**)&p_x1,   g_x1);
    cudaGetSymbolAddress((void**)&p_xn2,  g_xn2);
    cudaGetSymbolAddress((void**)&p_hbuf, g_hbuf);
    cudaGetSymbolAddress((void**)&p_Bqkv, g_Bqkv);
    cudaGetSymbolAddress((void**)&p_Wpr,  g_Wpr);
    cudaGetSymbolAddress((void**)&p_W1r,  g_W1r);
    cudaGetSymbolAddress((void**)&p_W2r,  g_W2r);

    cudaFuncSetAttribute(gemm_kernel<0>, cudaFuncAttributeMaxDynamicSharedMemorySize, GEMM_SMEM);
    cudaFuncSetAttribute(gemm_kernel<1>, cudaFuncAttributeMaxDynamicSharedMemorySize, GEMM_SMEM);
    cudaFuncSetAttribute(gemm_kernel<2>, cudaFuncAttributeMaxDynamicSharedMemorySize, GEMM_SMEM);
    cudaFuncSetAttribute(gemm_kernel<3>, cudaFuncAttributeMaxDynamicSharedMemorySize, GEMM_SMEM);
    cudaFuncSetAttribute(attn_kernel, cudaFuncAttributeMaxDynamicSharedMemorySize, ATTN_SMEM);

    // prep: round / pack weights
    round_kernel<<<(DD * DD / 4 + 255) / 256, 256>>>(Wproj, p_Wpr, DD * DD / 4);
    round_kernel<<<(DD * FF / 4 + 255) / 256, 256>>>(W1, p_W1r, DD * FF / 4);
    round_kernel<<<(FF * DD / 4 + 255) / 256, 256>>>(W2, p_W2r, FF * DD / 4);
    pack_qkv_kernel<<<dim3(NQKV / 256, DD), 256>>>(Wq, Wk, Wv);

    rmsnorm_kernel<<<TT, 256>>>(x, g1, p_xn);
    gemm_kernel<0><<<dim3(NQKV / BN, TT / BM), 128, GEMM_SMEM>>>(
        p_xn, p_Bqkv, p_qkv, nullptr, nullptr, TT, NQKV, DD);
    attn_kernel<<<dim3(TT / 128, HH), 256, ATTN_SMEM>>>();
    gemm_kernel<1><<<dim3(DD / BN, TT / BM), 128, GEMM_SMEM>>>(
        p_attn, p_Wpr, p_x1, x, bproj, TT, DD, DD);
    rmsnorm_kernel<<<TT, 256>>>(p_x1, g2, p_xn2);
    gemm_kernel<2><<<dim3(FF / BN, TT / BM), 128, GEMM_SMEM>>>(
        p_xn2, p_W1r, p_hbuf, nullptr, nullptr, TT, FF, DD);
    gemm_kernel<3><<<dim3(DD / BN, TT / BM), 128, GEMM_SMEM>>>(
        p_hbuf, p_W2r, out, p_x1, nullptr, TT, DD, FF);
}

// round 6
// speedup vs baseline: 5.3269x; 1.7146x over previous
#include <cuda_runtime.h>
#include <cuda_fp16.h>
#include <math.h>

#define TT 2048
#define DD 1024
#define HH 16
#define HS 64
#define FF 4096
#define NQKV 3072

// ---------------- scratch (device globals, no allocation) ----------------
__device__ __half g_xn[TT * DD];          // rmsnorm(x, g1), fp16
__device__ __half g_qkv[TT * NQKV];       // [T][3072]: q | k | v, fp16
__device__ __half g_attn[TT * DD];        // attention out, [T][H*64], fp16
__device__ float  g_x1[TT * DD];          // x + attn proj (fp32)
__device__ __half g_xn2[TT * DD];         // rmsnorm(x1, g2), fp16
__device__ __half g_hbuf[TT * FF];        // silu(xn2 @ W1), fp16
__device__ unsigned g_Bqkv[(DD / 2) * NQKV]; // QKV weights, k-pair packed fp16 [D/2][3072]
__device__ unsigned g_Wpr[(DD / 2) * DD];    // Wproj packed [512][1024]
__device__ unsigned g_W1r[(DD / 2) * FF];    // W1 packed [512][4096]
__device__ unsigned g_W2r[(FF / 2) * DD];    // W2 packed [2048][1024]

// ---------------- helpers ----------------
__device__ __forceinline__ unsigned pack2(float a, float b) {
    __half2 h = __floats2half2_rn(a, b);
    return *(unsigned*)&h;
}

__device__ __forceinline__ void cp16(void* s, const void* g) {
    unsigned saddr = (unsigned)__cvta_generic_to_shared(s);
    asm volatile("cp.async.cg.shared.global [%0], [%1], 16;\n" :: "r"(saddr), "l"(g));
}
__device__ __forceinline__ void cp_commit() { asm volatile("cp.async.commit_group;\n"); }
template <int N> __device__ __forceinline__ void cp_wait() {
    asm volatile("cp.async.wait_group %0;\n" :: "n"(N));
}

__device__ __forceinline__ void mma_f16(float* c, const unsigned* a, const unsigned* b) {
    asm volatile(
        "mma.sync.aligned.m16n8k16.row.col.f32.f16.f16.f32 "
        "{%0,%1,%2,%3}, {%4,%5,%6,%7}, {%8,%9}, {%0,%1,%2,%3};"
        : "+f"(c[0]), "+f"(c[1]), "+f"(c[2]), "+f"(c[3])
        : "r"(a[0]), "r"(a[1]), "r"(a[2]), "r"(a[3]), "r"(b[0]), "r"(b[1]));
}

// ---------------- prep: pack weights fp32[K][N] -> uint32[K/2][N] (k-pairs) ----------------
__global__ __launch_bounds__(256) void pack_w_kernel(const float* __restrict__ in,
                                                     unsigned* __restrict__ out, int N) {
    int n = blockIdx.x * 256 + threadIdx.x;
    int k2 = blockIdx.y;
    out[(size_t)k2 * N + n] = pack2(in[(size_t)(2 * k2) * N + n],
                                    in[(size_t)(2 * k2 + 1) * N + n]);
}

// Wq/Wk/Wv [H][D][HS] -> g_Bqkv[d/2][n], n = which*1024 + h*64 + s
__global__ __launch_bounds__(256) void pack_qkv_kernel(const float* __restrict__ Wq,
                                                       const float* __restrict__ Wk,
                                                       const float* __restrict__ Wv) {
    int n = blockIdx.x * 256 + threadIdx.x;  // 0..3071
    int d2 = blockIdx.y;                     // 0..511
    int which = n >> 10;
    int h = (n >> 6) & 15;
    int s = n & 63;
    const float* W = (which == 0 ? Wq : which == 1 ? Wk : Wv) + (size_t)h * DD * HS;
    g_Bqkv[(size_t)d2 * NQKV + n] = pack2(W[(size_t)(2 * d2) * HS + s],
                                          W[(size_t)(2 * d2 + 1) * HS + s]);
}

// ---------------- rmsnorm (fp32 in -> fp16 out) ----------------
__global__ __launch_bounds__(256) void rmsnorm_kernel(const float* __restrict__ x,
                                                      const float* __restrict__ g,
                                                      __half* __restrict__ out) {
    int row = blockIdx.x;
    const float* xr = x + (size_t)row * DD;
    float ss = 0.f;
    for (int i = threadIdx.x; i < DD; i += 256) { float v = xr[i]; ss += v * v; }
    __shared__ float red[8];
    #pragma unroll
    for (int o = 16; o; o >>= 1) ss += __shfl_xor_sync(0xffffffffu, ss, o);
    if ((threadIdx.x & 31) == 0) red[threadIdx.x >> 5] = ss;
    __syncthreads();
    if (threadIdx.x < 32) {
        float v = (threadIdx.x < 8) ? red[threadIdx.x] : 0.f;
        #pragma unroll
        for (int o = 4; o; o >>= 1) v += __shfl_xor_sync(0xffffffffu, v, o);
        if (threadIdx.x == 0) red[0] = v;
    }
    __syncthreads();
    float scale = rsqrtf(red[0] * (1.0f / DD) + 1e-6f);
    for (int i = threadIdx.x * 2; i < DD; i += 512) {
        __half2 h = __floats2half2_rn(xr[i] * scale * g[i], xr[i + 1] * scale * g[i + 1]);
        *(__half2*)&out[(size_t)row * DD + i] = h;
    }
}

// ---------------- fp16 tensor-core GEMM, 3-stage pipeline ----------------
// BM=128 BN=128 BK=32, 128 threads (4 warps), warp tile 64x64
#define BM 128
#define BN 128
#define BK 32
#define APW 20    // A pitch in uint32 (16 used + 4 pad)
#define BPW 136   // B pitch in uint32 (128 used + 8 pad)
#define STG_AW (BM * APW)
#define STG_BW (BK / 2 * BPW)
#define STG_W (STG_AW + STG_BW)
#define GEMM_SMEM (3 * STG_W * 4)

// MODE 0: C(half) = acc                          (qkv)
// MODE 1: C(float) = acc + aux1[row,col] + aux2[col]  (proj + residual + bias)
// MODE 2: C(half) = silu(acc)                    (ffn1)
// MODE 3: C(float) = acc + aux1[row,col]         (ffn2 + residual)
template <int MODE>
__global__ __launch_bounds__(128) void gemm_kernel(
    const __half* __restrict__ A, const unsigned* __restrict__ B, void* __restrict__ Cv,
    const float* __restrict__ aux1, const float* __restrict__ aux2,
    int M, int N, int K) {
    extern __shared__ unsigned smem[];

    const int tid = threadIdx.x;
    const int bx = blockIdx.x, by = blockIdx.y;
    const int warp = tid >> 5, lane = tid & 31;
    const int wm = warp & 1, wn = warp >> 1;   // warps 2(m) x 2(n)
    const int g = lane >> 2, t4 = lane & 3;

    const char* Ab = (const char*)(A + (size_t)by * BM * K);
    const unsigned* Bb = B + (size_t)bx * BN;

    float acc[4][8][4];
    #pragma unroll
    for (int i = 0; i < 4; i++)
        #pragma unroll
        for (int j = 0; j < 8; j++)
            #pragma unroll
            for (int c = 0; c < 4; c++) acc[i][j][c] = 0.f;

    const int KT = K / BK;

    auto load_stage = [&](int kt, int buf) {
        unsigned* Asb = smem + buf * STG_W;
        unsigned* Bsb = Asb + STG_AW;
        #pragma unroll
        for (int i = 0; i < 4; i++) {            // A: 128 rows x 64B
            int idx = tid + i * 128;
            int m = idx >> 2, c = idx & 3;
            cp16(Asb + m * APW + c * 4, Ab + (size_t)m * K * 2 + kt * 64 + c * 16);
        }
        #pragma unroll
        for (int i = 0; i < 4; i++) {            // B: 16 rows x 512B
            int idx = tid + i * 128;
            int r = idx >> 5, c = idx & 31;
            cp16(Bsb + r * BPW + c * 4, Bb + (size_t)(kt * 16 + r) * N + c * 4);
        }
        cp_commit();
    };

    load_stage(0, 0);
    load_stage(1, 1);

    int buf = 0;
    for (int kt = 0; kt < KT; kt++) {
        if (kt + 1 < KT) cp_wait<1>(); else cp_wait<0>();
        __syncthreads();
        if (kt + 2 < KT) {
            int nb = buf + 2; if (nb >= 3) nb -= 3;
            load_stage(kt + 2, nb);
        }

        const unsigned* As_ = smem + buf * STG_W;
        const unsigned* Bs_ = As_ + STG_AW;
        #pragma unroll
        for (int kc = 0; kc < 2; kc++) {        // 2 x K16 per K-tile
            unsigned a[4][4], b[8][2];
            #pragma unroll
            for (int mi = 0; mi < 4; mi++) {
                int rb = wm * 64 + mi * 16;
                a[mi][0] = As_[(rb + g) * APW + kc * 8 + t4];
                a[mi][1] = As_[(rb + g + 8) * APW + kc * 8 + t4];
                a[mi][2] = As_[(rb + g) * APW + kc * 8 + t4 + 4];
                a[mi][3] = As_[(rb + g + 8) * APW + kc * 8 + t4 + 4];
            }
            #pragma unroll
            for (int ni = 0; ni < 8; ni++) {
                int col = wn * 64 + ni * 8 + g;
                b[ni][0] = Bs_[(kc * 8 + t4) * BPW + col];
                b[ni][1] = Bs_[(kc * 8 + t4 + 4) * BPW + col];
            }
            #pragma unroll
            for (int mi = 0; mi < 4; mi++)
                #pragma unroll
                for (int ni = 0; ni < 8; ni++)
                    mma_f16(acc[mi][ni], a[mi], b[ni]);
        }
        buf++; if (buf >= 3) buf -= 3;
    }

    // epilogue
    #pragma unroll
    for (int mi = 0; mi < 4; mi++)
        #pragma unroll
        for (int r2 = 0; r2 < 2; r2++) {
            int row = by * BM + wm * 64 + mi * 16 + g + r2 * 8;
            #pragma unroll
            for (int ni = 0; ni < 8; ni++) {
                int col = bx * BN + wn * 64 + ni * 8 + t4 * 2;
                float v0 = acc[mi][ni][r2 * 2 + 0];
                float v1 = acc[mi][ni][r2 * 2 + 1];
                size_t oidx = (size_t)row * N + col;
                if (MODE == 0) {
                    *(__half2*)&((__half*)Cv)[oidx] = __floats2half2_rn(v0, v1);
                } else if (MODE == 1) {
                    float* C = (float*)Cv;
                    C[oidx] = v0 + aux1[oidx] + aux2[col];
                    C[oidx + 1] = v1 + aux1[oidx + 1] + aux2[col + 1];
                } else if (MODE == 2) {
                    *(__half2*)&((__half*)Cv)[oidx] =
                        __floats2half2_rn(v0 / (1.0f + __expf(-v0)),
                                          v1 / (1.0f + __expf(-v1)));
                } else {
                    float* C = (float*)Cv;
                    C[oidx] = v0 + aux1[oidx];
                    C[oidx + 1] = v1 + aux1[oidx + 1];
                }
            }
        }
}

// ---------------- fp16 tensor-core causal flash attention ----------------
// Qs/Ps: [128][36] words; Ks: [64][36] words; Vs packed: [32][72] words
#define QPW 36
#define KPW 36
#define VPW 72
#define ATTN_SMEM ((128 * QPW + 64 * KPW + 32 * VPW) * 4)

__global__ __launch_bounds__(256, 2) void attn_kernel() {
    extern __shared__ unsigned as_[];
    unsigned* Qs = as_;                     // Q fp16 pairs, later P
    unsigned* Ks = as_ + 128 * QPW;
    unsigned* Vs = Ks + 64 * KPW;           // V transposed-packed: [kv2][dim]

    const int h = blockIdx.y;
    const int qb = gridDim.x - 1 - blockIdx.x;
    const int q0 = qb * 128;
    const char* Qh = (const char*)(g_qkv + h * HS);
    const char* Kh = (const char*)(g_qkv + DD + h * HS);
    const char* Vh = (const char*)(g_qkv + 2 * DD + h * HS);

    const int tid = threadIdx.x;
    const int warp = tid >> 5, lane = tid & 31;
    const int g = lane >> 2, t4 = lane & 3;
    const int r0 = warp * 16;

    // stage Q tile (128 x 64 fp16 = 128B/row)
    #pragma unroll
    for (int i = 0; i < 4; i++) {
        int idx = tid + i * 256;
        int r = idx >> 3, c = idx & 7;
        cp16(Qs + r * QPW + c * 4, Qh + (size_t)(q0 + r) * NQKV * 2 + c * 16);
    }
    cp_commit(); cp_wait<0>();
    __syncthreads();

    // Q fragments, scale 1/8 folded (exact in fp16)
    const __half2 hscale = __float2half2_rn(0.125f);
    unsigned qa[4][4];
    #pragma unroll
    for (int kc = 0; kc < 4; kc++) {
        unsigned u0 = Qs[(r0 + g) * QPW + kc * 8 + t4];
        unsigned u1 = Qs[(r0 + g + 8) * QPW + kc * 8 + t4];
        unsigned u2 = Qs[(r0 + g) * QPW + kc * 8 + t4 + 4];
        unsigned u3 = Qs[(r0 + g + 8) * QPW + kc * 8 + t4 + 4];
        __half2 h0 = __hmul2(*(__half2*)&u0, hscale);
        __half2 h1 = __hmul2(*(__half2*)&u1, hscale);
        __half2 h2 = __hmul2(*(__half2*)&u2, hscale);
        __half2 h3 = __hmul2(*(__half2*)&u3, hscale);
        qa[kc][0] = *(unsigned*)&h0; qa[kc][1] = *(unsigned*)&h1;
        qa[kc][2] = *(unsigned*)&h2; qa[kc][3] = *(unsigned*)&h3;
    }
    __syncthreads();  // Qs now reusable as P

    float acc[8][4];
    #pragma unroll
    for (int ni = 0; ni < 8; ni++)
        #pragma unroll
        for (int c = 0; c < 4; c++) acc[ni][c] = 0.f;
    float m0 = -1e30f, m1 = -1e30f, l0 = 0.f, l1 = 0.f;
    const int row0 = q0 + r0 + g, row1 = row0 + 8;

    const int nkb = 2 * qb + 2;
    for (int kb = 0; kb < nkb; kb++) {
        const int k0t = kb * 64;
        __syncthreads();  // prev iter done with Ks/Vs
        // K tile via cp.async: 64 rows x 128B
        #pragma unroll
        for (int i = 0; i < 2; i++) {
            int idx = tid + i * 256;
            int j = idx >> 3, c = idx & 7;
            cp16(Ks + j * KPW + c * 4, Kh + (size_t)(k0t + j) * NQKV * 2 + c * 16);
        }
        // V tile: transpose-pack pairs along kv (LDG + prmt + STS)
        #pragma unroll
        for (int i = 0; i < 4; i++) {
            int t = tid + i * 256;             // 1024 tasks: kv2 x dim-pair
            int kv2 = t >> 5, dp = t & 31;
            unsigned u0 = *(const unsigned*)(Vh + (size_t)(k0t + 2 * kv2) * NQKV * 2 + dp * 4);
            unsigned u1 = *(const unsigned*)(Vh + (size_t)(k0t + 2 * kv2 + 1) * NQKV * 2 + dp * 4);
            Vs[kv2 * VPW + 2 * dp]     = __byte_perm(u0, u1, 0x5410);
            Vs[kv2 * VPW + 2 * dp + 1] = __byte_perm(u0, u1, 0x7632);
        }
        cp_commit(); cp_wait<0>();
        __syncthreads();

        // S = (Q/8) K^T : 4 K16 chunks x 8 n-tiles
        float s[8][4];
        #pragma unroll
        for (int ni = 0; ni < 8; ni++)
            #pragma unroll
            for (int c = 0; c < 4; c++) s[ni][c] = 0.f;
        #pragma unroll
        for (int kc = 0; kc < 4; kc++) {
            unsigned b[8][2];
            #pragma unroll
            for (int ni = 0; ni < 8; ni++) {
                b[ni][0] = Ks[(ni * 8 + g) * KPW + kc * 8 + t4];
                b[ni][1] = Ks[(ni * 8 + g) * KPW + kc * 8 + t4 + 4];
            }
            #pragma unroll
            for (int ni = 0; ni < 8; ni++)
                mma_f16(s[ni], qa[kc], b[ni]);
        }

        // causal mask
        if (k0t + 63 > row0) {
            #pragma unroll
            for (int ni = 0; ni < 8; ni++) {
                int col = k0t + ni * 8 + t4 * 2;
                if (col > row0) s[ni][0] = -1e30f;
                if (col + 1 > row0) s[ni][1] = -1e30f;
                if (col > row1) s[ni][2] = -1e30f;
                if (col + 1 > row1) s[ni][3] = -1e30f;
            }
        }

        // online softmax (fp32)
        float tm0 = -1e30f, tm1 = -1e30f;
        #pragma unroll
        for (int ni = 0; ni < 8; ni++) {
            tm0 = fmaxf(tm0, fmaxf(s[ni][0], s[ni][1]));
            tm1 = fmaxf(tm1, fmaxf(s[ni][2], s[ni][3]));
        }
        tm0 = fmaxf(tm0, __shfl_xor_sync(0xffffffffu, tm0, 1));
        tm0 = fmaxf(tm0, __shfl_xor_sync(0xffffffffu, tm0, 2));
        tm1 = fmaxf(tm1, __shfl_xor_sync(0xffffffffu, tm1, 1));
        tm1 = fmaxf(tm1, __shfl_xor_sync(0xffffffffu, tm1, 2));
        float mn0 = fmaxf(m0, tm0), mn1 = fmaxf(m1, tm1);
        float f0 = __expf(m0 - mn0), f1 = __expf(m1 - mn1);
        m0 = mn0; m1 = mn1;
        float sum0 = 0.f, sum1 = 0.f;
        #pragma unroll
        for (int ni = 0; ni < 8; ni++) {
            s[ni][0] = __expf(s[ni][0] - mn0);
            s[ni][1] = __expf(s[ni][1] - mn0);
            s[ni][2] = __expf(s[ni][2] - mn1);
            s[ni][3] = __expf(s[ni][3] - mn1);
            sum0 += s[ni][0] + s[ni][1];
            sum1 += s[ni][2] + s[ni][3];
        }
        sum0 += __shfl_xor_sync(0xffffffffu, sum0, 1);
        sum0 += __shfl_xor_sync(0xffffffffu, sum0, 2);
        sum1 += __shfl_xor_sync(0xffffffffu, sum1, 1);
        sum1 += __shfl_xor_sync(0xffffffffu, sum1, 2);
        l0 = l0 * f0 + sum0;
        l1 = l1 * f1 + sum1;
        #pragma unroll
        for (int ni = 0; ni < 8; ni++) {
            acc[ni][0] *= f0; acc[ni][1] *= f0;
            acc[ni][2] *= f1; acc[ni][3] *= f1;
        }

        // P -> smem fp16 pairs (own warp rows only)
        #pragma unroll
        for (int ni = 0; ni < 8; ni++) {
            Qs[(r0 + g) * QPW + ni * 4 + t4]     = pack2(s[ni][0], s[ni][1]);
            Qs[(r0 + g + 8) * QPW + ni * 4 + t4] = pack2(s[ni][2], s[ni][3]);
        }
        __syncwarp();

        // O += P V : 4 K16 chunks over kv
        #pragma unroll
        for (int kc = 0; kc < 4; kc++) {
            unsigned pa[4];
            pa[0] = Qs[(r0 + g) * QPW + kc * 8 + t4];
            pa[1] = Qs[(r0 + g + 8) * QPW + kc * 8 + t4];
            pa[2] = Qs[(r0 + g) * QPW + kc * 8 + t4 + 4];
            pa[3] = Qs[(r0 + g + 8) * QPW + kc * 8 + t4 + 4];
            unsigned vb[8][2];
            #pragma unroll
            for (int ni = 0; ni < 8; ni++) {
                vb[ni][0] = Vs[(kc * 8 + t4) * VPW + ni * 8 + g];
                vb[ni][1] = Vs[(kc * 8 + t4 + 4) * VPW + ni * 8 + g];
            }
            #pragma unroll
            for (int ni = 0; ni < 8; ni++)
                mma_f16(acc[ni], pa, vb[ni]);
        }
    }

    float inv0 = 1.0f / l0, inv1 = 1.0f / l1;
    #pragma unroll
    for (int ni = 0; ni < 8; ni++) {
        int col = h * HS + ni * 8 + t4 * 2;
        *(__half2*)&g_attn[(size_t)row0 * DD + col] =
            __floats2half2_rn(acc[ni][0] * inv0, acc[ni][1] * inv0);
        *(__half2*)&g_attn[(size_t)row1 * DD + col] =
            __floats2half2_rn(acc[ni][2] * inv1, acc[ni][3] * inv1);
    }
}

// ---------------- launch ----------------
extern "C" void kernel_launch(void* const* d_in, const int* in_sizes, int n_in,
                              void* d_out, int out_size) {
    const float* x     = (const float*)d_in[0];
    const float* Wq    = (const float*)d_in[1];
    const float* Wk    = (const float*)d_in[2];
    const float* Wv    = (const float*)d_in[3];
    const float* Wproj = (const float*)d_in[4];
    const float* bproj = (const float*)d_in[5];
    const float* W1    = (const float*)d_in[6];
    const float* W2    = (const float*)d_in[7];
    const float* g1    = (const float*)d_in[8];
    const float* g2    = (const float*)d_in[9];
    float* out = (float*)d_out;

    __half *p_xn, *p_qkv, *p_attn, *p_xn2, *p_hbuf;
    float *p_x1;
    unsigned *p_Bqkv, *p_Wpr, *p_W1r, *p_W2r;
    cudaGetSymbolAddress((void**)&p_xn,   g_xn);
    cudaGetSymbolAddress((void**)&p_qkv,  g_qkv);
    cudaGetSymbolAddress((void**)&p_attn, g_attn);
    cudaGetSymbolAddress((void**)&p_x1,   g_x1);
    cudaGetSymbolAddress((void**)&p_xn2,  g_xn2);
    cudaGetSymbolAddress((void**)&p_hbuf, g_hbuf);
    cudaGetSymbolAddress((void**)&p_Bqkv, g_Bqkv);
    cudaGetSymbolAddress((void**)&p_Wpr,  g_Wpr);
    cudaGetSymbolAddress((void**)&p_W1r,  g_W1r);
    cudaGetSymbolAddress((void**)&p_W2r,  g_W2r);

    cudaFuncSetAttribute(gemm_kernel<0>, cudaFuncAttributeMaxDynamicSharedMemorySize, GEMM_SMEM);
    cudaFuncSetAttribute(gemm_kernel<1>, cudaFuncAttributeMaxDynamicSharedMemorySize, GEMM_SMEM);
    cudaFuncSetAttribute(gemm_kernel<2>, cudaFuncAttributeMaxDynamicSharedMemorySize, GEMM_SMEM);
    cudaFuncSetAttribute(gemm_kernel<3>, cudaFuncAttributeMaxDynamicSharedMemorySize, GEMM_SMEM);
    cudaFuncSetAttribute(attn_kernel, cudaFuncAttributeMaxDynamicSharedMemorySize, ATTN_SMEM);

    // prep: pack weights to k-pair-interleaved fp16
    pack_w_kernel<<<dim3(DD / 256, DD / 2), 256>>>(Wproj, p_Wpr, DD);
    pack_w_kernel<<<dim3(FF / 256, DD / 2), 256>>>(W1, p_W1r, FF);
    pack_w_kernel<<<dim3(DD / 256, FF / 2), 256>>>(W2, p_W2r, DD);
    pack_qkv_kernel<<<dim3(NQKV / 256, DD / 2), 256>>>(Wq, Wk, Wv);

    rmsnorm_kernel<<<TT, 256>>>(x, g1, p_xn);
    gemm_kernel<0><<<dim3(NQKV / BN, TT / BM), 128, GEMM_SMEM>>>(
        p_xn, p_Bqkv, p_qkv, nullptr, nullptr, TT, NQKV, DD);
    attn_kernel<<<dim3(TT / 128, HH), 256, ATTN_SMEM>>>();
    gemm_kernel<1><<<dim3(DD / BN, TT / BM), 128, GEMM_SMEM>>>(
        p_attn, p_Wpr, p_x1, x, bproj, TT, DD, DD);
    rmsnorm_kernel<<<TT, 256>>>(p_x1, g2, p_xn2);
    gemm_kernel<2><<<dim3(FF / BN, TT / BM), 128, GEMM_SMEM>>>(
        p_xn2, p_W1r, p_hbuf, nullptr, nullptr, TT, FF, DD);
    gemm_kernel<3><<<dim3(DD / BN, TT / BM), 128, GEMM_SMEM>>>(
        p_hbuf, p_W2r, out, p_x1, nullptr, TT, DD, FF);
}

// round 7
// speedup vs baseline: 5.9998x; 1.1263x over previous
#include <cuda_runtime.h>
#include <cuda_fp16.h>
#include <math.h>

#define TT 2048
#define DD 1024
#define HH 16
#define HS 64
#define FF 4096
#define NQKV 3072

// ---------------- scratch (device globals, no allocation) ----------------
__device__ __half g_xn[TT * DD];          // rmsnorm(x, g1), fp16
__device__ __half g_qkv[TT * NQKV];       // [T][3072]: q | k | v, fp16
__device__ __half g_attn[TT * DD];        // attention out, [T][H*64], fp16
__device__ float  g_x1[TT * DD];          // x + attn proj (fp32)
__device__ __half g_xn2[TT * DD];         // rmsnorm(x1, g2), fp16
__device__ __half g_hbuf[TT * FF];        // silu(xn2 @ W1), fp16
__device__ __half g_Bqkv[DD * NQKV];      // QKV weights fp16 [K=1024][N=3072]
__device__ __half g_Wpr[DD * DD];         // Wproj fp16 [K][N]
__device__ __half g_W1r[DD * FF];         // W1 fp16 [1024][4096]
__device__ __half g_W2r[FF * DD];         // W2 fp16 [4096][1024]

// ---------------- helpers ----------------
__device__ __forceinline__ unsigned pack2(float a, float b) {
    __half2 h = __floats2half2_rn(a, b);
    return *(unsigned*)&h;
}
__device__ __forceinline__ void cp16(void* s, const void* g) {
    unsigned saddr = (unsigned)__cvta_generic_to_shared(s);
    asm volatile("cp.async.cg.shared.global [%0], [%1], 16;\n" :: "r"(saddr), "l"(g));
}
__device__ __forceinline__ void cp16s(unsigned saddr, const void* g) {
    asm volatile("cp.async.cg.shared.global [%0], [%1], 16;\n" :: "r"(saddr), "l"(g));
}
__device__ __forceinline__ void cp_commit() { asm volatile("cp.async.commit_group;\n"); }
template <int N> __device__ __forceinline__ void cp_wait() {
    asm volatile("cp.async.wait_group %0;\n" :: "n"(N));
}
__device__ __forceinline__ void mma_f16(float* c, const unsigned* a, const unsigned* b) {
    asm volatile(
        "mma.sync.aligned.m16n8k16.row.col.f32.f16.f16.f32 "
        "{%0,%1,%2,%3}, {%4,%5,%6,%7}, {%8,%9}, {%0,%1,%2,%3};"
        : "+f"(c[0]), "+f"(c[1]), "+f"(c[2]), "+f"(c[3])
        : "r"(a[0]), "r"(a[1]), "r"(a[2]), "r"(a[3]), "r"(b[0]), "r"(b[1]));
}
__device__ __forceinline__ void ldm_x4(unsigned* r, unsigned saddr) {
    asm volatile("ldmatrix.sync.aligned.m8n8.x4.shared.b16 {%0,%1,%2,%3}, [%4];"
                 : "=r"(r[0]), "=r"(r[1]), "=r"(r[2]), "=r"(r[3]) : "r"(saddr));
}
__device__ __forceinline__ void ldm_x4_t(unsigned* r, unsigned saddr) {
    asm volatile("ldmatrix.sync.aligned.m8n8.x4.trans.shared.b16 {%0,%1,%2,%3}, [%4];"
                 : "=r"(r[0]), "=r"(r[1]), "=r"(r[2]), "=r"(r[3]) : "r"(saddr));
}

// ---------------- prep: fp32 -> fp16 cast (layout preserved) ----------------
__global__ __launch_bounds__(256) void cvt_half_kernel(const float* __restrict__ in,
                                                       __half* __restrict__ out, int n8) {
    int i = blockIdx.x * 256 + threadIdx.x;
    if (i >= n8) return;
    float4 v0 = ((const float4*)in)[2 * i];
    float4 v1 = ((const float4*)in)[2 * i + 1];
    uint4 o;
    o.x = pack2(v0.x, v0.y); o.y = pack2(v0.z, v0.w);
    o.z = pack2(v1.x, v1.y); o.w = pack2(v1.z, v1.w);
    ((uint4*)out)[i] = o;
}

// Wq/Wk/Wv [H][D][HS] -> g_Bqkv fp16 [d][n], n = which*1024 + h*64 + s
__global__ __launch_bounds__(256) void pack_qkv_kernel(const float* __restrict__ Wq,
                                                       const float* __restrict__ Wk,
                                                       const float* __restrict__ Wv) {
    int n2 = blockIdx.x * 256 + threadIdx.x;   // 0..1535 (half2 granularity)
    int d = blockIdx.y;
    int n = n2 * 2;
    int which = n >> 10;
    int h = (n >> 6) & 15;
    int s = n & 63;
    const float* W = (which == 0 ? Wq : which == 1 ? Wk : Wv) + (size_t)h * DD * HS;
    float2 v = *(const float2*)&W[(size_t)d * HS + s];
    unsigned p = pack2(v.x, v.y);
    *(unsigned*)&g_Bqkv[(size_t)d * NQKV + n] = p;
}

// ---------------- rmsnorm (fp32 in -> fp16 out) ----------------
__global__ __launch_bounds__(256) void rmsnorm_kernel(const float* __restrict__ x,
                                                      const float* __restrict__ g,
                                                      __half* __restrict__ out) {
    int row = blockIdx.x;
    const float* xr = x + (size_t)row * DD;
    float ss = 0.f;
    for (int i = threadIdx.x; i < DD; i += 256) { float v = xr[i]; ss += v * v; }
    __shared__ float red[8];
    #pragma unroll
    for (int o = 16; o; o >>= 1) ss += __shfl_xor_sync(0xffffffffu, ss, o);
    if ((threadIdx.x & 31) == 0) red[threadIdx.x >> 5] = ss;
    __syncthreads();
    if (threadIdx.x < 32) {
        float v = (threadIdx.x < 8) ? red[threadIdx.x] : 0.f;
        #pragma unroll
        for (int o = 4; o; o >>= 1) v += __shfl_xor_sync(0xffffffffu, v, o);
        if (threadIdx.x == 0) red[0] = v;
    }
    __syncthreads();
    float scale = rsqrtf(red[0] * (1.0f / DD) + 1e-6f);
    for (int i = threadIdx.x * 2; i < DD; i += 512) {
        __half2 h = __floats2half2_rn(xr[i] * scale * g[i], xr[i + 1] * scale * g[i + 1]);
        *(__half2*)&out[(size_t)row * DD + i] = h;
    }
}

// ---------------- fp16 GEMM: ldmatrix + swizzled smem, BK=64, 3-stage ----------------
// BM=128 BN=128, 128 threads (4 warps, 2x2), warp tile 64x64
#define BM 128
#define BN 128
#define BK 64
// A stage: 128 rows x 128B (8 chunks swizzled: chunk c at c ^ (m&7))
// B stage: 64 rows x 256B (16 chunks swizzled: chunk c at c ^ (k&7))
#define STG_BYTES 32768
#define GEMM_SMEM (3 * STG_BYTES)

// MODE 0: C(half)=acc  1: C(f32)=acc+aux1+aux2[col]  2: C(half)=silu(acc)  3: C(f32)=acc+aux1
template <int MODE>
__global__ __launch_bounds__(128) void gemm_kernel(
    const __half* __restrict__ A, const __half* __restrict__ B, void* __restrict__ Cv,
    const float* __restrict__ aux1, const float* __restrict__ aux2,
    int M, int N, int K) {
    extern __shared__ char smem[];
    const unsigned sb = (unsigned)__cvta_generic_to_shared(smem);

    const int tid = threadIdx.x;
    const int bx = blockIdx.x, by = blockIdx.y;
    const int warp = tid >> 5, lane = tid & 31;
    const int wm = warp & 1, wn = warp >> 1;
    const int g = lane >> 2, t4 = lane & 3;

    const char* Ab = (const char*)(A + (size_t)by * BM * K);
    const __half* Bb = B + (size_t)bx * BN;

    // per-thread ldmatrix address components
    const int lrow = (lane & 7) + ((lane >> 3) & 1) * 8;  // 0..15
    const int lhi = lane >> 4;                            // 0/1
    const int lx = lane & 7;                              // swizzle xor

    float acc[4][8][4];
    #pragma unroll
    for (int i = 0; i < 4; i++)
        #pragma unroll
        for (int j = 0; j < 8; j++)
            #pragma unroll
            for (int c = 0; c < 4; c++) acc[i][j][c] = 0.f;

    const int KT = K / BK;

    auto load_stage = [&](int kt, int buf) {
        unsigned abase = sb + buf * STG_BYTES;
        unsigned bbase = abase + 16384;
        #pragma unroll
        for (int i = 0; i < 8; i++) {            // A: 1024 chunks of 16B
            int idx = tid + i * 128;
            int m = idx >> 3, c = idx & 7;
            cp16s(abase + m * 128 + ((c ^ (m & 7)) << 4),
                  Ab + (size_t)m * K * 2 + kt * 128 + c * 16);
        }
        #pragma unroll
        for (int i = 0; i < 8; i++) {            // B: 1024 chunks of 16B
            int idx = tid + i * 128;
            int k = idx >> 4, c = idx & 15;
            cp16s(bbase + k * 256 + ((c ^ (k & 7)) << 4),
                  Bb + (size_t)(kt * 64 + k) * N + c * 8);
        }
        cp_commit();
    };

    load_stage(0, 0);
    load_stage(1, 1);

    int buf = 0;
    for (int kt = 0; kt < KT; kt++) {
        if (kt + 1 < KT) cp_wait<1>(); else cp_wait<0>();
        __syncthreads();
        if (kt + 2 < KT) {
            int nb = buf + 2; if (nb >= 3) nb -= 3;
            load_stage(kt + 2, nb);
        }

        const unsigned abase = sb + buf * STG_BYTES;
        const unsigned bbase = abase + 16384;
        #pragma unroll
        for (int kc = 0; kc < 4; kc++) {         // 4 x K16 per K64 tile
            unsigned a[4][4], b[8][2];
            #pragma unroll
            for (int mi = 0; mi < 4; mi++) {
                int m = wm * 64 + mi * 16 + lrow;
                int chunk = kc * 2 + lhi;
                ldm_x4(a[mi], abase + m * 128 + ((chunk ^ lx) << 4));
            }
            #pragma unroll
            for (int nj = 0; nj < 4; nj++) {
                int k = kc * 16 + lrow;
                int chunk = wn * 8 + nj * 2 + lhi;
                unsigned d[4];
                ldm_x4_t(d, bbase + k * 256 + ((chunk ^ lx) << 4));
                b[2 * nj][0] = d[0]; b[2 * nj][1] = d[1];
                b[2 * nj + 1][0] = d[2]; b[2 * nj + 1][1] = d[3];
            }
            #pragma unroll
            for (int mi = 0; mi < 4; mi++)
                #pragma unroll
                for (int ni = 0; ni < 8; ni++)
                    mma_f16(acc[mi][ni], a[mi], b[ni]);
        }
        buf++; if (buf >= 3) buf -= 3;
    }

    // epilogue
    #pragma unroll
    for (int mi = 0; mi < 4; mi++)
        #pragma unroll
        for (int r2 = 0; r2 < 2; r2++) {
            int row = by * BM + wm * 64 + mi * 16 + g + r2 * 8;
            #pragma unroll
            for (int ni = 0; ni < 8; ni++) {
                int col = bx * BN + wn * 64 + ni * 8 + t4 * 2;
                float v0 = acc[mi][ni][r2 * 2 + 0];
                float v1 = acc[mi][ni][r2 * 2 + 1];
                size_t oidx = (size_t)row * N + col;
                if (MODE == 0) {
                    *(__half2*)&((__half*)Cv)[oidx] = __floats2half2_rn(v0, v1);
                } else if (MODE == 1) {
                    float* C = (float*)Cv;
                    C[oidx] = v0 + aux1[oidx] + aux2[col];
                    C[oidx + 1] = v1 + aux1[oidx + 1] + aux2[col + 1];
                } else if (MODE == 2) {
                    *(__half2*)&((__half*)Cv)[oidx] =
                        __floats2half2_rn(v0 / (1.0f + __expf(-v0)),
                                          v1 / (1.0f + __expf(-v1)));
                } else {
                    float* C = (float*)Cv;
                    C[oidx] = v0 + aux1[oidx];
                    C[oidx + 1] = v1 + aux1[oidx + 1];
                }
            }
        }
}

// ---------------- fp16 tensor-core causal flash attention ----------------
#define QPW 36
#define KPW 36
#define VPW 72
#define ATTN_SMEM ((128 * QPW + 64 * KPW + 32 * VPW) * 4)

__global__ __launch_bounds__(256, 2) void attn_kernel() {
    extern __shared__ unsigned as_[];
    unsigned* Qs = as_;                     // Q fp16 pairs, later P
    unsigned* Ks = as_ + 128 * QPW;
    unsigned* Vs = Ks + 64 * KPW;           // V transposed-packed: [kv2][dim]

    const int h = blockIdx.y;
    const int qb = gridDim.x - 1 - blockIdx.x;
    const int q0 = qb * 128;
    const char* Qh = (const char*)(g_qkv + h * HS);
    const char* Kh = (const char*)(g_qkv + DD + h * HS);
    const char* Vh = (const char*)(g_qkv + 2 * DD + h * HS);

    const int tid = threadIdx.x;
    const int warp = tid >> 5, lane = tid & 31;
    const int g = lane >> 2, t4 = lane & 3;
    const int r0 = warp * 16;

    #pragma unroll
    for (int i = 0; i < 4; i++) {
        int idx = tid + i * 256;
        int r = idx >> 3, c = idx & 7;
        cp16(Qs + r * QPW + c * 4, Qh + (size_t)(q0 + r) * NQKV * 2 + c * 16);
    }
    cp_commit(); cp_wait<0>();
    __syncthreads();

    const __half2 hscale = __float2half2_rn(0.125f);
    unsigned qa[4][4];
    #pragma unroll
    for (int kc = 0; kc < 4; kc++) {
        unsigned u0 = Qs[(r0 + g) * QPW + kc * 8 + t4];
        unsigned u1 = Qs[(r0 + g + 8) * QPW + kc * 8 + t4];
        unsigned u2 = Qs[(r0 + g) * QPW + kc * 8 + t4 + 4];
        unsigned u3 = Qs[(r0 + g + 8) * QPW + kc * 8 + t4 + 4];
        __half2 h0 = __hmul2(*(__half2*)&u0, hscale);
        __half2 h1 = __hmul2(*(__half2*)&u1, hscale);
        __half2 h2 = __hmul2(*(__half2*)&u2, hscale);
        __half2 h3 = __hmul2(*(__half2*)&u3, hscale);
        qa[kc][0] = *(unsigned*)&h0; qa[kc][1] = *(unsigned*)&h1;
        qa[kc][2] = *(unsigned*)&h2; qa[kc][3] = *(unsigned*)&h3;
    }
    __syncthreads();

    float acc[8][4];
    #pragma unroll
    for (int ni = 0; ni < 8; ni++)
        #pragma unroll
        for (int c = 0; c < 4; c++) acc[ni][c] = 0.f;
    float m0 = -1e30f, m1 = -1e30f, l0 = 0.f, l1 = 0.f;
    const int row0 = q0 + r0 + g, row1 = row0 + 8;

    const int nkb = 2 * qb + 2;
    for (int kb = 0; kb < nkb; kb++) {
        const int k0t = kb * 64;
        __syncthreads();
        #pragma unroll
        for (int i = 0; i < 2; i++) {
            int idx = tid + i * 256;
            int j = idx >> 3, c = idx & 7;
            cp16(Ks + j * KPW + c * 4, Kh + (size_t)(k0t + j) * NQKV * 2 + c * 16);
        }
        #pragma unroll
        for (int i = 0; i < 4; i++) {
            int t = tid + i * 256;
            int kv2 = t >> 5, dp = t & 31;
            unsigned u0 = *(const unsigned*)(Vh + (size_t)(k0t + 2 * kv2) * NQKV * 2 + dp * 4);
            unsigned u1 = *(const unsigned*)(Vh + (size_t)(k0t + 2 * kv2 + 1) * NQKV * 2 + dp * 4);
            Vs[kv2 * VPW + 2 * dp]     = __byte_perm(u0, u1, 0x5410);
            Vs[kv2 * VPW + 2 * dp + 1] = __byte_perm(u0, u1, 0x7632);
        }
        cp_commit(); cp_wait<0>();
        __syncthreads();

        float s[8][4];
        #pragma unroll
        for (int ni = 0; ni < 8; ni++)
            #pragma unroll
            for (int c = 0; c < 4; c++) s[ni][c] = 0.f;
        #pragma unroll
        for (int kc = 0; kc < 4; kc++) {
            unsigned b[8][2];
            #pragma unroll
            for (int ni = 0; ni < 8; ni++) {
                b[ni][0] = Ks[(ni * 8 + g) * KPW + kc * 8 + t4];
                b[ni][1] = Ks[(ni * 8 + g) * KPW + kc * 8 + t4 + 4];
            }
            #pragma unroll
            for (int ni = 0; ni < 8; ni++)
                mma_f16(s[ni], qa[kc], b[ni]);
        }

        if (k0t + 63 > row0) {
            #pragma unroll
            for (int ni = 0; ni < 8; ni++) {
                int col = k0t + ni * 8 + t4 * 2;
                if (col > row0) s[ni][0] = -1e30f;
                if (col + 1 > row0) s[ni][1] = -1e30f;
                if (col > row1) s[ni][2] = -1e30f;
                if (col + 1 > row1) s[ni][3] = -1e30f;
            }
        }

        float tm0 = -1e30f, tm1 = -1e30f;
        #pragma unroll
        for (int ni = 0; ni < 8; ni++) {
            tm0 = fmaxf(tm0, fmaxf(s[ni][0], s[ni][1]));
            tm1 = fmaxf(tm1, fmaxf(s[ni][2], s[ni][3]));
        }
        tm0 = fmaxf(tm0, __shfl_xor_sync(0xffffffffu, tm0, 1));
        tm0 = fmaxf(tm0, __shfl_xor_sync(0xffffffffu, tm0, 2));
        tm1 = fmaxf(tm1, __shfl_xor_sync(0xffffffffu, tm1, 1));
        tm1 = fmaxf(tm1, __shfl_xor_sync(0xffffffffu, tm1, 2));
        float mn0 = fmaxf(m0, tm0), mn1 = fmaxf(m1, tm1);
        float f0 = __expf(m0 - mn0), f1 = __expf(m1 - mn1);
        m0 = mn0; m1 = mn1;
        float sum0 = 0.f, sum1 = 0.f;
        #pragma unroll
        for (int ni = 0; ni < 8; ni++) {
            s[ni][0] = __expf(s[ni][0] - mn0);
            s[ni][1] = __expf(s[ni][1] - mn0);
            s[ni][2] = __expf(s[ni][2] - mn1);
            s[ni][3] = __expf(s[ni][3] - mn1);
            sum0 += s[ni][0] + s[ni][1];
            sum1 += s[ni][2] + s[ni][3];
        }
        sum0 += __shfl_xor_sync(0xffffffffu, sum0, 1);
        sum0 += __shfl_xor_sync(0xffffffffu, sum0, 2);
        sum1 += __shfl_xor_sync(0xffffffffu, sum1, 1);
        sum1 += __shfl_xor_sync(0xffffffffu, sum1, 2);
        l0 = l0 * f0 + sum0;
        l1 = l1 * f1 + sum1;
        #pragma unroll
        for (int ni = 0; ni < 8; ni++) {
            acc[ni][0] *= f0; acc[ni][1] *= f0;
            acc[ni][2] *= f1; acc[ni][3] *= f1;
        }

        #pragma unroll
        for (int ni = 0; ni < 8; ni++) {
            Qs[(r0 + g) * QPW + ni * 4 + t4]     = pack2(s[ni][0], s[ni][1]);
            Qs[(r0 + g + 8) * QPW + ni * 4 + t4] = pack2(s[ni][2], s[ni][3]);
        }
        __syncwarp();

        #pragma unroll
        for (int kc = 0; kc < 4; kc++) {
            unsigned pa[4];
            pa[0] = Qs[(r0 + g) * QPW + kc * 8 + t4];
            pa[1] = Qs[(r0 + g + 8) * QPW + kc * 8 + t4];
            pa[2] = Qs[(r0 + g) * QPW + kc * 8 + t4 + 4];
            pa[3] = Qs[(r0 + g + 8) * QPW + kc * 8 + t4 + 4];
            unsigned vb[8][2];
            #pragma unroll
            for (int ni = 0; ni < 8; ni++) {
                vb[ni][0] = Vs[(kc * 8 + t4) * VPW + ni * 8 + g];
                vb[ni][1] = Vs[(kc * 8 + t4 + 4) * VPW + ni * 8 + g];
            }
            #pragma unroll
            for (int ni = 0; ni < 8; ni++)
                mma_f16(acc[ni], pa, vb[ni]);
        }
    }

    float inv0 = 1.0f / l0, inv1 = 1.0f / l1;
    #pragma unroll
    for (int ni = 0; ni < 8; ni++) {
        int col = h * HS + ni * 8 + t4 * 2;
        *(__half2*)&g_attn[(size_t)row0 * DD + col] =
            __floats2half2_rn(acc[ni][0] * inv0, acc[ni][1] * inv0);
        *(__half2*)&g_attn[(size_t)row1 * DD + col] =
            __floats2half2_rn(acc[ni][2] * inv1, acc[ni][3] * inv1);
    }
}

// ---------------- launch ----------------
extern "C" void kernel_launch(void* const* d_in, const int* in_sizes, int n_in,
                              void* d_out, int out_size) {
    const float* x     = (const float*)d_in[0];
    const float* Wq    = (const float*)d_in[1];
    const float* Wk    = (const float*)d_in[2];
    const float* Wv    = (const float*)d_in[3];
    const float* Wproj = (const float*)d_in[4];
    const float* bproj = (const float*)d_in[5];
    const float* W1    = (const float*)d_in[6];
    const float* W2    = (const float*)d_in[7];
    const float* g1    = (const float*)d_in[8];
    const float* g2    = (const float*)d_in[9];
    float* out = (float*)d_out;

    __half *p_xn, *p_qkv, *p_attn, *p_xn2, *p_hbuf, *p_Bqkv, *p_Wpr, *p_W1r, *p_W2r;
    float *p_x1;
    cudaGetSymbolAddress((void**)&p_xn,   g_xn);
    cudaGetSymbolAddress((void**)&p_qkv,  g_qkv);
    cudaGetSymbolAddress((void**)&p_attn, g_attn);
    cudaGetSymbolAddress((void**)&p_x1,   g_x1);
    cudaGetSymbolAddress((void**)&p_xn2,  g_xn2);
    cudaGetSymbolAddress((void**)&p_hbuf, g_hbuf);
    cudaGetSymbolAddress((void**)&p_Bqkv, g_Bqkv);
    cudaGetSymbolAddress((void**)&p_Wpr,  g_Wpr);
    cudaGetSymbolAddress((void**)&p_W1r,  g_W1r);
    cudaGetSymbolAddress((void**)&p_W2r,  g_W2r);

    cudaFuncSetAttribute(gemm_kernel<0>, cudaFuncAttributeMaxDynamicSharedMemorySize, GEMM_SMEM);
    cudaFuncSetAttribute(gemm_kernel<1>, cudaFuncAttributeMaxDynamicSharedMemorySize, GEMM_SMEM);
    cudaFuncSetAttribute(gemm_kernel<2>, cudaFuncAttributeMaxDynamicSharedMemorySize, GEMM_SMEM);
    cudaFuncSetAttribute(gemm_kernel<3>, cudaFuncAttributeMaxDynamicSharedMemorySize, GEMM_SMEM);
    cudaFuncSetAttribute(attn_kernel, cudaFuncAttributeMaxDynamicSharedMemorySize, ATTN_SMEM);

    // prep: cast weights to fp16 (row-major [K][N] preserved)
    cvt_half_kernel<<<DD * DD / 8 / 256, 256>>>(Wproj, p_Wpr, DD * DD / 8);
    cvt_half_kernel<<<DD * FF / 8 / 256, 256>>>(W1, p_W1r, DD * FF / 8);
    cvt_half_kernel<<<FF * DD / 8 / 256, 256>>>(W2, p_W2r, FF * DD / 8);
    pack_qkv_kernel<<<dim3(NQKV / 2 / 256, DD), 256>>>(Wq, Wk, Wv);

    rmsnorm_kernel<<<TT, 256>>>(x, g1, p_xn);
    gemm_kernel<0><<<dim3(NQKV / BN, TT / BM), 128, GEMM_SMEM>>>(
        p_xn, p_Bqkv, p_qkv, nullptr, nullptr, TT, NQKV, DD);
    attn_kernel<<<dim3(TT / 128, HH), 256, ATTN_SMEM>>>();
    gemm_kernel<1><<<dim3(DD / BN, TT / BM), 128, GEMM_SMEM>>>(
        p_attn, p_Wpr, p_x1, x, bproj, TT, DD, DD);
    rmsnorm_kernel<<<TT, 256>>>(p_x1, g2, p_xn2);
    gemm_kernel<2><<<dim3(FF / BN, TT / BM), 128, GEMM_SMEM>>>(
        p_xn2, p_W1r, p_hbuf, nullptr, nullptr, TT, FF, DD);
    gemm_kernel<3><<<dim3(DD / BN, TT / BM), 128, GEMM_SMEM>>>(
        p_hbuf, p_W2r, out, p_x1, nullptr, TT, DD, FF);
}

// round 8
// speedup vs baseline: 6.6402x; 1.1067x over previous
#include <cuda_runtime.h>
#include <cuda_fp16.h>
#include <math.h>

#define TT 2048
#define DD 1024
#define HH 16
#define HS 64
#define FF 4096
#define NQKV 3072

// ---------------- scratch (device globals, no allocation) ----------------
__device__ __half g_xn[TT * DD];          // rmsnorm(x, g1), fp16
__device__ __half g_qkv[TT * NQKV];       // [T][3072]: q | k | v, fp16
__device__ __half g_attn[TT * DD];        // attention out, [T][H*64], fp16
__device__ float  g_x1[TT * DD];          // x + attn proj (fp32)
__device__ __half g_xn2[TT * DD];         // rmsnorm(x1, g2), fp16
__device__ __half g_hbuf[TT * FF];        // silu(xn2 @ W1), fp16
__device__ __half g_Bqkv[DD * NQKV];      // QKV weights fp16 [K=1024][N=3072]
__device__ __half g_Wpr[DD * DD];         // Wproj fp16 [K][N]
__device__ __half g_W1r[DD * FF];         // W1 fp16 [1024][4096]
__device__ __half g_W2r[FF * DD];         // W2 fp16 [4096][1024]

// ---------------- helpers ----------------
__device__ __forceinline__ unsigned pack2(float a, float b) {
    __half2 h = __floats2half2_rn(a, b);
    return *(unsigned*)&h;
}
__device__ __forceinline__ void cp16(void* s, const void* g) {
    unsigned saddr = (unsigned)__cvta_generic_to_shared(s);
    asm volatile("cp.async.cg.shared.global [%0], [%1], 16;\n" :: "r"(saddr), "l"(g));
}
__device__ __forceinline__ void cp16s(unsigned saddr, const void* g) {
    asm volatile("cp.async.cg.shared.global [%0], [%1], 16;\n" :: "r"(saddr), "l"(g));
}
__device__ __forceinline__ void cp_commit() { asm volatile("cp.async.commit_group;\n"); }
template <int N> __device__ __forceinline__ void cp_wait() {
    asm volatile("cp.async.wait_group %0;\n" :: "n"(N));
}
__device__ __forceinline__ void mma_f16(float* c, const unsigned* a, const unsigned* b) {
    asm volatile(
        "mma.sync.aligned.m16n8k16.row.col.f32.f16.f16.f32 "
        "{%0,%1,%2,%3}, {%4,%5,%6,%7}, {%8,%9}, {%0,%1,%2,%3};"
        : "+f"(c[0]), "+f"(c[1]), "+f"(c[2]), "+f"(c[3])
        : "r"(a[0]), "r"(a[1]), "r"(a[2]), "r"(a[3]), "r"(b[0]), "r"(b[1]));
}
__device__ __forceinline__ void ldm_x4(unsigned* r, unsigned saddr) {
    asm volatile("ldmatrix.sync.aligned.m8n8.x4.shared.b16 {%0,%1,%2,%3}, [%4];"
                 : "=r"(r[0]), "=r"(r[1]), "=r"(r[2]), "=r"(r[3]) : "r"(saddr));
}
__device__ __forceinline__ void ldm_x4_t(unsigned* r, unsigned saddr) {
    asm volatile("ldmatrix.sync.aligned.m8n8.x4.trans.shared.b16 {%0,%1,%2,%3}, [%4];"
                 : "=r"(r[0]), "=r"(r[1]), "=r"(r[2]), "=r"(r[3]) : "r"(saddr));
}

// ---------------- prep: fp32 -> fp16 cast (layout preserved) ----------------
__global__ __launch_bounds__(256) void cvt_half_kernel(const float* __restrict__ in,
                                                       __half* __restrict__ out, int n8) {
    int i = blockIdx.x * 256 + threadIdx.x;
    if (i >= n8) return;
    float4 v0 = ((const float4*)in)[2 * i];
    float4 v1 = ((const float4*)in)[2 * i + 1];
    uint4 o;
    o.x = pack2(v0.x, v0.y); o.y = pack2(v0.z, v0.w);
    o.z = pack2(v1.x, v1.y); o.w = pack2(v1.z, v1.w);
    ((uint4*)out)[i] = o;
}

// Wq/Wk/Wv [H][D][HS] -> g_Bqkv fp16 [d][n], n = which*1024 + h*64 + s
__global__ __launch_bounds__(256) void pack_qkv_kernel(const float* __restrict__ Wq,
                                                       const float* __restrict__ Wk,
                                                       const float* __restrict__ Wv) {
    int n2 = blockIdx.x * 256 + threadIdx.x;   // 0..1535 (half2 granularity)
    int d = blockIdx.y;
    int n = n2 * 2;
    int which = n >> 10;
    int h = (n >> 6) & 15;
    int s = n & 63;
    const float* W = (which == 0 ? Wq : which == 1 ? Wk : Wv) + (size_t)h * DD * HS;
    float2 v = *(const float2*)&W[(size_t)d * HS + s];
    *(unsigned*)&g_Bqkv[(size_t)d * NQKV + n] = pack2(v.x, v.y);
}

// ---------------- rmsnorm (fp32 in -> fp16 out) ----------------
__global__ __launch_bounds__(256) void rmsnorm_kernel(const float* __restrict__ x,
                                                      const float* __restrict__ g,
                                                      __half* __restrict__ out) {
    int row = blockIdx.x;
    const float* xr = x + (size_t)row * DD;
    float ss = 0.f;
    for (int i = threadIdx.x; i < DD; i += 256) { float v = xr[i]; ss += v * v; }
    __shared__ float red[8];
    #pragma unroll
    for (int o = 16; o; o >>= 1) ss += __shfl_xor_sync(0xffffffffu, ss, o);
    if ((threadIdx.x & 31) == 0) red[threadIdx.x >> 5] = ss;
    __syncthreads();
    if (threadIdx.x < 32) {
        float v = (threadIdx.x < 8) ? red[threadIdx.x] : 0.f;
        #pragma unroll
        for (int o = 4; o; o >>= 1) v += __shfl_xor_sync(0xffffffffu, v, o);
        if (threadIdx.x == 0) red[0] = v;
    }
    __syncthreads();
    float scale = rsqrtf(red[0] * (1.0f / DD) + 1e-6f);
    for (int i = threadIdx.x * 2; i < DD; i += 512) {
        __half2 h = __floats2half2_rn(xr[i] * scale * g[i], xr[i + 1] * scale * g[i + 1]);
        *(__half2*)&out[(size_t)row * DD + i] = h;
    }
}

// ---------------- fp16 GEMM: ldmatrix + swizzled smem, BK=64, 3-stage ----------------
// BMT = 128 (warp tile 64x64) or 64 (warp tile 32x64); BN=128, 128 threads (2x2 warps)
#define BN 128
#define BK 64
#define STG_BYTES(BMT) ((BMT) * 128 + 16384)
#define GEMM_SMEM(BMT) (3 * STG_BYTES(BMT))

// MODE 0: C(half)=acc  1: C(f32)=acc+aux1+aux2[col]  2: C(half)=silu(acc)  3: C(f32)=acc+aux1
template <int MODE, int BMT>
__global__ __launch_bounds__(128) void gemm_kernel(
    const __half* __restrict__ A, const __half* __restrict__ B, void* __restrict__ Cv,
    const float* __restrict__ aux1, const float* __restrict__ aux2,
    int M, int N, int K) {
    extern __shared__ char smem[];
    const unsigned sb = (unsigned)__cvta_generic_to_shared(smem);
    constexpr int MI = BMT / 32;           // m16 tiles per warp
    constexpr int STG = STG_BYTES(BMT);
    constexpr int ABYTES = BMT * 128;

    const int tid = threadIdx.x;
    const int bx = blockIdx.x, by = blockIdx.y;
    const int warp = tid >> 5, lane = tid & 31;
    const int wm = warp & 1, wn = warp >> 1;
    const int g = lane >> 2, t4 = lane & 3;

    const char* Ab = (const char*)(A + (size_t)by * BMT * K);
    const __half* Bb = B + (size_t)bx * BN;

    const int lrow = (lane & 7) + ((lane >> 3) & 1) * 8;  // 0..15
    const int lhi = lane >> 4;                            // 0/1
    const int lx = lane & 7;                              // swizzle xor

    float acc[MI][8][4];
    #pragma unroll
    for (int i = 0; i < MI; i++)
        #pragma unroll
        for (int j = 0; j < 8; j++)
            #pragma unroll
            for (int c = 0; c < 4; c++) acc[i][j][c] = 0.f;

    const int KT = K / BK;

    auto load_stage = [&](int kt, int buf) {
        unsigned abase = sb + buf * STG;
        unsigned bbase = abase + ABYTES;
        #pragma unroll
        for (int i = 0; i < BMT / 16; i++) {     // A: BMT*8 chunks of 16B
            int idx = tid + i * 128;
            int m = idx >> 3, c = idx & 7;
            cp16s(abase + m * 128 + ((c ^ (m & 7)) << 4),
                  Ab + (size_t)m * K * 2 + kt * 128 + c * 16);
        }
        #pragma unroll
        for (int i = 0; i < 8; i++) {            // B: 1024 chunks of 16B
            int idx = tid + i * 128;
            int k = idx >> 4, c = idx & 15;
            cp16s(bbase + k * 256 + ((c ^ (k & 7)) << 4),
                  Bb + (size_t)(kt * 64 + k) * N + c * 8);
        }
        cp_commit();
    };

    load_stage(0, 0);
    load_stage(1, 1);

    int buf = 0;
    for (int kt = 0; kt < KT; kt++) {
        if (kt + 1 < KT) cp_wait<1>(); else cp_wait<0>();
        __syncthreads();
        if (kt + 2 < KT) {
            int nb = buf + 2; if (nb >= 3) nb -= 3;
            load_stage(kt + 2, nb);
        }

        const unsigned abase = sb + buf * STG;
        const unsigned bbase = abase + ABYTES;
        #pragma unroll
        for (int kc = 0; kc < 4; kc++) {         // 4 x K16 per K64 tile
            unsigned a[MI][4], b[8][2];
            #pragma unroll
            for (int mi = 0; mi < MI; mi++) {
                int m = wm * (BMT / 2) + mi * 16 + lrow;
                int chunk = kc * 2 + lhi;
                ldm_x4(a[mi], abase + m * 128 + ((chunk ^ lx) << 4));
            }
            #pragma unroll
            for (int nj = 0; nj < 4; nj++) {
                int k = kc * 16 + lrow;
                int chunk = wn * 8 + nj * 2 + lhi;
                unsigned d[4];
                ldm_x4_t(d, bbase + k * 256 + ((chunk ^ lx) << 4));
                b[2 * nj][0] = d[0]; b[2 * nj][1] = d[1];
                b[2 * nj + 1][0] = d[2]; b[2 * nj + 1][1] = d[3];
            }
            #pragma unroll
            for (int mi = 0; mi < MI; mi++)
                #pragma unroll
                for (int ni = 0; ni < 8; ni++)
                    mma_f16(acc[mi][ni], a[mi], b[ni]);
        }
        buf++; if (buf >= 3) buf -= 3;
    }

    // epilogue
    #pragma unroll
    for (int mi = 0; mi < MI; mi++)
        #pragma unroll
        for (int r2 = 0; r2 < 2; r2++) {
            int row = by * BMT + wm * (BMT / 2) + mi * 16 + g + r2 * 8;
            #pragma unroll
            for (int ni = 0; ni < 8; ni++) {
                int col = bx * BN + wn * 64 + ni * 8 + t4 * 2;
                float v0 = acc[mi][ni][r2 * 2 + 0];
                float v1 = acc[mi][ni][r2 * 2 + 1];
                size_t oidx = (size_t)row * N + col;
                if (MODE == 0) {
                    *(__half2*)&((__half*)Cv)[oidx] = __floats2half2_rn(v0, v1);
                } else if (MODE == 1) {
                    float* C = (float*)Cv;
                    C[oidx] = v0 + aux1[oidx] + aux2[col];
                    C[oidx + 1] = v1 + aux1[oidx + 1] + aux2[col + 1];
                } else if (MODE == 2) {
                    *(__half2*)&((__half*)Cv)[oidx] =
                        __floats2half2_rn(v0 / (1.0f + __expf(-v0)),
                                          v1 / (1.0f + __expf(-v1)));
                } else {
                    float* C = (float*)Cv;
                    C[oidx] = v0 + aux1[oidx];
                    C[oidx + 1] = v1 + aux1[oidx + 1];
                }
            }
        }
}

// ---------------- fp16 tensor-core causal flash attention, BQ=64 ----------------
// 128 threads (4 warps x 16 rows). Qs/Ps [64][36]w, Ks [64][36]w, Vs [32][72]w
#define QPW 36
#define KPW 36
#define VPW 72
#define ATTN_SMEM ((64 * QPW + 64 * KPW + 32 * VPW) * 4)

__global__ __launch_bounds__(128, 4) void attn_kernel() {
    extern __shared__ unsigned as_[];
    unsigned* Qs = as_;                     // Q fp16 pairs, later P
    unsigned* Ks = as_ + 64 * QPW;
    unsigned* Vs = Ks + 64 * KPW;           // V transposed-packed: [kv2][dim]

    const int h = blockIdx.y;
    const int qb = gridDim.x - 1 - blockIdx.x;
    const int q0 = qb * 64;
    const char* Qh = (const char*)(g_qkv + h * HS);
    const char* Kh = (const char*)(g_qkv + DD + h * HS);
    const char* Vh = (const char*)(g_qkv + 2 * DD + h * HS);

    const int tid = threadIdx.x;
    const int warp = tid >> 5, lane = tid & 31;
    const int g = lane >> 2, t4 = lane & 3;
    const int r0 = warp * 16;

    // stage Q tile (64 x 64 fp16 = 128B/row)
    #pragma unroll
    for (int i = 0; i < 4; i++) {
        int idx = tid + i * 128;
        int r = idx >> 3, c = idx & 7;
        cp16(Qs + r * QPW + c * 4, Qh + (size_t)(q0 + r) * NQKV * 2 + c * 16);
    }
    cp_commit(); cp_wait<0>();
    __syncthreads();

    const __half2 hscale = __float2half2_rn(0.125f);
    unsigned qa[4][4];
    #pragma unroll
    for (int kc = 0; kc < 4; kc++) {
        unsigned u0 = Qs[(r0 + g) * QPW + kc * 8 + t4];
        unsigned u1 = Qs[(r0 + g + 8) * QPW + kc * 8 + t4];
        unsigned u2 = Qs[(r0 + g) * QPW + kc * 8 + t4 + 4];
        unsigned u3 = Qs[(r0 + g + 8) * QPW + kc * 8 + t4 + 4];
        __half2 h0 = __hmul2(*(__half2*)&u0, hscale);
        __half2 h1 = __hmul2(*(__half2*)&u1, hscale);
        __half2 h2 = __hmul2(*(__half2*)&u2, hscale);
        __half2 h3 = __hmul2(*(__half2*)&u3, hscale);
        qa[kc][0] = *(unsigned*)&h0; qa[kc][1] = *(unsigned*)&h1;
        qa[kc][2] = *(unsigned*)&h2; qa[kc][3] = *(unsigned*)&h3;
    }
    __syncthreads();

    float acc[8][4];
    #pragma unroll
    for (int ni = 0; ni < 8; ni++)
        #pragma unroll
        for (int c = 0; c < 4; c++) acc[ni][c] = 0.f;
    float m0 = -1e30f, m1 = -1e30f, l0 = 0.f, l1 = 0.f;
    const int row0 = q0 + r0 + g, row1 = row0 + 8;

    const int nkb = qb + 1;
    for (int kb = 0; kb < nkb; kb++) {
        const int k0t = kb * 64;
        __syncthreads();
        // K tile: 64 rows x 8 chunks = 512 tasks
        #pragma unroll
        for (int i = 0; i < 4; i++) {
            int idx = tid + i * 128;
            int j = idx >> 3, c = idx & 7;
            cp16(Ks + j * KPW + c * 4, Kh + (size_t)(k0t + j) * NQKV * 2 + c * 16);
        }
        // V tile: 32 kv2 x 32 dp = 1024 tasks
        #pragma unroll
        for (int i = 0; i < 8; i++) {
            int t = tid + i * 128;
            int kv2 = t >> 5, dp = t & 31;
            unsigned u0 = *(const unsigned*)(Vh + (size_t)(k0t + 2 * kv2) * NQKV * 2 + dp * 4);
            unsigned u1 = *(const unsigned*)(Vh + (size_t)(k0t + 2 * kv2 + 1) * NQKV * 2 + dp * 4);
            Vs[kv2 * VPW + 2 * dp]     = __byte_perm(u0, u1, 0x5410);
            Vs[kv2 * VPW + 2 * dp + 1] = __byte_perm(u0, u1, 0x7632);
        }
        cp_commit(); cp_wait<0>();
        __syncthreads();

        float s[8][4];
        #pragma unroll
        for (int ni = 0; ni < 8; ni++)
            #pragma unroll
            for (int c = 0; c < 4; c++) s[ni][c] = 0.f;
        #pragma unroll
        for (int kc = 0; kc < 4; kc++) {
            unsigned b[8][2];
            #pragma unroll
            for (int ni = 0; ni < 8; ni++) {
                b[ni][0] = Ks[(ni * 8 + g) * KPW + kc * 8 + t4];
                b[ni][1] = Ks[(ni * 8 + g) * KPW + kc * 8 + t4 + 4];
            }
            #pragma unroll
            for (int ni = 0; ni < 8; ni++)
                mma_f16(s[ni], qa[kc], b[ni]);
        }

        if (k0t + 63 > row0) {
            #pragma unroll
            for (int ni = 0; ni < 8; ni++) {
                int col = k0t + ni * 8 + t4 * 2;
                if (col > row0) s[ni][0] = -1e30f;
                if (col + 1 > row0) s[ni][1] = -1e30f;
                if (col > row1) s[ni][2] = -1e30f;
                if (col + 1 > row1) s[ni][3] = -1e30f;
            }
        }

        float tm0 = -1e30f, tm1 = -1e30f;
        #pragma unroll
        for (int ni = 0; ni < 8; ni++) {
            tm0 = fmaxf(tm0, fmaxf(s[ni][0], s[ni][1]));
            tm1 = fmaxf(tm1, fmaxf(s[ni][2], s[ni][3]));
        }
        tm0 = fmaxf(tm0, __shfl_xor_sync(0xffffffffu, tm0, 1));
        tm0 = fmaxf(tm0, __shfl_xor_sync(0xffffffffu, tm0, 2));
        tm1 = fmaxf(tm1, __shfl_xor_sync(0xffffffffu, tm1, 1));
        tm1 = fmaxf(tm1, __shfl_xor_sync(0xffffffffu, tm1, 2));
        float mn0 = fmaxf(m0, tm0), mn1 = fmaxf(m1, tm1);
        float f0 = __expf(m0 - mn0), f1 = __expf(m1 - mn1);
        m0 = mn0; m1 = mn1;
        float sum0 = 0.f, sum1 = 0.f;
        #pragma unroll
        for (int ni = 0; ni < 8; ni++) {
            s[ni][0] = __expf(s[ni][0] - mn0);
            s[ni][1] = __expf(s[ni][1] - mn0);
            s[ni][2] = __expf(s[ni][2] - mn1);
            s[ni][3] = __expf(s[ni][3] - mn1);
            sum0 += s[ni][0] + s[ni][1];
            sum1 += s[ni][2] + s[ni][3];
        }
        sum0 += __shfl_xor_sync(0xffffffffu, sum0, 1);
        sum0 += __shfl_xor_sync(0xffffffffu, sum0, 2);
        sum1 += __shfl_xor_sync(0xffffffffu, sum1, 1);
        sum1 += __shfl_xor_sync(0xffffffffu, sum1, 2);
        l0 = l0 * f0 + sum0;
        l1 = l1 * f1 + sum1;
        #pragma unroll
        for (int ni = 0; ni < 8; ni++) {
            acc[ni][0] *= f0; acc[ni][1] *= f0;
            acc[ni][2] *= f1; acc[ni][3] *= f1;
        }

        #pragma unroll
        for (int ni = 0; ni < 8; ni++) {
            Qs[(r0 + g) * QPW + ni * 4 + t4]     = pack2(s[ni][0], s[ni][1]);
            Qs[(r0 + g + 8) * QPW + ni * 4 + t4] = pack2(s[ni][2], s[ni][3]);
        }
        __syncwarp();

        #pragma unroll
        for (int kc = 0; kc < 4; kc++) {
            unsigned pa[4];
            pa[0] = Qs[(r0 + g) * QPW + kc * 8 + t4];
            pa[1] = Qs[(r0 + g + 8) * QPW + kc * 8 + t4];
            pa[2] = Qs[(r0 + g) * QPW + kc * 8 + t4 + 4];
            pa[3] = Qs[(r0 + g + 8) * QPW + kc * 8 + t4 + 4];
            unsigned vb[8][2];
            #pragma unroll
            for (int ni = 0; ni < 8; ni++) {
                vb[ni][0] = Vs[(kc * 8 + t4) * VPW + ni * 8 + g];
                vb[ni][1] = Vs[(kc * 8 + t4 + 4) * VPW + ni * 8 + g];
            }
            #pragma unroll
            for (int ni = 0; ni < 8; ni++)
                mma_f16(acc[ni], pa, vb[ni]);
        }
    }

    float inv0 = 1.0f / l0, inv1 = 1.0f / l1;
    #pragma unroll
    for (int ni = 0; ni < 8; ni++) {
        int col = h * HS + ni * 8 + t4 * 2;
        *(__half2*)&g_attn[(size_t)row0 * DD + col] =
            __floats2half2_rn(acc[ni][0] * inv0, acc[ni][1] * inv0);
        *(__half2*)&g_attn[(size_t)row1 * DD + col] =
            __floats2half2_rn(acc[ni][2] * inv1, acc[ni][3] * inv1);
    }
}

// ---------------- launch ----------------
extern "C" void kernel_launch(void* const* d_in, const int* in_sizes, int n_in,
                              void* d_out, int out_size) {
    const float* x     = (const float*)d_in[0];
    const float* Wq    = (const float*)d_in[1];
    const float* Wk    = (const float*)d_in[2];
    const float* Wv    = (const float*)d_in[3];
    const float* Wproj = (const float*)d_in[4];
    const float* bproj = (const float*)d_in[5];
    const float* W1    = (const float*)d_in[6];
    const float* W2    = (const float*)d_in[7];
    const float* g1    = (const float*)d_in[8];
    const float* g2    = (const float*)d_in[9];
    float* out = (float*)d_out;

    __half *p_xn, *p_qkv, *p_attn, *p_xn2, *p_hbuf, *p_Bqkv, *p_Wpr, *p_W1r, *p_W2r;
    float *p_x1;
    cudaGetSymbolAddress((void**)&p_xn,   g_xn);
    cudaGetSymbolAddress((void**)&p_qkv,  g_qkv);
    cudaGetSymbolAddress((void**)&p_attn, g_attn);
    cudaGetSymbolAddress((void**)&p_x1,   g_x1);
    cudaGetSymbolAddress((void**)&p_xn2,  g_xn2);
    cudaGetSymbolAddress((void**)&p_hbuf, g_hbuf);
    cudaGetSymbolAddress((void**)&p_Bqkv, g_Bqkv);
    cudaGetSymbolAddress((void**)&p_Wpr,  g_Wpr);
    cudaGetSymbolAddress((void**)&p_W1r,  g_W1r);
    cudaGetSymbolAddress((void**)&p_W2r,  g_W2r);

    cudaFuncSetAttribute(gemm_kernel<0, 128>, cudaFuncAttributeMaxDynamicSharedMemorySize, GEMM_SMEM(128));
    cudaFuncSetAttribute(gemm_kernel<2, 128>, cudaFuncAttributeMaxDynamicSharedMemorySize, GEMM_SMEM(128));
    cudaFuncSetAttribute(gemm_kernel<1, 64>,  cudaFuncAttributeMaxDynamicSharedMemorySize, GEMM_SMEM(64));
    cudaFuncSetAttribute(gemm_kernel<3, 64>,  cudaFuncAttributeMaxDynamicSharedMemorySize, GEMM_SMEM(64));
    cudaFuncSetAttribute(attn_kernel, cudaFuncAttributeMaxDynamicSharedMemorySize, ATTN_SMEM);

    // prep: cast weights to fp16 (row-major [K][N] preserved)
    cvt_half_kernel<<<DD * DD / 8 / 256, 256>>>(Wproj, p_Wpr, DD * DD / 8);
    cvt_half_kernel<<<DD * FF / 8 / 256, 256>>>(W1, p_W1r, DD * FF / 8);
    cvt_half_kernel<<<FF * DD / 8 / 256, 256>>>(W2, p_W2r, FF * DD / 8);
    pack_qkv_kernel<<<dim3(NQKV / 2 / 256, DD), 256>>>(Wq, Wk, Wv);

    rmsnorm_kernel<<<TT, 256>>>(x, g1, p_xn);
    gemm_kernel<0, 128><<<dim3(NQKV / BN, TT / 128), 128, GEMM_SMEM(128)>>>(
        p_xn, p_Bqkv, p_qkv, nullptr, nullptr, TT, NQKV, DD);
    attn_kernel<<<dim3(TT / 64, HH), 128, ATTN_SMEM>>>();
    gemm_kernel<1, 64><<<dim3(DD / BN, TT / 64), 128, GEMM_SMEM(64)>>>(
        p_attn, p_Wpr, p_x1, x, bproj, TT, DD, DD);
    rmsnorm_kernel<<<TT, 256>>>(p_x1, g2, p_xn2);
    gemm_kernel<2, 128><<<dim3(FF / BN, TT / 128), 128, GEMM_SMEM(128)>>>(
        p_xn2, p_W1r, p_hbuf, nullptr, nullptr, TT, FF, DD);
    gemm_kernel<3, 64><<<dim3(DD / BN, TT / 64), 128, GEMM_SMEM(64)>>>(
        p_hbuf, p_W2r, out, p_x1, nullptr, TT, DD, FF);
}

// round 9
// speedup vs baseline: 6.9896x; 1.0526x over previous
#include <cuda_runtime.h>
#include <cuda_fp16.h>
#include <math.h>

#define TT 2048
#define DD 1024
#define HH 16
#define HS 64
#define FF 4096
#define NQKV 3072

// ---------------- scratch (device globals, no allocation) ----------------
__device__ __half g_xn[TT * DD];          // rmsnorm(x, g1), fp16
__device__ __half g_qkv[TT * NQKV];       // [T][3072]: q | k | v, fp16
__device__ __half g_attn[TT * DD];        // attention out, [T][H*64], fp16
__device__ float  g_x1[TT * DD];          // x + attn proj (fp32)
__device__ __half g_xn2[TT * DD];         // rmsnorm(x1, g2), fp16
__device__ __half g_hbuf[TT * FF];        // silu(xn2 @ W1), fp16
__device__ __half g_Bqkv[DD * NQKV];      // QKV weights fp16 [K=1024][N=3072]
__device__ __half g_Wpr[DD * DD];         // Wproj fp16 [K][N]
__device__ __half g_W1r[DD * FF];         // W1 fp16 [1024][4096]
__device__ __half g_W2r[FF * DD];         // W2 fp16 [4096][1024]

// ---------------- helpers ----------------
__device__ __forceinline__ unsigned pack2(float a, float b) {
    __half2 h = __floats2half2_rn(a, b);
    return *(unsigned*)&h;
}
__device__ __forceinline__ void cvt8(const float* __restrict__ src, __half* __restrict__ dst) {
    float4 v0 = ((const float4*)src)[0];
    float4 v1 = ((const float4*)src)[1];
    uint4 o;
    o.x = pack2(v0.x, v0.y); o.y = pack2(v0.z, v0.w);
    o.z = pack2(v1.x, v1.y); o.w = pack2(v1.z, v1.w);
    *(uint4*)dst = o;
}
__device__ __forceinline__ void cp16(void* s, const void* g) {
    unsigned saddr = (unsigned)__cvta_generic_to_shared(s);
    asm volatile("cp.async.cg.shared.global [%0], [%1], 16;\n" :: "r"(saddr), "l"(g));
}
__device__ __forceinline__ void cp16s(unsigned saddr, const void* g) {
    asm volatile("cp.async.cg.shared.global [%0], [%1], 16;\n" :: "r"(saddr), "l"(g));
}
__device__ __forceinline__ void cp_commit() { asm volatile("cp.async.commit_group;\n"); }
template <int N> __device__ __forceinline__ void cp_wait() {
    asm volatile("cp.async.wait_group %0;\n" :: "n"(N));
}
__device__ __forceinline__ void mma_f16(float* c, const unsigned* a, const unsigned* b) {
    asm volatile(
        "mma.sync.aligned.m16n8k16.row.col.f32.f16.f16.f32 "
        "{%0,%1,%2,%3}, {%4,%5,%6,%7}, {%8,%9}, {%0,%1,%2,%3};"
        : "+f"(c[0]), "+f"(c[1]), "+f"(c[2]), "+f"(c[3])
        : "r"(a[0]), "r"(a[1]), "r"(a[2]), "r"(a[3]), "r"(b[0]), "r"(b[1]));
}
__device__ __forceinline__ void ldm_x4(unsigned* r, unsigned saddr) {
    asm volatile("ldmatrix.sync.aligned.m8n8.x4.shared.b16 {%0,%1,%2,%3}, [%4];"
                 : "=r"(r[0]), "=r"(r[1]), "=r"(r[2]), "=r"(r[3]) : "r"(saddr));
}
__device__ __forceinline__ void ldm_x4_t(unsigned* r, unsigned saddr) {
    asm volatile("ldmatrix.sync.aligned.m8n8.x4.trans.shared.b16 {%0,%1,%2,%3}, [%4];"
                 : "=r"(r[0]), "=r"(r[1]), "=r"(r[2]), "=r"(r[3]) : "r"(saddr));
}

// ---------------- fused prep: all weight conversions in one kernel ----------------
// 8-element tasks: Wproj (131072) | W1 (524288) | W2 (524288) | qkv pack (393216)
#define PREP_T0 131072
#define PREP_T1 (PREP_T0 + 524288)
#define PREP_T2 (PREP_T1 + 524288)
#define PREP_TOTAL (PREP_T2 + 393216)

__global__ __launch_bounds__(256) void prep_kernel(
    const float* __restrict__ Wproj, const float* __restrict__ W1,
    const float* __restrict__ W2, const float* __restrict__ Wq,
    const float* __restrict__ Wk, const float* __restrict__ Wv) {
    int id = blockIdx.x * 256 + threadIdx.x;
    if (id >= PREP_TOTAL) return;
    if (id < PREP_T0) {
        cvt8(Wproj + (size_t)id * 8, g_Wpr + (size_t)id * 8);
    } else if (id < PREP_T1) {
        size_t t = id - PREP_T0;
        cvt8(W1 + t * 8, g_W1r + t * 8);
    } else if (id < PREP_T2) {
        size_t t = id - PREP_T1;
        cvt8(W2 + t * 8, g_W2r + t * 8);
    } else {
        int t = id - PREP_T2;          // 0..393215
        int c = t & 7;                 // 8-chunk within s-dim
        int u = t >> 3;
        int d = u & 1023;
        int wh = u >> 10;              // 0..47
        int which = wh >> 4, h = wh & 15;
        const float* W = (which == 0 ? Wq : which == 1 ? Wk : Wv) +
                         (size_t)h * DD * HS + (size_t)d * HS + c * 8;
        __half* o = g_Bqkv + (size_t)d * NQKV + which * 1024 + h * 64 + c * 8;
        cvt8(W, o);
    }
}

// ---------------- rmsnorm: single-pass, float4 per thread ----------------
__global__ __launch_bounds__(256) void rmsnorm_kernel(const float* __restrict__ x,
                                                      const float* __restrict__ g,
                                                      __half* __restrict__ out) {
    int row = blockIdx.x;
    int i = threadIdx.x;
    float4 v = ((const float4*)(x + (size_t)row * DD))[i];
    float ss = v.x * v.x + v.y * v.y + v.z * v.z + v.w * v.w;
    __shared__ float red[8];
    #pragma unroll
    for (int o = 16; o; o >>= 1) ss += __shfl_xor_sync(0xffffffffu, ss, o);
    if ((i & 31) == 0) red[i >> 5] = ss;
    __syncthreads();
    if (i < 32) {
        float t = (i < 8) ? red[i] : 0.f;
        #pragma unroll
        for (int o = 4; o; o >>= 1) t += __shfl_xor_sync(0xffffffffu, t, o);
        if (i == 0) red[0] = t;
    }
    __syncthreads();
    float scale = rsqrtf(red[0] * (1.0f / DD) + 1e-6f);
    float4 gg = ((const float4*)g)[i];
    uint2 o;
    o.x = pack2(v.x * scale * gg.x, v.y * scale * gg.y);
    o.y = pack2(v.z * scale * gg.z, v.w * scale * gg.w);
    *(uint2*)&out[(size_t)row * DD + i * 4] = o;
}

// ---------------- fp16 GEMM: ldmatrix + swizzled smem, BK=64, 3-stage ----------------
#define BN 128
#define BK 64
#define STG_BYTES(BMT) ((BMT) * 128 + 16384)
#define GEMM_SMEM(BMT) (3 * STG_BYTES(BMT))

// MODE 0: C(half)=acc  1: C(f32)=acc+aux1+aux2[col]  2: C(half)=silu(acc)  3: C(f32)=acc+aux1
template <int MODE, int BMT>
__global__ __launch_bounds__(128) void gemm_kernel(
    const __half* __restrict__ A, const __half* __restrict__ B, void* __restrict__ Cv,
    const float* __restrict__ aux1, const float* __restrict__ aux2,
    int M, int N, int K) {
    extern __shared__ char smem[];
    const unsigned sb = (unsigned)__cvta_generic_to_shared(smem);
    constexpr int MI = BMT / 32;
    constexpr int STG = STG_BYTES(BMT);
    constexpr int ABYTES = BMT * 128;

    const int tid = threadIdx.x;
    const int bx = blockIdx.x, by = blockIdx.y;
    const int warp = tid >> 5, lane = tid & 31;
    const int wm = warp & 1, wn = warp >> 1;
    const int g = lane >> 2, t4 = lane & 3;

    const char* Ab = (const char*)(A + (size_t)by * BMT * K);
    const __half* Bb = B + (size_t)bx * BN;

    const int lrow = (lane & 7) + ((lane >> 3) & 1) * 8;
    const int lhi = lane >> 4;
    const int lx = lane & 7;

    float acc[MI][8][4];
    #pragma unroll
    for (int i = 0; i < MI; i++)
        #pragma unroll
        for (int j = 0; j < 8; j++)
            #pragma unroll
            for (int c = 0; c < 4; c++) acc[i][j][c] = 0.f;

    const int KT = K / BK;

    auto load_stage = [&](int kt, int buf) {
        unsigned abase = sb + buf * STG;
        unsigned bbase = abase + ABYTES;
        #pragma unroll
        for (int i = 0; i < BMT / 16; i++) {
            int idx = tid + i * 128;
            int m = idx >> 3, c = idx & 7;
            cp16s(abase + m * 128 + ((c ^ (m & 7)) << 4),
                  Ab + (size_t)m * K * 2 + kt * 128 + c * 16);
        }
        #pragma unroll
        for (int i = 0; i < 8; i++) {
            int idx = tid + i * 128;
            int k = idx >> 4, c = idx & 15;
            cp16s(bbase + k * 256 + ((c ^ (k & 7)) << 4),
                  Bb + (size_t)(kt * 64 + k) * N + c * 8);
        }
        cp_commit();
    };

    load_stage(0, 0);
    load_stage(1, 1);

    int buf = 0;
    for (int kt = 0; kt < KT; kt++) {
        if (kt + 1 < KT) cp_wait<1>(); else cp_wait<0>();
        __syncthreads();
        if (kt + 2 < KT) {
            int nb = buf + 2; if (nb >= 3) nb -= 3;
            load_stage(kt + 2, nb);
        }

        const unsigned abase = sb + buf * STG;
        const unsigned bbase = abase + ABYTES;
        #pragma unroll
        for (int kc = 0; kc < 4; kc++) {
            unsigned a[MI][4], b[8][2];
            #pragma unroll
            for (int mi = 0; mi < MI; mi++) {
                int m = wm * (BMT / 2) + mi * 16 + lrow;
                int chunk = kc * 2 + lhi;
                ldm_x4(a[mi], abase + m * 128 + ((chunk ^ lx) << 4));
            }
            #pragma unroll
            for (int nj = 0; nj < 4; nj++) {
                int k = kc * 16 + lrow;
                int chunk = wn * 8 + nj * 2 + lhi;
                unsigned d[4];
                ldm_x4_t(d, bbase + k * 256 + ((chunk ^ lx) << 4));
                b[2 * nj][0] = d[0]; b[2 * nj][1] = d[1];
                b[2 * nj + 1][0] = d[2]; b[2 * nj + 1][1] = d[3];
            }
            #pragma unroll
            for (int mi = 0; mi < MI; mi++)
                #pragma unroll
                for (int ni = 0; ni < 8; ni++)
                    mma_f16(acc[mi][ni], a[mi], b[ni]);
        }
        buf++; if (buf >= 3) buf -= 3;
    }

    #pragma unroll
    for (int mi = 0; mi < MI; mi++)
        #pragma unroll
        for (int r2 = 0; r2 < 2; r2++) {
            int row = by * BMT + wm * (BMT / 2) + mi * 16 + g + r2 * 8;
            #pragma unroll
            for (int ni = 0; ni < 8; ni++) {
                int col = bx * BN + wn * 64 + ni * 8 + t4 * 2;
                float v0 = acc[mi][ni][r2 * 2 + 0];
                float v1 = acc[mi][ni][r2 * 2 + 1];
                size_t oidx = (size_t)row * N + col;
                if (MODE == 0) {
                    *(__half2*)&((__half*)Cv)[oidx] = __floats2half2_rn(v0, v1);
                } else if (MODE == 1) {
                    float* C = (float*)Cv;
                    C[oidx] = v0 + aux1[oidx] + aux2[col];
                    C[oidx + 1] = v1 + aux1[oidx + 1] + aux2[col + 1];
                } else if (MODE == 2) {
                    *(__half2*)&((__half*)Cv)[oidx] =
                        __floats2half2_rn(v0 / (1.0f + __expf(-v0)),
                                          v1 / (1.0f + __expf(-v1)));
                } else {
                    float* C = (float*)Cv;
                    C[oidx] = v0 + aux1[oidx];
                    C[oidx + 1] = v1 + aux1[oidx + 1];
                }
            }
        }
}

// ---------------- fp16 tensor-core causal flash attention, BQ=64 ----------------
#define QPW 36
#define KPW 36
#define VPW 72
#define ATTN_SMEM ((64 * QPW + 64 * KPW + 32 * VPW) * 4)

__global__ __launch_bounds__(128, 4) void attn_kernel() {
    extern __shared__ unsigned as_[];
    unsigned* Qs = as_;
    unsigned* Ks = as_ + 64 * QPW;
    unsigned* Vs = Ks + 64 * KPW;

    const int h = blockIdx.y;
    const int qb = gridDim.x - 1 - blockIdx.x;
    const int q0 = qb * 64;
    const char* Qh = (const char*)(g_qkv + h * HS);
    const char* Kh = (const char*)(g_qkv + DD + h * HS);
    const char* Vh = (const char*)(g_qkv + 2 * DD + h * HS);

    const int tid = threadIdx.x;
    const int warp = tid >> 5, lane = tid & 31;
    const int g = lane >> 2, t4 = lane & 3;
    const int r0 = warp * 16;

    #pragma unroll
    for (int i = 0; i < 4; i++) {
        int idx = tid + i * 128;
        int r = idx >> 3, c = idx & 7;
        cp16(Qs + r * QPW + c * 4, Qh + (size_t)(q0 + r) * NQKV * 2 + c * 16);
    }
    cp_commit(); cp_wait<0>();
    __syncthreads();

    const __half2 hscale = __float2half2_rn(0.125f);
    unsigned qa[4][4];
    #pragma unroll
    for (int kc = 0; kc < 4; kc++) {
        unsigned u0 = Qs[(r0 + g) * QPW + kc * 8 + t4];
        unsigned u1 = Qs[(r0 + g + 8) * QPW + kc * 8 + t4];
        unsigned u2 = Qs[(r0 + g) * QPW + kc * 8 + t4 + 4];
        unsigned u3 = Qs[(r0 + g + 8) * QPW + kc * 8 + t4 + 4];
        __half2 h0 = __hmul2(*(__half2*)&u0, hscale);
        __half2 h1 = __hmul2(*(__half2*)&u1, hscale);
        __half2 h2 = __hmul2(*(__half2*)&u2, hscale);
        __half2 h3 = __hmul2(*(__half2*)&u3, hscale);
        qa[kc][0] = *(unsigned*)&h0; qa[kc][1] = *(unsigned*)&h1;
        qa[kc][2] = *(unsigned*)&h2; qa[kc][3] = *(unsigned*)&h3;
    }
    __syncthreads();

    float acc[8][4];
    #pragma unroll
    for (int ni = 0; ni < 8; ni++)
        #pragma unroll
        for (int c = 0; c < 4; c++) acc[ni][c] = 0.f;
    float m0 = -1e30f, m1 = -1e30f, l0 = 0.f, l1 = 0.f;
    const int row0 = q0 + r0 + g, row1 = row0 + 8;

    const int nkb = qb + 1;
    for (int kb = 0; kb < nkb; kb++) {
        const int k0t = kb * 64;
        __syncthreads();
        #pragma unroll
        for (int i = 0; i < 4; i++) {
            int idx = tid + i * 128;
            int j = idx >> 3, c = idx & 7;
            cp16(Ks + j * KPW + c * 4, Kh + (size_t)(k0t + j) * NQKV * 2 + c * 16);
        }
        #pragma unroll
        for (int i = 0; i < 8; i++) {
            int t = tid + i * 128;
            int kv2 = t >> 5, dp = t & 31;
            unsigned u0 = *(const unsigned*)(Vh + (size_t)(k0t + 2 * kv2) * NQKV * 2 + dp * 4);
            unsigned u1 = *(const unsigned*)(Vh + (size_t)(k0t + 2 * kv2 + 1) * NQKV * 2 + dp * 4);
            Vs[kv2 * VPW + 2 * dp]     = __byte_perm(u0, u1, 0x5410);
            Vs[kv2 * VPW + 2 * dp + 1] = __byte_perm(u0, u1, 0x7632);
        }
        cp_commit(); cp_wait<0>();
        __syncthreads();

        float s[8][4];
        #pragma unroll
        for (int ni = 0; ni < 8; ni++)
            #pragma unroll
            for (int c = 0; c < 4; c++) s[ni][c] = 0.f;
        #pragma unroll
        for (int kc = 0; kc < 4; kc++) {
            unsigned b[8][2];
            #pragma unroll
            for (int ni = 0; ni < 8; ni++) {
                b[ni][0] = Ks[(ni * 8 + g) * KPW + kc * 8 + t4];
                b[ni][1] = Ks[(ni * 8 + g) * KPW + kc * 8 + t4 + 4];
            }
            #pragma unroll
            for (int ni = 0; ni < 8; ni++)
                mma_f16(s[ni], qa[kc], b[ni]);
        }

        if (k0t + 63 > row0) {
            #pragma unroll
            for (int ni = 0; ni < 8; ni++) {
                int col = k0t + ni * 8 + t4 * 2;
                if (col > row0) s[ni][0] = -1e30f;
                if (col + 1 > row0) s[ni][1] = -1e30f;
                if (col > row1) s[ni][2] = -1e30f;
                if (col + 1 > row1) s[ni][3] = -1e30f;
            }
        }

        float tm0 = -1e30f, tm1 = -1e30f;
        #pragma unroll
        for (int ni = 0; ni < 8; ni++) {
            tm0 = fmaxf(tm0, fmaxf(s[ni][0], s[ni][1]));
            tm1 = fmaxf(tm1, fmaxf(s[ni][2], s[ni][3]));
        }
        tm0 = fmaxf(tm0, __shfl_xor_sync(0xffffffffu, tm0, 1));
        tm0 = fmaxf(tm0, __shfl_xor_sync(0xffffffffu, tm0, 2));
        tm1 = fmaxf(tm1, __shfl_xor_sync(0xffffffffu, tm1, 1));
        tm1 = fmaxf(tm1, __shfl_xor_sync(0xffffffffu, tm1, 2));
        float mn0 = fmaxf(m0, tm0), mn1 = fmaxf(m1, tm1);
        float f0 = __expf(m0 - mn0), f1 = __expf(m1 - mn1);
        m0 = mn0; m1 = mn1;
        float sum0 = 0.f, sum1 = 0.f;
        #pragma unroll
        for (int ni = 0; ni < 8; ni++) {
            s[ni][0] = __expf(s[ni][0] - mn0);
            s[ni][1] = __expf(s[ni][1] - mn0);
            s[ni][2] = __expf(s[ni][2] - mn1);
            s[ni][3] = __expf(s[ni][3] - mn1);
            sum0 += s[ni][0] + s[ni][1];
            sum1 += s[ni][2] + s[ni][3];
        }
        sum0 += __shfl_xor_sync(0xffffffffu, sum0, 1);
        sum0 += __shfl_xor_sync(0xffffffffu, sum0, 2);
        sum1 += __shfl_xor_sync(0xffffffffu, sum1, 1);
        sum1 += __shfl_xor_sync(0xffffffffu, sum1, 2);
        l0 = l0 * f0 + sum0;
        l1 = l1 * f1 + sum1;
        #pragma unroll
        for (int ni = 0; ni < 8; ni++) {
            acc[ni][0] *= f0; acc[ni][1] *= f0;
            acc[ni][2] *= f1; acc[ni][3] *= f1;
        }

        #pragma unroll
        for (int ni = 0; ni < 8; ni++) {
            Qs[(r0 + g) * QPW + ni * 4 + t4]     = pack2(s[ni][0], s[ni][1]);
            Qs[(r0 + g + 8) * QPW + ni * 4 + t4] = pack2(s[ni][2], s[ni][3]);
        }
        __syncwarp();

        #pragma unroll
        for (int kc = 0; kc < 4; kc++) {
            unsigned pa[4];
            pa[0] = Qs[(r0 + g) * QPW + kc * 8 + t4];
            pa[1] = Qs[(r0 + g + 8) * QPW + kc * 8 + t4];
            pa[2] = Qs[(r0 + g) * QPW + kc * 8 + t4 + 4];
            pa[3] = Qs[(r0 + g + 8) * QPW + kc * 8 + t4 + 4];
            unsigned vb[8][2];
            #pragma unroll
            for (int ni = 0; ni < 8; ni++) {
                vb[ni][0] = Vs[(kc * 8 + t4) * VPW + ni * 8 + g];
                vb[ni][1] = Vs[(kc * 8 + t4 + 4) * VPW + ni * 8 + g];
            }
            #pragma unroll
            for (int ni = 0; ni < 8; ni++)
                mma_f16(acc[ni], pa, vb[ni]);
        }
    }

    float inv0 = 1.0f / l0, inv1 = 1.0f / l1;
    #pragma unroll
    for (int ni = 0; ni < 8; ni++) {
        int col = h * HS + ni * 8 + t4 * 2;
        *(__half2*)&g_attn[(size_t)row0 * DD + col] =
            __floats2half2_rn(acc[ni][0] * inv0, acc[ni][1] * inv0);
        *(__half2*)&g_attn[(size_t)row1 * DD + col] =
            __floats2half2_rn(acc[ni][2] * inv1, acc[ni][3] * inv1);
    }
}

// ---------------- launch ----------------
extern "C" void kernel_launch(void* const* d_in, const int* in_sizes, int n_in,
                              void* d_out, int out_size) {
    const float* x     = (const float*)d_in[0];
    const float* Wq    = (const float*)d_in[1];
    const float* Wk    = (const float*)d_in[2];
    const float* Wv    = (const float*)d_in[3];
    const float* Wproj = (const float*)d_in[4];
    const float* bproj = (const float*)d_in[5];
    const float* W1    = (const float*)d_in[6];
    const float* W2    = (const float*)d_in[7];
    const float* g1    = (const float*)d_in[8];
    const float* g2    = (const float*)d_in[9];
    float* out = (float*)d_out;

    __half *p_xn, *p_qkv, *p_attn, *p_xn2, *p_hbuf, *p_Bqkv, *p_Wpr, *p_W1r, *p_W2r;
    float *p_x1;
    cudaGetSymbolAddress((void**)&p_xn,   g_xn);
    cudaGetSymbolAddress((void**)&p_qkv,  g_qkv);
    cudaGetSymbolAddress((void**)&p_attn, g_attn);
    cudaGetSymbolAddress((void**)&p_x1,   g_x1);
    cudaGetSymbolAddress((void**)&p_xn2,  g_xn2);
    cudaGetSymbolAddress((void**)&p_hbuf, g_hbuf);
    cudaGetSymbolAddress((void**)&p_Bqkv, g_Bqkv);
    cudaGetSymbolAddress((void**)&p_Wpr,  g_Wpr);
    cudaGetSymbolAddress((void**)&p_W1r,  g_W1r);
    cudaGetSymbolAddress((void**)&p_W2r,  g_W2r);

    cudaFuncSetAttribute(gemm_kernel<0, 128>, cudaFuncAttributeMaxDynamicSharedMemorySize, GEMM_SMEM(128));
    cudaFuncSetAttribute(gemm_kernel<2, 128>, cudaFuncAttributeMaxDynamicSharedMemorySize, GEMM_SMEM(128));
    cudaFuncSetAttribute(gemm_kernel<1, 64>,  cudaFuncAttributeMaxDynamicSharedMemorySize, GEMM_SMEM(64));
    cudaFuncSetAttribute(gemm_kernel<3, 64>,  cudaFuncAttributeMaxDynamicSharedMemorySize, GEMM_SMEM(64));
    cudaFuncSetAttribute(attn_kernel, cudaFuncAttributeMaxDynamicSharedMemorySize, ATTN_SMEM);

    prep_kernel<<<(PREP_TOTAL + 255) / 256, 256>>>(Wproj, W1, W2, Wq, Wk, Wv);
    rmsnorm_kernel<<<TT, 256>>>(x, g1, p_xn);
    gemm_kernel<0, 128><<<dim3(NQKV / BN, TT / 128), 128, GEMM_SMEM(128)>>>(
        p_xn, p_Bqkv, p_qkv, nullptr, nullptr, TT, NQKV, DD);
    attn_kernel<<<dim3(TT / 64, HH), 128, ATTN_SMEM>>>();
    gemm_kernel<1, 64><<<dim3(DD / BN, TT / 64), 128, GEMM_SMEM(64)>>>(
        p_attn, p_Wpr, p_x1, x, bproj, TT, DD, DD);
    rmsnorm_kernel<<<TT, 256>>>(p_x1, g2, p_xn2);
    gemm_kernel<2, 128><<<dim3(FF / BN, TT / 128), 128, GEMM_SMEM(128)>>>(
        p_xn2, p_W1r, p_hbuf, nullptr, nullptr, TT, FF, DD);
    gemm_kernel<3, 64><<<dim3(DD / BN, TT / 64), 128, GEMM_SMEM(64)>>>(
        p_hbuf, p_W2r, out, p_x1, nullptr, TT, DD, FF);
}

// round 10
// speedup vs baseline: 7.5638x; 1.0822x over previous
#include <cuda_runtime.h>
#include <cuda_fp16.h>
#include <math.h>

#define TT 2048
#define DD 1024
#define HH 16
#define HS 64
#define FF 4096
#define NQKV 3072

// ---------------- scratch (device globals, no allocation) ----------------
__device__ __half g_xn[TT * DD];          // rmsnorm(x, g1), fp16
__device__ __half g_qkv[TT * NQKV];       // [T][3072]: q | k | v, fp16
__device__ __half g_attn[TT * DD];        // attention out, [T][H*64], fp16
__device__ float  g_x1[TT * DD];          // x + attn proj (fp32)
__device__ __half g_xn2[TT * DD];         // rmsnorm(x1, g2), fp16
__device__ __half g_hbuf[TT * FF];        // silu(xn2 @ W1), fp16
__device__ __half g_Bqkv[DD * NQKV];      // QKV weights fp16 [K=1024][N=3072]
__device__ __half g_Wpr[DD * DD];         // Wproj fp16 [K][N]
__device__ __half g_W1r[DD * FF];         // W1 fp16 [1024][4096]
__device__ __half g_W2r[FF * DD];         // W2 fp16 [4096][1024]

// ---------------- helpers ----------------
__device__ __forceinline__ unsigned pack2(float a, float b) {
    __half2 h = __floats2half2_rn(a, b);
    return *(unsigned*)&h;
}
__device__ __forceinline__ void cvt8(const float* __restrict__ src, __half* __restrict__ dst) {
    float4 v0 = ((const float4*)src)[0];
    float4 v1 = ((const float4*)src)[1];
    uint4 o;
    o.x = pack2(v0.x, v0.y); o.y = pack2(v0.z, v0.w);
    o.z = pack2(v1.x, v1.y); o.w = pack2(v1.z, v1.w);
    *(uint4*)dst = o;
}
__device__ __forceinline__ void cp16s(unsigned saddr, const void* g) {
    asm volatile("cp.async.cg.shared.global [%0], [%1], 16;\n" :: "r"(saddr), "l"(g));
}
__device__ __forceinline__ void cp_commit() { asm volatile("cp.async.commit_group;\n"); }
template <int N> __device__ __forceinline__ void cp_wait() {
    asm volatile("cp.async.wait_group %0;\n" :: "n"(N));
}
__device__ __forceinline__ void mma_f16(float* c, const unsigned* a, const unsigned* b) {
    asm volatile(
        "mma.sync.aligned.m16n8k16.row.col.f32.f16.f16.f32 "
        "{%0,%1,%2,%3}, {%4,%5,%6,%7}, {%8,%9}, {%0,%1,%2,%3};"
        : "+f"(c[0]), "+f"(c[1]), "+f"(c[2]), "+f"(c[3])
        : "r"(a[0]), "r"(a[1]), "r"(a[2]), "r"(a[3]), "r"(b[0]), "r"(b[1]));
}
__device__ __forceinline__ void ldm_x4(unsigned* r, unsigned saddr) {
    asm volatile("ldmatrix.sync.aligned.m8n8.x4.shared.b16 {%0,%1,%2,%3}, [%4];"
                 : "=r"(r[0]), "=r"(r[1]), "=r"(r[2]), "=r"(r[3]) : "r"(saddr));
}
__device__ __forceinline__ void ldm_x4_t(unsigned* r, unsigned saddr) {
    asm volatile("ldmatrix.sync.aligned.m8n8.x4.trans.shared.b16 {%0,%1,%2,%3}, [%4];"
                 : "=r"(r[0]), "=r"(r[1]), "=r"(r[2]), "=r"(r[3]) : "r"(saddr));
}

// ---------------- fused prep: all weight conversions in one kernel ----------------
#define PREP_T0 131072
#define PREP_T1 (PREP_T0 + 524288)
#define PREP_T2 (PREP_T1 + 524288)
#define PREP_TOTAL (PREP_T2 + 393216)

__global__ __launch_bounds__(256) void prep_kernel(
    const float* __restrict__ Wproj, const float* __restrict__ W1,
    const float* __restrict__ W2, const float* __restrict__ Wq,
    const float* __restrict__ Wk, const float* __restrict__ Wv) {
    int id = blockIdx.x * 256 + threadIdx.x;
    if (id >= PREP_TOTAL) return;
    if (id < PREP_T0) {
        cvt8(Wproj + (size_t)id * 8, g_Wpr + (size_t)id * 8);
    } else if (id < PREP_T1) {
        size_t t = id - PREP_T0;
        cvt8(W1 + t * 8, g_W1r + t * 8);
    } else if (id < PREP_T2) {
        size_t t = id - PREP_T1;
        cvt8(W2 + t * 8, g_W2r + t * 8);
    } else {
        int t = id - PREP_T2;
        int c = t & 7;
        int u = t >> 3;
        int d = u & 1023;
        int wh = u >> 10;
        int which = wh >> 4, h = wh & 15;
        const float* W = (which == 0 ? Wq : which == 1 ? Wk : Wv) +
                         (size_t)h * DD * HS + (size_t)d * HS + c * 8;
        __half* o = g_Bqkv + (size_t)d * NQKV + which * 1024 + h * 64 + c * 8;
        cvt8(W, o);
    }
}

// ---------------- rmsnorm: single-pass, float4 per thread ----------------
__global__ __launch_bounds__(256) void rmsnorm_kernel(const float* __restrict__ x,
                                                      const float* __restrict__ g,
                                                      __half* __restrict__ out) {
    int row = blockIdx.x;
    int i = threadIdx.x;
    float4 v = ((const float4*)(x + (size_t)row * DD))[i];
    float ss = v.x * v.x + v.y * v.y + v.z * v.z + v.w * v.w;
    __shared__ float red[8];
    #pragma unroll
    for (int o = 16; o; o >>= 1) ss += __shfl_xor_sync(0xffffffffu, ss, o);
    if ((i & 31) == 0) red[i >> 5] = ss;
    __syncthreads();
    if (i < 32) {
        float t = (i < 8) ? red[i] : 0.f;
        #pragma unroll
        for (int o = 4; o; o >>= 1) t += __shfl_xor_sync(0xffffffffu, t, o);
        if (i == 0) red[0] = t;
    }
    __syncthreads();
    float scale = rsqrtf(red[0] * (1.0f / DD) + 1e-6f);
    float4 gg = ((const float4*)g)[i];
    uint2 o;
    o.x = pack2(v.x * scale * gg.x, v.y * scale * gg.y);
    o.y = pack2(v.z * scale * gg.z, v.w * scale * gg.w);
    *(uint2*)&out[(size_t)row * DD + i * 4] = o;
}

// ---------------- fp16 GEMM: ldmatrix + swizzled smem, BK=64, 3-stage ----------------
#define BN 128
#define BK 64
#define STG_BYTES(BMT) ((BMT) * 128 + 16384)
#define GEMM_SMEM(BMT) (3 * STG_BYTES(BMT))

template <int MODE, int BMT>
__global__ __launch_bounds__(128) void gemm_kernel(
    const __half* __restrict__ A, const __half* __restrict__ B, void* __restrict__ Cv,
    const float* __restrict__ aux1, const float* __restrict__ aux2,
    int M, int N, int K) {
    extern __shared__ char smem[];
    const unsigned sb = (unsigned)__cvta_generic_to_shared(smem);
    constexpr int MI = BMT / 32;
    constexpr int STG = STG_BYTES(BMT);
    constexpr int ABYTES = BMT * 128;

    const int tid = threadIdx.x;
    const int bx = blockIdx.x, by = blockIdx.y;
    const int warp = tid >> 5, lane = tid & 31;
    const int wm = warp & 1, wn = warp >> 1;
    const int g = lane >> 2, t4 = lane & 3;

    const char* Ab = (const char*)(A + (size_t)by * BMT * K);
    const __half* Bb = B + (size_t)bx * BN;

    const int lrow = (lane & 7) + ((lane >> 3) & 1) * 8;
    const int lhi = lane >> 4;
    const int lx = lane & 7;

    float acc[MI][8][4];
    #pragma unroll
    for (int i = 0; i < MI; i++)
        #pragma unroll
        for (int j = 0; j < 8; j++)
            #pragma unroll
            for (int c = 0; c < 4; c++) acc[i][j][c] = 0.f;

    const int KT = K / BK;

    auto load_stage = [&](int kt, int buf) {
        unsigned abase = sb + buf * STG;
        unsigned bbase = abase + ABYTES;
        #pragma unroll
        for (int i = 0; i < BMT / 16; i++) {
            int idx = tid + i * 128;
            int m = idx >> 3, c = idx & 7;
            cp16s(abase + m * 128 + ((c ^ (m & 7)) << 4),
                  Ab + (size_t)m * K * 2 + kt * 128 + c * 16);
        }
        #pragma unroll
        for (int i = 0; i < 8; i++) {
            int idx = tid + i * 128;
            int k = idx >> 4, c = idx & 15;
            cp16s(bbase + k * 256 + ((c ^ (k & 7)) << 4),
                  Bb + (size_t)(kt * 64 + k) * N + c * 8);
        }
        cp_commit();
    };

    load_stage(0, 0);
    load_stage(1, 1);

    int buf = 0;
    for (int kt = 0; kt < KT; kt++) {
        if (kt + 1 < KT) cp_wait<1>(); else cp_wait<0>();
        __syncthreads();
        if (kt + 2 < KT) {
            int nb = buf + 2; if (nb >= 3) nb -= 3;
            load_stage(kt + 2, nb);
        }

        const unsigned abase = sb + buf * STG;
        const unsigned bbase = abase + ABYTES;
        #pragma unroll
        for (int kc = 0; kc < 4; kc++) {
            unsigned a[MI][4], b[8][2];
            #pragma unroll
            for (int mi = 0; mi < MI; mi++) {
                int m = wm * (BMT / 2) + mi * 16 + lrow;
                int chunk = kc * 2 + lhi;
                ldm_x4(a[mi], abase + m * 128 + ((chunk ^ lx) << 4));
            }
            #pragma unroll
            for (int nj = 0; nj < 4; nj++) {
                int k = kc * 16 + lrow;
                int chunk = wn * 8 + nj * 2 + lhi;
                unsigned d[4];
                ldm_x4_t(d, bbase + k * 256 + ((chunk ^ lx) << 4));
                b[2 * nj][0] = d[0]; b[2 * nj][1] = d[1];
                b[2 * nj + 1][0] = d[2]; b[2 * nj + 1][1] = d[3];
            }
            #pragma unroll
            for (int mi = 0; mi < MI; mi++)
                #pragma unroll
                for (int ni = 0; ni < 8; ni++)
                    mma_f16(acc[mi][ni], a[mi], b[ni]);
        }
        buf++; if (buf >= 3) buf -= 3;
    }

    #pragma unroll
    for (int mi = 0; mi < MI; mi++)
        #pragma unroll
        for (int r2 = 0; r2 < 2; r2++) {
            int row = by * BMT + wm * (BMT / 2) + mi * 16 + g + r2 * 8;
            #pragma unroll
            for (int ni = 0; ni < 8; ni++) {
                int col = bx * BN + wn * 64 + ni * 8 + t4 * 2;
                float v0 = acc[mi][ni][r2 * 2 + 0];
                float v1 = acc[mi][ni][r2 * 2 + 1];
                size_t oidx = (size_t)row * N + col;
                if (MODE == 0) {
                    *(__half2*)&((__half*)Cv)[oidx] = __floats2half2_rn(v0, v1);
                } else if (MODE == 1) {
                    float* C = (float*)Cv;
                    C[oidx] = v0 + aux1[oidx] + aux2[col];
                    C[oidx + 1] = v1 + aux1[oidx + 1] + aux2[col + 1];
                } else if (MODE == 2) {
                    *(__half2*)&((__half*)Cv)[oidx] =
                        __floats2half2_rn(v0 / (1.0f + __expf(-v0)),
                                          v1 / (1.0f + __expf(-v1)));
                } else {
                    float* C = (float*)Cv;
                    C[oidx] = v0 + aux1[oidx];
                    C[oidx + 1] = v1 + aux1[oidx + 1];
                }
            }
        }
}

// ---------------- fp16 flash attention v2: ldmatrix K/V, register P, 2-buf pipeline ----
// BQ=64, 128 threads (4 warps x 16 rows).
// smem: Q 64x128B | K[2] 64x128B | V[2] 64x128B  = 40 KB, all xor-swizzled
#define AT_QOFF 0
#define AT_KOFF 8192
#define AT_VOFF 24576
#define ATTN_SMEM 40960

__global__ __launch_bounds__(128, 4) void attn_kernel() {
    extern __shared__ char asmem[];
    const unsigned sb = (unsigned)__cvta_generic_to_shared(asmem);

    const int h = blockIdx.y;
    const int qb = gridDim.x - 1 - blockIdx.x;
    const int q0 = qb * 64;
    const char* Qh = (const char*)(g_qkv + h * HS);
    const char* Kh = (const char*)(g_qkv + DD + h * HS);
    const char* Vh = (const char*)(g_qkv + 2 * DD + h * HS);

    const int tid = threadIdx.x;
    const int warp = tid >> 5, lane = tid & 31;
    const int g = lane >> 2, t4 = lane & 3;
    const int r0 = warp * 16;

    // ldmatrix per-thread address components
    const int lrow = (lane & 7) + ((lane >> 3) & 1) * 8;  // A/V(trans) row pattern
    const int lhi = lane >> 4;
    const int nrow = (lane & 7) + (lane >> 4) * 8;        // K(non-trans B) row pattern
    const int nhi = (lane >> 3) & 1;

    // stage Q tile (64 rows x 8 chunks, swizzled)
    #pragma unroll
    for (int i = 0; i < 4; i++) {
        int idx = tid + i * 128;
        int r = idx >> 3, c = idx & 7;
        cp16s(sb + AT_QOFF + r * 128 + ((c ^ (r & 7)) << 4),
              Qh + (size_t)(q0 + r) * NQKV * 2 + c * 16);
    }
    cp_commit(); cp_wait<0>();
    __syncthreads();

    // Q a-fragments, scale 1/8 folded (exact in fp16)
    const __half2 hscale = __float2half2_rn(0.125f);
    unsigned qa[4][4];
    #pragma unroll
    for (int kc = 0; kc < 4; kc++) {
        int m = r0 + lrow;
        int chunk = kc * 2 + lhi;
        ldm_x4(qa[kc], sb + AT_QOFF + m * 128 + ((chunk ^ (m & 7)) << 4));
        #pragma unroll
        for (int j = 0; j < 4; j++) {
            __half2 hv = __hmul2(*(__half2*)&qa[kc][j], hscale);
            qa[kc][j] = *(unsigned*)&hv;
        }
    }

    float acc[8][4];
    #pragma unroll
    for (int ni = 0; ni < 8; ni++)
        #pragma unroll
        for (int c = 0; c < 4; c++) acc[ni][c] = 0.f;
    float m0 = -1e30f, m1 = -1e30f, l0 = 0.f, l1 = 0.f;
    const int row0 = q0 + r0 + g, row1 = row0 + 8;

    const int nkb = qb + 1;

    auto load_kv = [&](int kb, int buf) {
        const int k0t = kb * 64;
        unsigned kbase = sb + AT_KOFF + buf * 8192;
        unsigned vbase = sb + AT_VOFF + buf * 8192;
        #pragma unroll
        for (int i = 0; i < 4; i++) {
            int idx = tid + i * 128;
            int r = idx >> 3, c = idx & 7;
            unsigned off = r * 128 + ((c ^ (r & 7)) << 4);
            cp16s(kbase + off, Kh + (size_t)(k0t + r) * NQKV * 2 + c * 16);
            cp16s(vbase + off, Vh + (size_t)(k0t + r) * NQKV * 2 + c * 16);
        }
        cp_commit();
    };

    load_kv(0, 0);
    if (nkb > 1) load_kv(1, 1);

    for (int kb = 0; kb < nkb; kb++) {
        const int k0t = kb * 64;
        const int buf = kb & 1;
        if (kb + 1 < nkb) cp_wait<1>(); else cp_wait<0>();
        __syncthreads();
        const unsigned kbase = sb + AT_KOFF + buf * 8192;
        const unsigned vbase = sb + AT_VOFF + buf * 8192;

        // S = (Q/8) K^T : b-fragments via non-trans ldmatrix on K rows (n)
        float s[8][4];
        #pragma unroll
        for (int ni = 0; ni < 8; ni++)
            #pragma unroll
            for (int c = 0; c < 4; c++) s[ni][c] = 0.f;
        #pragma unroll
        for (int kc = 0; kc < 4; kc++) {
            unsigned b[8][2];
            #pragma unroll
            for (int nj = 0; nj < 4; nj++) {
                int n = nj * 16 + nrow;
                int chunk = kc * 2 + nhi;
                unsigned d[4];
                ldm_x4(d, kbase + n * 128 + ((chunk ^ (n & 7)) << 4));
                b[2 * nj][0] = d[0]; b[2 * nj][1] = d[1];
                b[2 * nj + 1][0] = d[2]; b[2 * nj + 1][1] = d[3];
            }
            #pragma unroll
            for (int ni = 0; ni < 8; ni++)
                mma_f16(s[ni], qa[kc], b[ni]);
        }

        // causal mask
        if (k0t + 63 > row0) {
            #pragma unroll
            for (int ni = 0; ni < 8; ni++) {
                int col = k0t + ni * 8 + t4 * 2;
                if (col > row0) s[ni][0] = -1e30f;
                if (col + 1 > row0) s[ni][1] = -1e30f;
                if (col > row1) s[ni][2] = -1e30f;
                if (col + 1 > row1) s[ni][3] = -1e30f;
            }
        }

        // online softmax
        float tm0 = -1e30f, tm1 = -1e30f;
        #pragma unroll
        for (int ni = 0; ni < 8; ni++) {
            tm0 = fmaxf(tm0, fmaxf(s[ni][0], s[ni][1]));
            tm1 = fmaxf(tm1, fmaxf(s[ni][2], s[ni][3]));
        }
        tm0 = fmaxf(tm0, __shfl_xor_sync(0xffffffffu, tm0, 1));
        tm0 = fmaxf(tm0, __shfl_xor_sync(0xffffffffu, tm0, 2));
        tm1 = fmaxf(tm1, __shfl_xor_sync(0xffffffffu, tm1, 1));
        tm1 = fmaxf(tm1, __shfl_xor_sync(0xffffffffu, tm1, 2));
        float mn0 = fmaxf(m0, tm0), mn1 = fmaxf(m1, tm1);
        float f0 = __expf(m0 - mn0), f1 = __expf(m1 - mn1);
        m0 = mn0; m1 = mn1;
        float sum0 = 0.f, sum1 = 0.f;
        #pragma unroll
        for (int ni = 0; ni < 8; ni++) {
            s[ni][0] = __expf(s[ni][0] - mn0);
            s[ni][1] = __expf(s[ni][1] - mn0);
            s[ni][2] = __expf(s[ni][2] - mn1);
            s[ni][3] = __expf(s[ni][3] - mn1);
            sum0 += s[ni][0] + s[ni][1];
            sum1 += s[ni][2] + s[ni][3];
        }
        sum0 += __shfl_xor_sync(0xffffffffu, sum0, 1);
        sum0 += __shfl_xor_sync(0xffffffffu, sum0, 2);
        sum1 += __shfl_xor_sync(0xffffffffu, sum1, 1);
        sum1 += __shfl_xor_sync(0xffffffffu, sum1, 2);
        l0 = l0 * f0 + sum0;
        l1 = l1 * f1 + sum1;
        #pragma unroll
        for (int ni = 0; ni < 8; ni++) {
            acc[ni][0] *= f0; acc[ni][1] *= f0;
            acc[ni][2] *= f1; acc[ni][3] *= f1;
        }

        // O += P V : P a-fragments directly from registers, V via trans ldmatrix
        #pragma unroll
        for (int kc = 0; kc < 4; kc++) {
            unsigned pa[4];
            pa[0] = pack2(s[2 * kc][0], s[2 * kc][1]);
            pa[1] = pack2(s[2 * kc][2], s[2 * kc][3]);
            pa[2] = pack2(s[2 * kc + 1][0], s[2 * kc + 1][1]);
            pa[3] = pack2(s[2 * kc + 1][2], s[2 * kc + 1][3]);
            unsigned vb[8][2];
            #pragma unroll
            for (int nj = 0; nj < 4; nj++) {
                int kv = kc * 16 + lrow;
                int chunk = nj * 2 + lhi;
                unsigned d[4];
                ldm_x4_t(d, vbase + kv * 128 + ((chunk ^ (kv & 7)) << 4));
                vb[2 * nj][0] = d[0]; vb[2 * nj][1] = d[1];
                vb[2 * nj + 1][0] = d[2]; vb[2 * nj + 1][1] = d[3];
            }
            #pragma unroll
            for (int ni = 0; ni < 8; ni++)
                mma_f16(acc[ni], pa, vb[ni]);
        }

        // prefetch tile kb+2 into this buffer (after everyone is done reading it)
        if (kb + 2 < nkb) {
            __syncthreads();
            load_kv(kb + 2, buf);
        }
    }

    float inv0 = 1.0f / l0, inv1 = 1.0f / l1;
    #pragma unroll
    for (int ni = 0; ni < 8; ni++) {
        int col = h * HS + ni * 8 + t4 * 2;
        *(__half2*)&g_attn[(size_t)row0 * DD + col] =
            __floats2half2_rn(acc[ni][0] * inv0, acc[ni][1] * inv0);
        *(__half2*)&g_attn[(size_t)row1 * DD + col] =
            __floats2half2_rn(acc[ni][2] * inv1, acc[ni][3] * inv1);
    }
}

// ---------------- launch ----------------
extern "C" void kernel_launch(void* const* d_in, const int* in_sizes, int n_in,
                              void* d_out, int out_size) {
    const float* x     = (const float*)d_in[0];
    const float* Wq    = (const float*)d_in[1];
    const float* Wk    = (const float*)d_in[2];
    const float* Wv    = (const float*)d_in[3];
    const float* Wproj = (const float*)d_in[4];
    const float* bproj = (const float*)d_in[5];
    const float* W1    = (const float*)d_in[6];
    const float* W2    = (const float*)d_in[7];
    const float* g1    = (const float*)d_in[8];
    const float* g2    = (const float*)d_in[9];
    float* out = (float*)d_out;

    __half *p_xn, *p_qkv, *p_attn, *p_xn2, *p_hbuf, *p_Bqkv, *p_Wpr, *p_W1r, *p_W2r;
    float *p_x1;
    cudaGetSymbolAddress((void**)&p_xn,   g_xn);
    cudaGetSymbolAddress((void**)&p_qkv,  g_qkv);
    cudaGetSymbolAddress((void**)&p_attn, g_attn);
    cudaGetSymbolAddress((void**)&p_x1,   g_x1);
    cudaGetSymbolAddress((void**)&p_xn2,  g_xn2);
    cudaGetSymbolAddress((void**)&p_hbuf, g_hbuf);
    cudaGetSymbolAddress((void**)&p_Bqkv, g_Bqkv);
    cudaGetSymbolAddress((void**)&p_Wpr,  g_Wpr);
    cudaGetSymbolAddress((void**)&p_W1r,  g_W1r);
    cudaGetSymbolAddress((void**)&p_W2r,  g_W2r);

    cudaFuncSetAttribute(gemm_kernel<0, 128>, cudaFuncAttributeMaxDynamicSharedMemorySize, GEMM_SMEM(128));
    cudaFuncSetAttribute(gemm_kernel<2, 128>, cudaFuncAttributeMaxDynamicSharedMemorySize, GEMM_SMEM(128));
    cudaFuncSetAttribute(gemm_kernel<1, 64>,  cudaFuncAttributeMaxDynamicSharedMemorySize, GEMM_SMEM(64));
    cudaFuncSetAttribute(gemm_kernel<3, 64>,  cudaFuncAttributeMaxDynamicSharedMemorySize, GEMM_SMEM(64));
    cudaFuncSetAttribute(attn_kernel, cudaFuncAttributeMaxDynamicSharedMemorySize, ATTN_SMEM);

    prep_kernel<<<(PREP_TOTAL + 255) / 256, 256>>>(Wproj, W1, W2, Wq, Wk, Wv);
    rmsnorm_kernel<<<TT, 256>>>(x, g1, p_xn);
    gemm_kernel<0, 128><<<dim3(NQKV / BN, TT / 128), 128, GEMM_SMEM(128)>>>(
        p_xn, p_Bqkv, p_qkv, nullptr, nullptr, TT, NQKV, DD);
    attn_kernel<<<dim3(TT / 64, HH), 128, ATTN_SMEM>>>();
    gemm_kernel<1, 64><<<dim3(DD / BN, TT / 64), 128, GEMM_SMEM(64)>>>(
        p_attn, p_Wpr, p_x1, x, bproj, TT, DD, DD);
    rmsnorm_kernel<<<TT, 256>>>(p_x1, g2, p_xn2);
    gemm_kernel<2, 128><<<dim3(FF / BN, TT / 128), 128, GEMM_SMEM(128)>>>(
        p_xn2, p_W1r, p_hbuf, nullptr, nullptr, TT, FF, DD);
    gemm_kernel<3, 64><<<dim3(DD / BN, TT / 64), 128, GEMM_SMEM(64)>>>(
        p_hbuf, p_W2r, out, p_x1, nullptr, TT, DD, FF);
}